// round 11
// baseline (speedup 1.0000x reference)
#include <cuda_runtime.h>
#include <cuda_bf16.h>
#include <cstdint>

// Problem constants
#define BB 64
#define PP 196
#define EE 2048
#define LL 32
#define VV 10000
#define EMB 512
#define DEC 512
#define ATT 512
#define TT 31   // L-1 steps

// ---------------- device scratch ----------------
__device__ __align__(16) int   d_sort_src[BB];
__device__ __align__(16) int   d_nb[TT + 1];
__device__ int   d_total;
__device__ __align__(16) int   d_rowmap[BB * TT];
__device__ __align__(16) float d_mean[BB * EE];
__device__ __align__(16) float d_h[BB * DEC];
__device__ __align__(16) float d_c[BB * DEC];
__device__ __align__(16) float d_hhist[(size_t)TT * BB * DEC];
__device__ __align__(16) float d_att1[(size_t)BB * PP * ATT];
__device__ __align__(16) float d_awe[BB * EE];
__device__ __align__(16) float d_embc[(size_t)TT * BB * 2048];
__device__ __align__(16) float d_part[8 * BB * 2048];
__device__ int d_sem[64];
// phase-A partials: [split(2)][b(64)][col(4608)] — 0..511 att2, 512..2559 gate, 2560..4607 hg
#define AGC 4608
__device__ __align__(16) float d_agp[2 * BB * AGC];

#define BUF_MEAN 0
#define BUF_AWE  5

__device__ __forceinline__ float* selbuf(int s) {
    switch (s) {
        case BUF_MEAN: return d_mean;
        case BUF_AWE:  return d_awe;
        default:       return nullptr;
    }
}

// ---------------- tf32 helpers ----------------
__device__ __forceinline__ float tf32r(float f) {
    uint32_t u;
    asm("cvt.rna.tf32.f32 %0, %1;" : "=r"(u) : "f"(f));
    return __uint_as_float(u);
}
__device__ __forceinline__ void mma_tf32(float* c, const uint32_t* a, const uint32_t* b) {
    asm volatile("mma.sync.aligned.m16n8k8.row.col.f32.tf32.tf32.f32 "
        "{%0,%1,%2,%3}, {%4,%5,%6,%7}, {%8,%9}, {%0,%1,%2,%3};"
        : "+f"(c[0]), "+f"(c[1]), "+f"(c[2]), "+f"(c[3])
        : "r"(a[0]), "r"(a[1]), "r"(a[2]), "r"(a[3]), "r"(b[0]), "r"(b[1]));
}

// ---------------- setup ----------------
__global__ void k_setup(const int* __restrict__ cap_len) {
    __shared__ int lens[BB];
    __shared__ int nbs[TT + 1];
    __shared__ int off[TT + 1];
    int b = threadIdx.x;
    if (b < BB) lens[b] = cap_len[b];
    if (b < 64) d_sem[b] = 0;
    __syncthreads();
    if (b < BB) {
        int rank = 0;
        int lb = lens[b];
        for (int j = 0; j < BB; j++) {
            int lj = lens[j];
            if (lj > lb || (lj == lb && j < b)) rank++;
        }
        d_sort_src[rank] = b;
    }
    if (b <= TT) {
        int cnt = 0;
        for (int j = 0; j < BB; j++) if (lens[j] - 1 > b) cnt++;
        d_nb[b] = cnt;
        nbs[b] = cnt;
    }
    __syncthreads();
    if (b == 0) {
        int a = 0;
        for (int t = 0; t < TT; t++) { off[t] = a; a += nbs[t]; }
        d_total = a;
    }
    __syncthreads();
    if (b < BB) {
        for (int t = 0; t < TT; t++)
            if (b < nbs[t]) d_rowmap[off[t] + b] = (t << 6) | b;
    }
}

__global__ void k_zero(float* __restrict__ out, size_t n) {
    size_t i = (size_t)blockIdx.x * blockDim.x + threadIdx.x;
    size_t stride = (size_t)gridDim.x * blockDim.x;
    for (; i < n; i += stride) out[i] = 0.0f;
}

__global__ void k_mean(const float* __restrict__ enc) {
    int b = blockIdx.y;
    int e = blockIdx.x * 256 + threadIdx.x;
    const float* base = enc + (size_t)d_sort_src[b] * PP * EE + e;
    float s = 0.0f;
    #pragma unroll 7
    for (int p = 0; p < PP; p++) s += base[(size_t)p * EE];
    d_mean[b * EE + e] = s * (1.0f / 196.0f);
}

// ---------------- split-K GEMM, KTILE=32, into d_part (h0/c0 only) ----------------
__global__ void __launch_bounds__(256, 2) k_gemm32(
        int xsel, const float* __restrict__ WA, const float* __restrict__ WB,
        int colSplit, int NA, int NB, int Nout, int K, int S) {
    __shared__ __align__(16) float Xs[2][32][68];
    __shared__ __align__(16) float Ws[2][32][34];

    const float* X = selbuf(xsel);
    int tid = threadIdx.x;
    int n0 = blockIdx.x * 32;

    const float* W; int wc0, NW;
    if (n0 < colSplit) { W = WA; wc0 = n0; NW = NA; }
    else               { W = WB; wc0 = n0 - colSplit; NW = NB; }

    int s = blockIdx.y;
    int kbeg = s * (K / S);
    int ntiles = (K / S) / 32;

    int nl = tid & 15;
    int mg = tid >> 4;
    int m0 = mg << 2;

    int lm = tid >> 2, lk = (tid & 3) << 2;
    int wk = tid >> 4, wn = tid & 15;
    const float* Xrow = X + (size_t)lm * K;

    float acc[4][2];
    #pragma unroll
    for (int i = 0; i < 4; i++) { acc[i][0] = 0.f; acc[i][1] = 0.f; }

    float4 xr0, xr1; float wr00, wr01, wr10, wr11;
    auto loadG = [&](int k0) {
        xr0 = *reinterpret_cast<const float4*>(Xrow + k0 + lk);
        xr1 = *reinterpret_cast<const float4*>(Xrow + k0 + lk + 16);
        int kg = k0 + wk;
        wr00 = W[(size_t)kg * NW + wc0 + wn];
        wr01 = W[(size_t)kg * NW + wc0 + wn + 16];
        wr10 = W[(size_t)(kg + 16) * NW + wc0 + wn];
        wr11 = W[(size_t)(kg + 16) * NW + wc0 + wn + 16];
    };
    auto stS = [&](int buf) {
        Xs[buf][lk + 0][lm] = xr0.x; Xs[buf][lk + 1][lm] = xr0.y;
        Xs[buf][lk + 2][lm] = xr0.z; Xs[buf][lk + 3][lm] = xr0.w;
        Xs[buf][lk + 16][lm] = xr1.x; Xs[buf][lk + 17][lm] = xr1.y;
        Xs[buf][lk + 18][lm] = xr1.z; Xs[buf][lk + 19][lm] = xr1.w;
        Ws[buf][wk][wn] = wr00; Ws[buf][wk][wn + 16] = wr01;
        Ws[buf][wk + 16][wn] = wr10; Ws[buf][wk + 16][wn + 16] = wr11;
    };

    loadG(kbeg);
    stS(0);
    __syncthreads();

    for (int it = 0; it < ntiles; it++) {
        int cur = it & 1;
        bool more = (it + 1 < ntiles);
        if (more) loadG(kbeg + (it + 1) * 32);
        #pragma unroll
        for (int kk = 0; kk < 32; kk++) {
            float4 xv = *reinterpret_cast<const float4*>(&Xs[cur][kk][m0]);
            float2 wv = *reinterpret_cast<const float2*>(&Ws[cur][kk][nl * 2]);
            acc[0][0] += xv.x * wv.x; acc[0][1] += xv.x * wv.y;
            acc[1][0] += xv.y * wv.x; acc[1][1] += xv.y * wv.y;
            acc[2][0] += xv.z * wv.x; acc[2][1] += xv.z * wv.y;
            acc[3][0] += xv.w * wv.x; acc[3][1] += xv.w * wv.y;
        }
        if (more) stS(cur ^ 1);
        __syncthreads();
    }

    int na = n0 + nl * 2;
    #pragma unroll
    for (int j = 0; j < 4; j++) {
        int m = m0 + j;
        size_t base = ((size_t)(s * BB + m)) * Nout + na;
        d_part[base] = acc[j][0];
        d_part[base + 1] = acc[j][1];
    }
}

// reduce combined h0/c0 (N=1024, S=8)
__global__ void k_reduce_hc(const float* __restrict__ bhi, const float* __restrict__ bci) {
    int idx = blockIdx.x * 256 + threadIdx.x;
    if (idx >= BB * 1024) return;
    int m = idx >> 10, n = idx & 1023;
    float v = 0.f;
    #pragma unroll
    for (int s = 0; s < 8; s++) v += d_part[((size_t)(s * BB + m)) * 1024 + n];
    if (n < 512) d_h[m * 512 + n] = v + bhi[n];
    else         d_c[m * 512 + (n - 512)] = v + bci[n - 512];
}

// ---------------- phase A: split-K2 KTILE=32 GEMM h @ [Wd|Wb|Whh] -> d_agp ----------------
__global__ void __launch_bounds__(256, 2) k_ag(
        const float* __restrict__ Wd, const float* __restrict__ Wb,
        const float* __restrict__ Whh, int t) {
    __shared__ __align__(16) float Xs[2][32][68];
    __shared__ __align__(16) float Ws[2][32][34];

    int n0 = blockIdx.x * 32;
    int s = blockIdx.y;
    int nb = d_nb[t];

    const float* W; int wc0, NW;
    if (n0 < 512)       { W = Wd;  wc0 = n0;        NW = ATT; }
    else if (n0 < 2560) { W = Wb;  wc0 = n0 - 512;  NW = 2048; }
    else                { W = Whh; wc0 = n0 - 2560; NW = 2048; }

    int kbeg = s * 256;
    const int ntiles = 8;

    int tid = threadIdx.x;
    int nl = tid & 15;
    int mg = tid >> 4;
    int m0 = mg << 2;
    bool rowact = (m0 < nb);

    int lm = tid >> 2, lk = (tid & 3) << 2;
    int wk = tid >> 4, wn = tid & 15;
    const float* Xrow = d_h + (size_t)lm * DEC;

    float acc[4][2];
    #pragma unroll
    for (int i = 0; i < 4; i++) { acc[i][0] = 0.f; acc[i][1] = 0.f; }

    float4 xr0, xr1; float wr00, wr01, wr10, wr11;
    auto loadG = [&](int k0) {
        xr0 = *reinterpret_cast<const float4*>(Xrow + k0 + lk);
        xr1 = *reinterpret_cast<const float4*>(Xrow + k0 + lk + 16);
        int kg = k0 + wk;
        wr00 = W[(size_t)kg * NW + wc0 + wn];
        wr01 = W[(size_t)kg * NW + wc0 + wn + 16];
        wr10 = W[(size_t)(kg + 16) * NW + wc0 + wn];
        wr11 = W[(size_t)(kg + 16) * NW + wc0 + wn + 16];
    };
    auto stS = [&](int buf) {
        Xs[buf][lk + 0][lm] = xr0.x; Xs[buf][lk + 1][lm] = xr0.y;
        Xs[buf][lk + 2][lm] = xr0.z; Xs[buf][lk + 3][lm] = xr0.w;
        Xs[buf][lk + 16][lm] = xr1.x; Xs[buf][lk + 17][lm] = xr1.y;
        Xs[buf][lk + 18][lm] = xr1.z; Xs[buf][lk + 19][lm] = xr1.w;
        Ws[buf][wk][wn] = wr00; Ws[buf][wk][wn + 16] = wr01;
        Ws[buf][wk + 16][wn] = wr10; Ws[buf][wk + 16][wn + 16] = wr11;
    };

    loadG(kbeg);
    stS(0);
    __syncthreads();

    for (int it = 0; it < ntiles; it++) {
        int cur = it & 1;
        bool more = (it + 1 < ntiles);
        if (more) loadG(kbeg + (it + 1) * 32);
        if (rowact) {
            #pragma unroll
            for (int kk = 0; kk < 32; kk++) {
                float4 xv = *reinterpret_cast<const float4*>(&Xs[cur][kk][m0]);
                float2 wv = *reinterpret_cast<const float2*>(&Ws[cur][kk][nl * 2]);
                acc[0][0] += xv.x * wv.x; acc[0][1] += xv.x * wv.y;
                acc[1][0] += xv.y * wv.x; acc[1][1] += xv.y * wv.y;
                acc[2][0] += xv.z * wv.x; acc[2][1] += xv.z * wv.y;
                acc[3][0] += xv.w * wv.x; acc[3][1] += xv.w * wv.y;
            }
        }
        if (more) stS(cur ^ 1);
        __syncthreads();
    }

    if (!rowact) return;
    int na = n0 + nl * 2;
    #pragma unroll
    for (int j = 0; j < 4; j++) {
        int m = m0 + j;
        if (m < nb) {
            size_t base = ((size_t)(s * BB + m)) * AGC + na;
            d_agp[base] = acc[j][0];
            d_agp[base + 1] = acc[j][1];
        }
    }
}

// ---------------- fused awe-GEMM + split-K semaphore LSTM epilogue ----------------
// grid (64, 4): dtile -> 8 LSTM dims (all 4 gates, flat 32 cols), s -> K split of 512.
// Flat col f (0..31) maps to gate column gcol = (f>>3)*512 + dtile*8 + (f&7).
// Last-arriving split block per dtile sums 4 partials + embc + hg + biases and
// runs the LSTM pointwise for its 8 dims (deterministic fixed-order sum).
__global__ void __launch_bounds__(256, 2) k_awe_lstm(
        const float* __restrict__ Wih2,
        const float* __restrict__ bih, const float* __restrict__ bhh, int t) {
    __shared__ __align__(16) float Xs[2][32][68];
    __shared__ __align__(16) float Ws[2][32][34];
    __shared__ int lastFlag;

    int dtile = blockIdx.x;
    int d0 = dtile * 8;
    int s = blockIdx.y;
    int nb = d_nb[t];
    const int NW = 2048, K = 2048;
    int kbeg = s * 512;
    const int ntiles = 16;

    int tid = threadIdx.x;
    int nl = tid & 15;
    int mg = tid >> 4;
    int m0 = mg << 2;
    bool rowact = (m0 < nb);

    int lm = tid >> 2, lk = (tid & 3) << 2;
    int wk = tid >> 4, wn = tid & 15;
    const float* Xrow = d_awe + (size_t)lm * K;
    int gc0 = ((wn >> 3) << 9) + d0 + (wn & 7);
    int gc1 = (((wn + 16) >> 3) << 9) + d0 + (wn & 7);

    float acc[4][2];
    #pragma unroll
    for (int i = 0; i < 4; i++) { acc[i][0] = 0.f; acc[i][1] = 0.f; }

    float4 xr0, xr1; float wr00, wr01, wr10, wr11;
    auto loadG = [&](int k0) {
        xr0 = *reinterpret_cast<const float4*>(Xrow + k0 + lk);
        xr1 = *reinterpret_cast<const float4*>(Xrow + k0 + lk + 16);
        int kg = k0 + wk;
        wr00 = Wih2[(size_t)kg * NW + gc0];
        wr01 = Wih2[(size_t)kg * NW + gc1];
        wr10 = Wih2[(size_t)(kg + 16) * NW + gc0];
        wr11 = Wih2[(size_t)(kg + 16) * NW + gc1];
    };
    auto stS = [&](int buf) {
        Xs[buf][lk + 0][lm] = xr0.x; Xs[buf][lk + 1][lm] = xr0.y;
        Xs[buf][lk + 2][lm] = xr0.z; Xs[buf][lk + 3][lm] = xr0.w;
        Xs[buf][lk + 16][lm] = xr1.x; Xs[buf][lk + 17][lm] = xr1.y;
        Xs[buf][lk + 18][lm] = xr1.z; Xs[buf][lk + 19][lm] = xr1.w;
        Ws[buf][wk][wn] = wr00; Ws[buf][wk][wn + 16] = wr01;
        Ws[buf][wk + 16][wn] = wr10; Ws[buf][wk + 16][wn + 16] = wr11;
    };

    loadG(kbeg);
    stS(0);
    __syncthreads();

    for (int it = 0; it < ntiles; it++) {
        int cur = it & 1;
        bool more = (it + 1 < ntiles);
        if (more) loadG(kbeg + (it + 1) * 32);
        if (rowact) {
            #pragma unroll
            for (int kk = 0; kk < 32; kk++) {
                float4 xv = *reinterpret_cast<const float4*>(&Xs[cur][kk][m0]);
                float2 wv = *reinterpret_cast<const float2*>(&Ws[cur][kk][nl * 2]);
                acc[0][0] += xv.x * wv.x; acc[0][1] += xv.x * wv.y;
                acc[1][0] += xv.y * wv.x; acc[1][1] += xv.y * wv.y;
                acc[2][0] += xv.z * wv.x; acc[2][1] += xv.z * wv.y;
                acc[3][0] += xv.w * wv.x; acc[3][1] += xv.w * wv.y;
            }
        }
        if (more) stS(cur ^ 1);
        __syncthreads();
    }

    // store partials (flat layout), rows < nb only
    if (rowact) {
        int na = dtile * 32 + nl * 2;
        #pragma unroll
        for (int j = 0; j < 4; j++) {
            int m = m0 + j;
            if (m < nb) {
                size_t base = ((size_t)(s * BB + m)) * 2048 + na;
                d_part[base] = acc[j][0];
                d_part[base + 1] = acc[j][1];
            }
        }
    }

    // semaphore: all blocks (even fully-inactive ones) arrive
    __threadfence();
    __syncthreads();
    if (tid == 0) {
        int v = atomicAdd(&d_sem[dtile], 1);
        lastFlag = (v == 3);
    }
    __syncthreads();
    if (!lastFlag) return;
    __threadfence();

    // epilogue: LSTM pointwise for dims [d0, d0+8), all rows < nb
    for (int ci = tid; ci < 512; ci += 256) {
        int m = ci >> 3;
        if (m >= nb) continue;
        int dj = ci & 7;
        int d = d0 + dj;
        float gv[4];
        #pragma unroll
        for (int q = 0; q < 4; q++) {
            int gcol = (q << 9) + d;
            float v = bih[gcol] + bhh[gcol]
                    + d_embc[((size_t)((t << 6) | m)) * 2048 + gcol]
                    + d_agp[(size_t)m * AGC + 2560 + gcol]
                    + d_agp[(size_t)(BB + m) * AGC + 2560 + gcol];
            int pcol = dtile * 32 + (q << 3) + dj;
            #pragma unroll
            for (int ss = 0; ss < 4; ss++)
                v += d_part[((size_t)(ss * BB + m)) * 2048 + pcol];
            gv[q] = v;
        }
        float c = d_c[m * DEC + d];
        float si = 1.0f / (1.0f + __expf(-gv[0]));
        float sf = 1.0f / (1.0f + __expf(-gv[1]));
        float so = 1.0f / (1.0f + __expf(-gv[3]));
        float cn = sf * c + si * tanhf(gv[2]);
        float hn = so * tanhf(cn);
        d_c[m * DEC + d] = cn;
        d_h[m * DEC + d] = hn;
        d_hhist[((size_t)t * BB + m) * DEC + d] = hn;
    }
    if (tid == 0) d_sem[dtile] = 0;
}

// ---------------- att1 = enc[sorted] @ We + be : tf32 MMA ----------------
__global__ void __launch_bounds__(256, 2) k_att1_mma(const float* __restrict__ enc,
                                                     const float* __restrict__ We,
                                                     const float* __restrict__ be) {
    __shared__ float As[2][16][136];
    __shared__ float Bs[2][16][72];
    int tid = threadIdx.x;
    int warp = tid >> 5, lane = tid & 31;
    int g = lane >> 2, tk = lane & 3;
    int mw = (warp & 3) * 32, nw = (warp >> 2) * 32;
    int rowBase = blockIdx.x * 128, colBase = blockIdx.y * 64;

    int lm = tid >> 1, lk = (tid & 1) << 3;
    int r = rowBase + lm;
    int bidx = r / PP, pidx = r % PP;
    const float* Arow = enc + ((size_t)d_sort_src[bidx] * PP + pidx) * EE;
    int bk = tid >> 4, bn = (tid & 15) << 2;

    float acc[2][4][4];
    #pragma unroll
    for (int i = 0; i < 2; i++)
        #pragma unroll
        for (int j = 0; j < 4; j++)
            #pragma unroll
            for (int q = 0; q < 4; q++) acc[i][j][q] = 0.f;

    float4 av0, av1, bv;
    av0 = *reinterpret_cast<const float4*>(Arow + lk);
    av1 = *reinterpret_cast<const float4*>(Arow + lk + 4);
    bv  = *reinterpret_cast<const float4*>(We + (size_t)bk * ATT + colBase + bn);
    As[0][lk + 0][lm] = tf32r(av0.x); As[0][lk + 1][lm] = tf32r(av0.y);
    As[0][lk + 2][lm] = tf32r(av0.z); As[0][lk + 3][lm] = tf32r(av0.w);
    As[0][lk + 4][lm] = tf32r(av1.x); As[0][lk + 5][lm] = tf32r(av1.y);
    As[0][lk + 6][lm] = tf32r(av1.z); As[0][lk + 7][lm] = tf32r(av1.w);
    *reinterpret_cast<float4*>(&Bs[0][bk][bn]) =
        make_float4(tf32r(bv.x), tf32r(bv.y), tf32r(bv.z), tf32r(bv.w));
    __syncthreads();

    const int ntiles = EE / 16;
    for (int it = 0; it < ntiles; it++) {
        int cur = it & 1;
        bool more = (it + 1 < ntiles);
        if (more) {
            int k0 = (it + 1) * 16;
            av0 = *reinterpret_cast<const float4*>(Arow + k0 + lk);
            av1 = *reinterpret_cast<const float4*>(Arow + k0 + lk + 4);
            bv  = *reinterpret_cast<const float4*>(We + (size_t)(k0 + bk) * ATT + colBase + bn);
        }
        #pragma unroll
        for (int ks = 0; ks < 16; ks += 8) {
            uint32_t a[2][4], bfr[4][2];
            #pragma unroll
            for (int i = 0; i < 2; i++) {
                a[i][0] = __float_as_uint(As[cur][ks + tk][mw + i * 16 + g]);
                a[i][1] = __float_as_uint(As[cur][ks + tk][mw + i * 16 + g + 8]);
                a[i][2] = __float_as_uint(As[cur][ks + tk + 4][mw + i * 16 + g]);
                a[i][3] = __float_as_uint(As[cur][ks + tk + 4][mw + i * 16 + g + 8]);
            }
            #pragma unroll
            for (int j = 0; j < 4; j++) {
                bfr[j][0] = __float_as_uint(Bs[cur][ks + tk][nw + j * 8 + g]);
                bfr[j][1] = __float_as_uint(Bs[cur][ks + tk + 4][nw + j * 8 + g]);
            }
            #pragma unroll
            for (int i = 0; i < 2; i++)
                #pragma unroll
                for (int j = 0; j < 4; j++)
                    mma_tf32(acc[i][j], a[i], bfr[j]);
        }
        if (more) {
            int nxt = cur ^ 1;
            As[nxt][lk + 0][lm] = tf32r(av0.x); As[nxt][lk + 1][lm] = tf32r(av0.y);
            As[nxt][lk + 2][lm] = tf32r(av0.z); As[nxt][lk + 3][lm] = tf32r(av0.w);
            As[nxt][lk + 4][lm] = tf32r(av1.x); As[nxt][lk + 5][lm] = tf32r(av1.y);
            As[nxt][lk + 6][lm] = tf32r(av1.z); As[nxt][lk + 7][lm] = tf32r(av1.w);
            *reinterpret_cast<float4*>(&Bs[nxt][bk][bn]) =
                make_float4(tf32r(bv.x), tf32r(bv.y), tf32r(bv.z), tf32r(bv.w));
        }
        __syncthreads();
    }

    #pragma unroll
    for (int i = 0; i < 2; i++) {
        int row0 = rowBase + mw + i * 16 + g;
        #pragma unroll
        for (int j = 0; j < 4; j++) {
            int col = colBase + nw + j * 8 + tk * 2;
            float be0 = be[col], be1 = be[col + 1];
            float2 o0 = make_float2(acc[i][j][0] + be0, acc[i][j][1] + be1);
            float2 o1 = make_float2(acc[i][j][2] + be0, acc[i][j][3] + be1);
            *reinterpret_cast<float2*>(d_att1 + (size_t)row0 * ATT + col) = o0;
            *reinterpret_cast<float2*>(d_att1 + (size_t)(row0 + 8) * ATT + col) = o1;
        }
    }
}

// ---------------- batched preds: tf32 MMA, compact rows @ Wfc ----------------
__global__ void __launch_bounds__(256, 2) k_preds_mma(const float* __restrict__ Wfc,
                                                      const float* __restrict__ bfc,
                                                      float* __restrict__ out) {
    int total = d_total;
    int rowBase = blockIdx.x * 128;
    if (rowBase >= total) return;
    int colBase = blockIdx.y * 64;

    __shared__ float As[2][16][136];
    __shared__ float Bs[2][16][72];
    int tid = threadIdx.x;
    int warp = tid >> 5, lane = tid & 31;
    int g = lane >> 2, tk = lane & 3;
    int mw = (warp & 3) * 32, nw = (warp >> 2) * 32;

    int lm = tid >> 1, lk = (tid & 1) << 3;
    int r = rowBase + lm;
    bool rvalid = (r < total);
    const float* Arow = d_hhist + (size_t)(rvalid ? d_rowmap[r] : 0) * DEC;
    int bk = tid >> 4, bn = (tid & 15) << 2;
    int bcol = colBase + bn;
    bool cvalid = (bcol < VV);

    float acc[2][4][4];
    #pragma unroll
    for (int i = 0; i < 2; i++)
        #pragma unroll
        for (int j = 0; j < 4; j++)
            #pragma unroll
            for (int q = 0; q < 4; q++) acc[i][j][q] = 0.f;

    float4 av0, av1, bv;
    auto loadA = [&](int k0) {
        if (rvalid) {
            av0 = *reinterpret_cast<const float4*>(Arow + k0 + lk);
            av1 = *reinterpret_cast<const float4*>(Arow + k0 + lk + 4);
        } else {
            av0 = make_float4(0.f, 0.f, 0.f, 0.f);
            av1 = av0;
        }
    };
    auto loadB = [&](int k0) {
        if (cvalid) bv = *reinterpret_cast<const float4*>(Wfc + (size_t)(k0 + bk) * VV + bcol);
        else        bv = make_float4(0.f, 0.f, 0.f, 0.f);
    };

    loadA(0); loadB(0);
    As[0][lk + 0][lm] = tf32r(av0.x); As[0][lk + 1][lm] = tf32r(av0.y);
    As[0][lk + 2][lm] = tf32r(av0.z); As[0][lk + 3][lm] = tf32r(av0.w);
    As[0][lk + 4][lm] = tf32r(av1.x); As[0][lk + 5][lm] = tf32r(av1.y);
    As[0][lk + 6][lm] = tf32r(av1.z); As[0][lk + 7][lm] = tf32r(av1.w);
    *reinterpret_cast<float4*>(&Bs[0][bk][bn]) =
        make_float4(tf32r(bv.x), tf32r(bv.y), tf32r(bv.z), tf32r(bv.w));
    __syncthreads();

    const int ntiles = DEC / 16;
    for (int it = 0; it < ntiles; it++) {
        int cur = it & 1;
        bool more = (it + 1 < ntiles);
        if (more) { loadA((it + 1) * 16); loadB((it + 1) * 16); }
        #pragma unroll
        for (int ks = 0; ks < 16; ks += 8) {
            uint32_t a[2][4], bfr[4][2];
            #pragma unroll
            for (int i = 0; i < 2; i++) {
                a[i][0] = __float_as_uint(As[cur][ks + tk][mw + i * 16 + g]);
                a[i][1] = __float_as_uint(As[cur][ks + tk][mw + i * 16 + g + 8]);
                a[i][2] = __float_as_uint(As[cur][ks + tk + 4][mw + i * 16 + g]);
                a[i][3] = __float_as_uint(As[cur][ks + tk + 4][mw + i * 16 + g + 8]);
            }
            #pragma unroll
            for (int j = 0; j < 4; j++) {
                bfr[j][0] = __float_as_uint(Bs[cur][ks + tk][nw + j * 8 + g]);
                bfr[j][1] = __float_as_uint(Bs[cur][ks + tk + 4][nw + j * 8 + g]);
            }
            #pragma unroll
            for (int i = 0; i < 2; i++)
                #pragma unroll
                for (int j = 0; j < 4; j++)
                    mma_tf32(acc[i][j], a[i], bfr[j]);
        }
        if (more) {
            int nxt = cur ^ 1;
            As[nxt][lk + 0][lm] = tf32r(av0.x); As[nxt][lk + 1][lm] = tf32r(av0.y);
            As[nxt][lk + 2][lm] = tf32r(av0.z); As[nxt][lk + 3][lm] = tf32r(av0.w);
            As[nxt][lk + 4][lm] = tf32r(av1.x); As[nxt][lk + 5][lm] = tf32r(av1.y);
            As[nxt][lk + 6][lm] = tf32r(av1.z); As[nxt][lk + 7][lm] = tf32r(av1.w);
            *reinterpret_cast<float4*>(&Bs[nxt][bk][bn]) =
                make_float4(tf32r(bv.x), tf32r(bv.y), tf32r(bv.z), tf32r(bv.w));
        }
        __syncthreads();
    }

    #pragma unroll
    for (int i = 0; i < 2; i++) {
        #pragma unroll
        for (int j = 0; j < 4; j++) {
            int col = colBase + nw + j * 8 + tk * 2;
            if (col >= VV) continue;
            float bf0 = bfc[col], bf1 = bfc[col + 1];
            #pragma unroll
            for (int h = 0; h < 2; h++) {
                int rr = rowBase + mw + i * 16 + g + h * 8;
                if (rr < total) {
                    int mapped = d_rowmap[rr];
                    int t = mapped >> 6, b = mapped & 63;
                    float* orow = out + ((size_t)b * TT + t) * VV;
                    orow[col]     = acc[i][j][h * 2]     + bf0;
                    orow[col + 1] = acc[i][j][h * 2 + 1] + bf1;
                }
            }
        }
    }
}

// ---------------- embc = embs(active rows) @ Wih[0:512] : tf32 MMA ----------------
__global__ void __launch_bounds__(256, 2) k_embc_mma(const float* __restrict__ emb,
                                                     const int* __restrict__ caps,
                                                     const float* __restrict__ Wih) {
    int total = d_total;
    int rowBase = blockIdx.x * 128;
    if (rowBase >= total) return;
    int colBase = blockIdx.y * 64;
    const int Nw = 2048;

    __shared__ float As[2][16][136];
    __shared__ float Bs[2][16][72];
    int tid = threadIdx.x;
    int warp = tid >> 5, lane = tid & 31;
    int g = lane >> 2, tk = lane & 3;
    int mw = (warp & 3) * 32, nw = (warp >> 2) * 32;

    int lm = tid >> 1, lk = (tid & 1) << 3;
    int r = rowBase + lm;
    bool rvalid = (r < total);
    const float* Arow;
    {
        int mapped = rvalid ? d_rowmap[r] : 0;
        int t = mapped >> 6, b = mapped & 63;
        int cap = caps[d_sort_src[b] * LL + t];
        Arow = emb + (size_t)cap * EMB;
    }
    int bk = tid >> 4, bn = (tid & 15) << 2;
    int bcol = colBase + bn;

    float acc[2][4][4];
    #pragma unroll
    for (int i = 0; i < 2; i++)
        #pragma unroll
        for (int j = 0; j < 4; j++)
            #pragma unroll
            for (int q = 0; q < 4; q++) acc[i][j][q] = 0.f;

    float4 av0, av1, bv;
    auto loadA = [&](int k0) {
        if (rvalid) {
            av0 = *reinterpret_cast<const float4*>(Arow + k0 + lk);
            av1 = *reinterpret_cast<const float4*>(Arow + k0 + lk + 4);
        } else {
            av0 = make_float4(0.f, 0.f, 0.f, 0.f);
            av1 = av0;
        }
    };
    auto loadB = [&](int k0) {
        bv = *reinterpret_cast<const float4*>(Wih + (size_t)(k0 + bk) * Nw + bcol);
    };

    loadA(0); loadB(0);
    As[0][lk + 0][lm] = tf32r(av0.x); As[0][lk + 1][lm] = tf32r(av0.y);
    As[0][lk + 2][lm] = tf32r(av0.z); As[0][lk + 3][lm] = tf32r(av0.w);
    As[0][lk + 4][lm] = tf32r(av1.x); As[0][lk + 5][lm] = tf32r(av1.y);
    As[0][lk + 6][lm] = tf32r(av1.z); As[0][lk + 7][lm] = tf32r(av1.w);
    *reinterpret_cast<float4*>(&Bs[0][bk][bn]) =
        make_float4(tf32r(bv.x), tf32r(bv.y), tf32r(bv.z), tf32r(bv.w));
    __syncthreads();

    const int ntiles = EMB / 16;
    for (int it = 0; it < ntiles; it++) {
        int cur = it & 1;
        bool more = (it + 1 < ntiles);
        if (more) { loadA((it + 1) * 16); loadB((it + 1) * 16); }
        #pragma unroll
        for (int ks = 0; ks < 16; ks += 8) {
            uint32_t a[2][4], bfr[4][2];
            #pragma unroll
            for (int i = 0; i < 2; i++) {
                a[i][0] = __float_as_uint(As[cur][ks + tk][mw + i * 16 + g]);
                a[i][1] = __float_as_uint(As[cur][ks + tk][mw + i * 16 + g + 8]);
                a[i][2] = __float_as_uint(As[cur][ks + tk + 4][mw + i * 16 + g]);
                a[i][3] = __float_as_uint(As[cur][ks + tk + 4][mw + i * 16 + g + 8]);
            }
            #pragma unroll
            for (int j = 0; j < 4; j++) {
                bfr[j][0] = __float_as_uint(Bs[cur][ks + tk][nw + j * 8 + g]);
                bfr[j][1] = __float_as_uint(Bs[cur][ks + tk + 4][nw + j * 8 + g]);
            }
            #pragma unroll
            for (int i = 0; i < 2; i++)
                #pragma unroll
                for (int j = 0; j < 4; j++)
                    mma_tf32(acc[i][j], a[i], bfr[j]);
        }
        if (more) {
            int nxt = cur ^ 1;
            As[nxt][lk + 0][lm] = tf32r(av0.x); As[nxt][lk + 1][lm] = tf32r(av0.y);
            As[nxt][lk + 2][lm] = tf32r(av0.z); As[nxt][lk + 3][lm] = tf32r(av0.w);
            As[nxt][lk + 4][lm] = tf32r(av1.x); As[nxt][lk + 5][lm] = tf32r(av1.y);
            As[nxt][lk + 6][lm] = tf32r(av1.z); As[nxt][lk + 7][lm] = tf32r(av1.w);
            *reinterpret_cast<float4*>(&Bs[nxt][bk][bn]) =
                make_float4(tf32r(bv.x), tf32r(bv.y), tf32r(bv.z), tf32r(bv.w));
        }
        __syncthreads();
    }

    #pragma unroll
    for (int i = 0; i < 2; i++) {
        #pragma unroll
        for (int j = 0; j < 4; j++) {
            int col = colBase + nw + j * 8 + tk * 2;
            #pragma unroll
            for (int h = 0; h < 2; h++) {
                int rr = rowBase + mw + i * 16 + g + h * 8;
                if (rr < total) {
                    int mapped = d_rowmap[rr];
                    float* orow = d_embc + (size_t)mapped * 2048;
                    orow[col]     = acc[i][j][h * 2];
                    orow[col + 1] = acc[i][j][h * 2 + 1];
                }
            }
        }
    }
}

// ---------------- fused: e -> softmax -> awe, 1024 threads ----------------
__global__ void __launch_bounds__(1024, 1) k_attend(
        const float* __restrict__ enc,
        const float* __restrict__ Wf, const float* __restrict__ bf,
        const float* __restrict__ bd, const float* __restrict__ bb,
        float* __restrict__ out_alphas, int t) {
    int b = blockIdx.x;
    if (b >= d_nb[t]) return;
    __shared__ __align__(16) float a2[ATT];
    __shared__ __align__(16) float wf[ATT];
    __shared__ float es[PP + 4];
    __shared__ float red[32];
    __shared__ float redsum[32];
    __shared__ __align__(16) float awe_sh[2048];
    int tid = threadIdx.x;
    const float* p0 = d_agp + (size_t)b * AGC;
    const float* p1 = d_agp + (size_t)(BB + b) * AGC;
    if (tid < 512) {
        a2[tid] = p0[tid] + p1[tid] + bd[tid];
        wf[tid] = Wf[tid];
    }
    __syncthreads();
    int lane = tid & 31, warp = tid >> 5;

    const float4* a24 = reinterpret_cast<const float4*>(a2);
    const float4* wf4 = reinterpret_cast<const float4*>(wf);
    for (int p = warp; p < PP; p += 32) {
        const float4* row4 = reinterpret_cast<const float4*>(d_att1 + ((size_t)b * PP + p) * ATT);
        float s = 0.f;
        #pragma unroll
        for (int i = 0; i < 4; i++) {
            int idx = lane + i * 32;
            float4 v = row4[idx];
            float4 a = a24[idx];
            float4 w = wf4[idx];
            s += fmaxf(v.x + a.x, 0.f) * w.x;
            s += fmaxf(v.y + a.y, 0.f) * w.y;
            s += fmaxf(v.z + a.z, 0.f) * w.z;
            s += fmaxf(v.w + a.w, 0.f) * w.w;
        }
        #pragma unroll
        for (int off = 16; off > 0; off >>= 1) s += __shfl_xor_sync(0xffffffffu, s, off);
        if (lane == 0) es[p] = s + bf[0];
    }
    __syncthreads();

    float v = (tid < PP) ? es[tid] : -1e30f;
    float m = v;
    #pragma unroll
    for (int off = 16; off > 0; off >>= 1) m = fmaxf(m, __shfl_xor_sync(0xffffffffu, m, off));
    if (lane == 0) red[warp] = m;
    __syncthreads();
    if (tid == 0) {
        float mm = red[0];
        for (int i = 1; i < 32; i++) mm = fmaxf(mm, red[i]);
        red[0] = mm;
    }
    __syncthreads();
    float smax = red[0];
    float ev = (tid < PP) ? __expf(v - smax) : 0.f;
    float s = ev;
    #pragma unroll
    for (int off = 16; off > 0; off >>= 1) s += __shfl_xor_sync(0xffffffffu, s, off);
    if (lane == 0) redsum[warp] = s;
    __syncthreads();
    if (tid == 0) {
        float ss = redsum[0];
        for (int i = 1; i < 32; i++) ss += redsum[i];
        redsum[0] = ss;
    }
    __syncthreads();
    float inv = 1.0f / redsum[0];
    float al = ev * inv;
    if (tid < PP) {
        es[tid] = al;
        out_alphas[((size_t)b * TT + t) * PP + tid] = al;
    }
    __syncthreads();

    int src = d_sort_src[b];
    int half = tid >> 9;
    int c4 = tid & 511;
    const float4* enc4 = reinterpret_cast<const float4*>(enc + (size_t)src * PP * EE);
    int pbeg = half * 98, pend = pbeg + 98;
    float4 acc = make_float4(0.f, 0.f, 0.f, 0.f);
    #pragma unroll 2
    for (int p = pbeg; p < pend; p++) {
        float alp = es[p];
        float4 e4 = enc4[p * 512 + c4];
        acc.x += alp * e4.x; acc.y += alp * e4.y;
        acc.z += alp * e4.z; acc.w += alp * e4.w;
    }
    float4* awe4 = reinterpret_cast<float4*>(awe_sh);
    if (half == 1) awe4[c4] = acc;
    __syncthreads();
    if (half == 0) {
        float4 o = awe4[c4];
        acc.x += o.x; acc.y += o.y; acc.z += o.z; acc.w += o.w;
        float4 gp0 = reinterpret_cast<const float4*>(p0 + 512)[c4];
        float4 gp1 = reinterpret_cast<const float4*>(p1 + 512)[c4];
        float4 bbv = reinterpret_cast<const float4*>(bb)[c4];
        float4 gt;
        gt.x = 1.0f / (1.0f + __expf(-(gp0.x + gp1.x + bbv.x)));
        gt.y = 1.0f / (1.0f + __expf(-(gp0.y + gp1.y + bbv.y)));
        gt.z = 1.0f / (1.0f + __expf(-(gp0.z + gp1.z + bbv.z)));
        gt.w = 1.0f / (1.0f + __expf(-(gp0.w + gp1.w + bbv.w)));
        reinterpret_cast<float4*>(d_awe + (size_t)b * EE)[c4] =
            make_float4(acc.x * gt.x, acc.y * gt.y, acc.z * gt.z, acc.w * gt.w);
    }
}

// ---------------- host launch ----------------
extern "C" void kernel_launch(void* const* d_in, const int* in_sizes, int n_in,
                              void* d_out, int out_size) {
    const float* enc  = (const float*)d_in[0];
    const int*   caps = (const int*)d_in[1];
    const int*   clen = (const int*)d_in[2];
    const float* emb  = (const float*)d_in[3];
    const float* We   = (const float*)d_in[4];
    const float* be   = (const float*)d_in[5];
    const float* Wd   = (const float*)d_in[6];
    const float* bd   = (const float*)d_in[7];
    const float* Wf   = (const float*)d_in[8];
    const float* bf   = (const float*)d_in[9];
    const float* Wih  = (const float*)d_in[10];
    const float* bih  = (const float*)d_in[11];
    const float* Whh  = (const float*)d_in[12];
    const float* bhh  = (const float*)d_in[13];
    const float* Wb   = (const float*)d_in[14];
    const float* bb   = (const float*)d_in[15];
    const float* Whi  = (const float*)d_in[16];
    const float* bhi  = (const float*)d_in[17];
    const float* Wci  = (const float*)d_in[18];
    const float* bci  = (const float*)d_in[19];
    const float* Wfc  = (const float*)d_in[20];
    const float* bfc  = (const float*)d_in[21];
    float* out = (float*)d_out;
    float* out_alphas = out + (size_t)BB * TT * VV;

    k_setup<<<1, 64>>>(clen);
    k_zero<<<2048, 256>>>(out, (size_t)out_size);
    k_mean<<<dim3(8, BB), 256>>>(enc);

    // h0 + c0 in ONE split-K GEMM (concat [Whi|Wci], N=1024, K=2048, S=8)
    k_gemm32<<<dim3(32, 8), 256>>>(BUF_MEAN, Whi, Wci, 512, 512, 512, 1024, EE, 8);
    k_reduce_hc<<<256, 256>>>(bhi, bci);

    // att1 via tf32 tensor cores
    k_att1_mma<<<dim3(98, 8), 256>>>(enc, We, be);

    // embc = embs(active rows) @ Wih[0:512]
    k_embc_mma<<<dim3(16, 32), 256>>>(emb, caps, Wih);

    for (int t = 0; t < TT; t++) {
        // phase A: att2/gate/hg partials, split-K 2, KTILE 32
        k_ag<<<dim3(144, 2), 256>>>(Wd, Wb, Whh, t);
        // attention: sums partials, softmax, gated awe
        k_attend<<<BB, 1024>>>(enc, Wf, bf, bd, bb, out_alphas, t);
        // awe GEMM + fused split-K semaphore LSTM epilogue (3rd & last launch)
        k_awe_lstm<<<dim3(64, 4), 256>>>(Wih + (size_t)512 * 2048, bih, bhh, t);
    }

    // batched vocab projection via tf32 tensor cores
    k_preds_mma<<<dim3(16, 157), 256>>>(Wfc, bfc, out);
}

// round 12
// speedup vs baseline: 1.2302x; 1.2302x over previous
#include <cuda_runtime.h>
#include <cuda_bf16.h>
#include <cstdint>

// Problem constants
#define BB 64
#define PP 196
#define EE 2048
#define LL 32
#define VV 10000
#define EMB 512
#define DEC 512
#define ATT 512
#define TT 31   // L-1 steps

// ---------------- device scratch ----------------
__device__ __align__(16) int   d_sort_src[BB];
__device__ __align__(16) int   d_nb[TT + 1];
__device__ int   d_total;
__device__ __align__(16) int   d_rowmap[BB * TT];
__device__ __align__(16) float d_mean[BB * EE];
__device__ __align__(16) float d_h[BB * DEC];
__device__ __align__(16) float d_c[BB * DEC];
__device__ __align__(16) float d_hhist[(size_t)TT * BB * DEC];
__device__ __align__(16) float d_att1[(size_t)BB * PP * ATT];
__device__ __align__(16) float d_awe[BB * EE];
__device__ __align__(16) float d_embc[(size_t)TT * BB * 2048];
__device__ __align__(16) float d_part[8 * BB * 2048];
// phase-A partials: [split(2)][b(64)][col(4608)] — 0..511 att2, 512..2559 gate, 2560..4607 hg
#define AGC 4608
__device__ __align__(16) float d_agp[2 * BB * AGC];

#define BUF_MEAN 0
#define BUF_AWE  5

__device__ __forceinline__ float* selbuf(int s) {
    switch (s) {
        case BUF_MEAN: return d_mean;
        case BUF_AWE:  return d_awe;
        default:       return nullptr;
    }
}

// ---------------- tf32 helpers ----------------
__device__ __forceinline__ float tf32r(float f) {
    uint32_t u;
    asm("cvt.rna.tf32.f32 %0, %1;" : "=r"(u) : "f"(f));
    return __uint_as_float(u);
}
__device__ __forceinline__ void mma_tf32(float* c, const uint32_t* a, const uint32_t* b) {
    asm volatile("mma.sync.aligned.m16n8k8.row.col.f32.tf32.tf32.f32 "
        "{%0,%1,%2,%3}, {%4,%5,%6,%7}, {%8,%9}, {%0,%1,%2,%3};"
        : "+f"(c[0]), "+f"(c[1]), "+f"(c[2]), "+f"(c[3])
        : "r"(a[0]), "r"(a[1]), "r"(a[2]), "r"(a[3]), "r"(b[0]), "r"(b[1]));
}

// ---------------- setup ----------------
__global__ void k_setup(const int* __restrict__ cap_len) {
    __shared__ int lens[BB];
    __shared__ int nbs[TT + 1];
    __shared__ int off[TT + 1];
    int b = threadIdx.x;
    if (b < BB) lens[b] = cap_len[b];
    __syncthreads();
    if (b < BB) {
        int rank = 0;
        int lb = lens[b];
        for (int j = 0; j < BB; j++) {
            int lj = lens[j];
            if (lj > lb || (lj == lb && j < b)) rank++;
        }
        d_sort_src[rank] = b;
    }
    if (b <= TT) {
        int cnt = 0;
        for (int j = 0; j < BB; j++) if (lens[j] - 1 > b) cnt++;
        d_nb[b] = cnt;
        nbs[b] = cnt;
    }
    __syncthreads();
    if (b == 0) {
        int a = 0;
        for (int t = 0; t < TT; t++) { off[t] = a; a += nbs[t]; }
        d_total = a;
    }
    __syncthreads();
    if (b < BB) {
        for (int t = 0; t < TT; t++)
            if (b < nbs[t]) d_rowmap[off[t] + b] = (t << 6) | b;
    }
}

__global__ void k_zero(float* __restrict__ out, size_t n) {
    size_t i = (size_t)blockIdx.x * blockDim.x + threadIdx.x;
    size_t stride = (size_t)gridDim.x * blockDim.x;
    for (; i < n; i += stride) out[i] = 0.0f;
}

__global__ void k_mean(const float* __restrict__ enc) {
    int b = blockIdx.y;
    int e = blockIdx.x * 256 + threadIdx.x;
    const float* base = enc + (size_t)d_sort_src[b] * PP * EE + e;
    float s = 0.0f;
    #pragma unroll 7
    for (int p = 0; p < PP; p++) s += base[(size_t)p * EE];
    d_mean[b * EE + e] = s * (1.0f / 196.0f);
}

// ---------------- split-K GEMM, KTILE=32, into d_part ----------------
__global__ void __launch_bounds__(256, 2) k_gemm32(
        int xsel, const float* __restrict__ WA, const float* __restrict__ WB,
        int colSplit, int NA, int NB, int Nout, int K, int S, int t) {
    __shared__ __align__(16) float Xs[2][32][68];
    __shared__ __align__(16) float Ws[2][32][34];

    const float* X = selbuf(xsel);
    int tid = threadIdx.x;
    int nb = (t >= 0) ? d_nb[t] : BB;
    int n0 = blockIdx.x * 32;

    const float* W; int wc0, NW;
    if (n0 < colSplit) { W = WA; wc0 = n0; NW = NA; }
    else               { W = WB; wc0 = n0 - colSplit; NW = NB; }

    int s = blockIdx.y;
    int kbeg = s * (K / S);
    int ntiles = (K / S) / 32;

    int nl = tid & 15;
    int mg = tid >> 4;
    int m0 = mg << 2;
    bool rowact = (m0 < nb);

    int lm = tid >> 2, lk = (tid & 3) << 2;
    int wk = tid >> 4, wn = tid & 15;
    bool xact = (lm < nb);
    const float* Xrow = X + (size_t)lm * K;

    float acc[4][2];
    #pragma unroll
    for (int i = 0; i < 4; i++) { acc[i][0] = 0.f; acc[i][1] = 0.f; }

    float4 xr0 = make_float4(0.f, 0.f, 0.f, 0.f), xr1 = xr0;
    float wr00, wr01, wr10, wr11;
    auto loadG = [&](int k0) {
        if (xact) {
            xr0 = *reinterpret_cast<const float4*>(Xrow + k0 + lk);
            xr1 = *reinterpret_cast<const float4*>(Xrow + k0 + lk + 16);
        }
        int kg = k0 + wk;
        wr00 = W[(size_t)kg * NW + wc0 + wn];
        wr01 = W[(size_t)kg * NW + wc0 + wn + 16];
        wr10 = W[(size_t)(kg + 16) * NW + wc0 + wn];
        wr11 = W[(size_t)(kg + 16) * NW + wc0 + wn + 16];
    };
    auto stS = [&](int buf) {
        Xs[buf][lk + 0][lm] = xr0.x; Xs[buf][lk + 1][lm] = xr0.y;
        Xs[buf][lk + 2][lm] = xr0.z; Xs[buf][lk + 3][lm] = xr0.w;
        Xs[buf][lk + 16][lm] = xr1.x; Xs[buf][lk + 17][lm] = xr1.y;
        Xs[buf][lk + 18][lm] = xr1.z; Xs[buf][lk + 19][lm] = xr1.w;
        Ws[buf][wk][wn] = wr00; Ws[buf][wk][wn + 16] = wr01;
        Ws[buf][wk + 16][wn] = wr10; Ws[buf][wk + 16][wn + 16] = wr11;
    };

    loadG(kbeg);
    stS(0);
    __syncthreads();

    for (int it = 0; it < ntiles; it++) {
        int cur = it & 1;
        bool more = (it + 1 < ntiles);
        if (more) loadG(kbeg + (it + 1) * 32);
        if (rowact) {
            #pragma unroll
            for (int kk = 0; kk < 32; kk++) {
                float4 xv = *reinterpret_cast<const float4*>(&Xs[cur][kk][m0]);
                float2 wv = *reinterpret_cast<const float2*>(&Ws[cur][kk][nl * 2]);
                acc[0][0] += xv.x * wv.x; acc[0][1] += xv.x * wv.y;
                acc[1][0] += xv.y * wv.x; acc[1][1] += xv.y * wv.y;
                acc[2][0] += xv.z * wv.x; acc[2][1] += xv.z * wv.y;
                acc[3][0] += xv.w * wv.x; acc[3][1] += xv.w * wv.y;
            }
        }
        if (more) stS(cur ^ 1);
        __syncthreads();
    }

    if (!rowact) return;
    int na = n0 + nl * 2;
    #pragma unroll
    for (int j = 0; j < 4; j++) {
        int m = m0 + j;
        if (m < nb) {
            size_t base = ((size_t)(s * BB + m)) * Nout + na;
            d_part[base] = acc[j][0];
            d_part[base + 1] = acc[j][1];
        }
    }
}

// reduce combined h0/c0 (N=1024, S=8)
__global__ void k_reduce_hc(const float* __restrict__ bhi, const float* __restrict__ bci) {
    int idx = blockIdx.x * 256 + threadIdx.x;
    if (idx >= BB * 1024) return;
    int m = idx >> 10, n = idx & 1023;
    float v = 0.f;
    #pragma unroll
    for (int s = 0; s < 8; s++) v += d_part[((size_t)(s * BB + m)) * 1024 + n];
    if (n < 512) d_h[m * 512 + n] = v + bhi[n];
    else         d_c[m * 512 + (n - 512)] = v + bci[n - 512];
}

// ---------------- phase A: split-K2 KTILE=32 GEMM h @ [Wd|Wb|Whh] -> d_agp ----------------
__global__ void __launch_bounds__(256, 2) k_ag(
        const float* __restrict__ Wd, const float* __restrict__ Wb,
        const float* __restrict__ Whh, int t) {
    __shared__ __align__(16) float Xs[2][32][68];
    __shared__ __align__(16) float Ws[2][32][34];

    int n0 = blockIdx.x * 32;
    int s = blockIdx.y;
    int nb = d_nb[t];

    const float* W; int wc0, NW;
    if (n0 < 512)       { W = Wd;  wc0 = n0;        NW = ATT; }
    else if (n0 < 2560) { W = Wb;  wc0 = n0 - 512;  NW = 2048; }
    else                { W = Whh; wc0 = n0 - 2560; NW = 2048; }

    int kbeg = s * 256;
    const int ntiles = 8;

    int tid = threadIdx.x;
    int nl = tid & 15;
    int mg = tid >> 4;
    int m0 = mg << 2;
    bool rowact = (m0 < nb);

    int lm = tid >> 2, lk = (tid & 3) << 2;
    int wk = tid >> 4, wn = tid & 15;
    bool xact = (lm < nb);
    const float* Xrow = d_h + (size_t)lm * DEC;

    float acc[4][2];
    #pragma unroll
    for (int i = 0; i < 4; i++) { acc[i][0] = 0.f; acc[i][1] = 0.f; }

    float4 xr0 = make_float4(0.f, 0.f, 0.f, 0.f), xr1 = xr0;
    float wr00, wr01, wr10, wr11;
    auto loadG = [&](int k0) {
        if (xact) {
            xr0 = *reinterpret_cast<const float4*>(Xrow + k0 + lk);
            xr1 = *reinterpret_cast<const float4*>(Xrow + k0 + lk + 16);
        }
        int kg = k0 + wk;
        wr00 = W[(size_t)kg * NW + wc0 + wn];
        wr01 = W[(size_t)kg * NW + wc0 + wn + 16];
        wr10 = W[(size_t)(kg + 16) * NW + wc0 + wn];
        wr11 = W[(size_t)(kg + 16) * NW + wc0 + wn + 16];
    };
    auto stS = [&](int buf) {
        Xs[buf][lk + 0][lm] = xr0.x; Xs[buf][lk + 1][lm] = xr0.y;
        Xs[buf][lk + 2][lm] = xr0.z; Xs[buf][lk + 3][lm] = xr0.w;
        Xs[buf][lk + 16][lm] = xr1.x; Xs[buf][lk + 17][lm] = xr1.y;
        Xs[buf][lk + 18][lm] = xr1.z; Xs[buf][lk + 19][lm] = xr1.w;
        Ws[buf][wk][wn] = wr00; Ws[buf][wk][wn + 16] = wr01;
        Ws[buf][wk + 16][wn] = wr10; Ws[buf][wk + 16][wn + 16] = wr11;
    };

    loadG(kbeg);
    stS(0);
    __syncthreads();

    for (int it = 0; it < ntiles; it++) {
        int cur = it & 1;
        bool more = (it + 1 < ntiles);
        if (more) loadG(kbeg + (it + 1) * 32);
        if (rowact) {
            #pragma unroll
            for (int kk = 0; kk < 32; kk++) {
                float4 xv = *reinterpret_cast<const float4*>(&Xs[cur][kk][m0]);
                float2 wv = *reinterpret_cast<const float2*>(&Ws[cur][kk][nl * 2]);
                acc[0][0] += xv.x * wv.x; acc[0][1] += xv.x * wv.y;
                acc[1][0] += xv.y * wv.x; acc[1][1] += xv.y * wv.y;
                acc[2][0] += xv.z * wv.x; acc[2][1] += xv.z * wv.y;
                acc[3][0] += xv.w * wv.x; acc[3][1] += xv.w * wv.y;
            }
        }
        if (more) stS(cur ^ 1);
        __syncthreads();
    }

    if (!rowact) return;
    int na = n0 + nl * 2;
    #pragma unroll
    for (int j = 0; j < 4; j++) {
        int m = m0 + j;
        if (m < nb) {
            size_t base = ((size_t)(s * BB + m)) * AGC + na;
            d_agp[base] = acc[j][0];
            d_agp[base + 1] = acc[j][1];
        }
    }
}

// ---------------- reduce: g = embc + hg(2) + awe parts(4) + biases, LSTM ----------------
__global__ void k_reduce_lstm(const float* __restrict__ bih, const float* __restrict__ bhh, int t) {
    int idx = blockIdx.x * 256 + threadIdx.x;
    int b = idx >> 9, d = idx & 511;
    if (b >= d_nb[t]) return;
    const float* e   = d_embc + ((size_t)((t << 6) | b)) * 2048;
    const float* hg0 = d_agp + (size_t)b * AGC + 2560;
    const float* hg1 = d_agp + (size_t)(BB + b) * AGC + 2560;
    float gi = bih[d]        + bhh[d]        + e[d]        + hg0[d]        + hg1[d];
    float gf = bih[512 + d]  + bhh[512 + d]  + e[512 + d]  + hg0[512 + d]  + hg1[512 + d];
    float gg = bih[1024 + d] + bhh[1024 + d] + e[1024 + d] + hg0[1024 + d] + hg1[1024 + d];
    float go = bih[1536 + d] + bhh[1536 + d] + e[1536 + d] + hg0[1536 + d] + hg1[1536 + d];
    #pragma unroll
    for (int s = 0; s < 4; s++) {
        const float* p = d_part + ((size_t)(s * BB + b)) * 2048;
        gi += p[d]; gf += p[512 + d]; gg += p[1024 + d]; go += p[1536 + d];
    }
    float c = d_c[b * DEC + d];
    float si = 1.0f / (1.0f + __expf(-gi));
    float sf = 1.0f / (1.0f + __expf(-gf));
    float so = 1.0f / (1.0f + __expf(-go));
    float cn = sf * c + si * tanhf(gg);
    float hn = so * tanhf(cn);
    d_c[b * DEC + d] = cn;
    d_h[b * DEC + d] = hn;
    d_hhist[((size_t)t * BB + b) * DEC + d] = hn;
}

// ---------------- att1 = enc[sorted] @ We + be : tf32 MMA ----------------
__global__ void __launch_bounds__(256, 2) k_att1_mma(const float* __restrict__ enc,
                                                     const float* __restrict__ We,
                                                     const float* __restrict__ be) {
    __shared__ float As[2][16][136];
    __shared__ float Bs[2][16][72];
    int tid = threadIdx.x;
    int warp = tid >> 5, lane = tid & 31;
    int g = lane >> 2, tk = lane & 3;
    int mw = (warp & 3) * 32, nw = (warp >> 2) * 32;
    int rowBase = blockIdx.x * 128, colBase = blockIdx.y * 64;

    int lm = tid >> 1, lk = (tid & 1) << 3;
    int r = rowBase + lm;
    int bidx = r / PP, pidx = r % PP;
    const float* Arow = enc + ((size_t)d_sort_src[bidx] * PP + pidx) * EE;
    int bk = tid >> 4, bn = (tid & 15) << 2;

    float acc[2][4][4];
    #pragma unroll
    for (int i = 0; i < 2; i++)
        #pragma unroll
        for (int j = 0; j < 4; j++)
            #pragma unroll
            for (int q = 0; q < 4; q++) acc[i][j][q] = 0.f;

    float4 av0, av1, bv;
    av0 = *reinterpret_cast<const float4*>(Arow + lk);
    av1 = *reinterpret_cast<const float4*>(Arow + lk + 4);
    bv  = *reinterpret_cast<const float4*>(We + (size_t)bk * ATT + colBase + bn);
    As[0][lk + 0][lm] = tf32r(av0.x); As[0][lk + 1][lm] = tf32r(av0.y);
    As[0][lk + 2][lm] = tf32r(av0.z); As[0][lk + 3][lm] = tf32r(av0.w);
    As[0][lk + 4][lm] = tf32r(av1.x); As[0][lk + 5][lm] = tf32r(av1.y);
    As[0][lk + 6][lm] = tf32r(av1.z); As[0][lk + 7][lm] = tf32r(av1.w);
    *reinterpret_cast<float4*>(&Bs[0][bk][bn]) =
        make_float4(tf32r(bv.x), tf32r(bv.y), tf32r(bv.z), tf32r(bv.w));
    __syncthreads();

    const int ntiles = EE / 16;
    for (int it = 0; it < ntiles; it++) {
        int cur = it & 1;
        bool more = (it + 1 < ntiles);
        if (more) {
            int k0 = (it + 1) * 16;
            av0 = *reinterpret_cast<const float4*>(Arow + k0 + lk);
            av1 = *reinterpret_cast<const float4*>(Arow + k0 + lk + 4);
            bv  = *reinterpret_cast<const float4*>(We + (size_t)(k0 + bk) * ATT + colBase + bn);
        }
        #pragma unroll
        for (int ks = 0; ks < 16; ks += 8) {
            uint32_t a[2][4], bfr[4][2];
            #pragma unroll
            for (int i = 0; i < 2; i++) {
                a[i][0] = __float_as_uint(As[cur][ks + tk][mw + i * 16 + g]);
                a[i][1] = __float_as_uint(As[cur][ks + tk][mw + i * 16 + g + 8]);
                a[i][2] = __float_as_uint(As[cur][ks + tk + 4][mw + i * 16 + g]);
                a[i][3] = __float_as_uint(As[cur][ks + tk + 4][mw + i * 16 + g + 8]);
            }
            #pragma unroll
            for (int j = 0; j < 4; j++) {
                bfr[j][0] = __float_as_uint(Bs[cur][ks + tk][nw + j * 8 + g]);
                bfr[j][1] = __float_as_uint(Bs[cur][ks + tk + 4][nw + j * 8 + g]);
            }
            #pragma unroll
            for (int i = 0; i < 2; i++)
                #pragma unroll
                for (int j = 0; j < 4; j++)
                    mma_tf32(acc[i][j], a[i], bfr[j]);
        }
        if (more) {
            int nxt = cur ^ 1;
            As[nxt][lk + 0][lm] = tf32r(av0.x); As[nxt][lk + 1][lm] = tf32r(av0.y);
            As[nxt][lk + 2][lm] = tf32r(av0.z); As[nxt][lk + 3][lm] = tf32r(av0.w);
            As[nxt][lk + 4][lm] = tf32r(av1.x); As[nxt][lk + 5][lm] = tf32r(av1.y);
            As[nxt][lk + 6][lm] = tf32r(av1.z); As[nxt][lk + 7][lm] = tf32r(av1.w);
            *reinterpret_cast<float4*>(&Bs[nxt][bk][bn]) =
                make_float4(tf32r(bv.x), tf32r(bv.y), tf32r(bv.z), tf32r(bv.w));
        }
        __syncthreads();
    }

    #pragma unroll
    for (int i = 0; i < 2; i++) {
        int row0 = rowBase + mw + i * 16 + g;
        #pragma unroll
        for (int j = 0; j < 4; j++) {
            int col = colBase + nw + j * 8 + tk * 2;
            float be0 = be[col], be1 = be[col + 1];
            float2 o0 = make_float2(acc[i][j][0] + be0, acc[i][j][1] + be1);
            float2 o1 = make_float2(acc[i][j][2] + be0, acc[i][j][3] + be1);
            *reinterpret_cast<float2*>(d_att1 + (size_t)row0 * ATT + col) = o0;
            *reinterpret_cast<float2*>(d_att1 + (size_t)(row0 + 8) * ATT + col) = o1;
        }
    }
}

// ---------------- batched preds: tf32 MMA, compact rows @ Wfc ----------------
__global__ void __launch_bounds__(256, 2) k_preds_mma(const float* __restrict__ Wfc,
                                                      const float* __restrict__ bfc,
                                                      float* __restrict__ out) {
    int total = d_total;
    int rowBase = blockIdx.x * 128;
    if (rowBase >= total) return;
    int colBase = blockIdx.y * 64;

    __shared__ float As[2][16][136];
    __shared__ float Bs[2][16][72];
    int tid = threadIdx.x;
    int warp = tid >> 5, lane = tid & 31;
    int g = lane >> 2, tk = lane & 3;
    int mw = (warp & 3) * 32, nw = (warp >> 2) * 32;

    int lm = tid >> 1, lk = (tid & 1) << 3;
    int r = rowBase + lm;
    bool rvalid = (r < total);
    const float* Arow = d_hhist + (size_t)(rvalid ? d_rowmap[r] : 0) * DEC;
    int bk = tid >> 4, bn = (tid & 15) << 2;
    int bcol = colBase + bn;
    bool cvalid = (bcol < VV);

    float acc[2][4][4];
    #pragma unroll
    for (int i = 0; i < 2; i++)
        #pragma unroll
        for (int j = 0; j < 4; j++)
            #pragma unroll
            for (int q = 0; q < 4; q++) acc[i][j][q] = 0.f;

    float4 av0, av1, bv;
    auto loadA = [&](int k0) {
        if (rvalid) {
            av0 = *reinterpret_cast<const float4*>(Arow + k0 + lk);
            av1 = *reinterpret_cast<const float4*>(Arow + k0 + lk + 4);
        } else {
            av0 = make_float4(0.f, 0.f, 0.f, 0.f);
            av1 = av0;
        }
    };
    auto loadB = [&](int k0) {
        if (cvalid) bv = *reinterpret_cast<const float4*>(Wfc + (size_t)(k0 + bk) * VV + bcol);
        else        bv = make_float4(0.f, 0.f, 0.f, 0.f);
    };

    loadA(0); loadB(0);
    As[0][lk + 0][lm] = tf32r(av0.x); As[0][lk + 1][lm] = tf32r(av0.y);
    As[0][lk + 2][lm] = tf32r(av0.z); As[0][lk + 3][lm] = tf32r(av0.w);
    As[0][lk + 4][lm] = tf32r(av1.x); As[0][lk + 5][lm] = tf32r(av1.y);
    As[0][lk + 6][lm] = tf32r(av1.z); As[0][lk + 7][lm] = tf32r(av1.w);
    *reinterpret_cast<float4*>(&Bs[0][bk][bn]) =
        make_float4(tf32r(bv.x), tf32r(bv.y), tf32r(bv.z), tf32r(bv.w));
    __syncthreads();

    const int ntiles = DEC / 16;
    for (int it = 0; it < ntiles; it++) {
        int cur = it & 1;
        bool more = (it + 1 < ntiles);
        if (more) { loadA((it + 1) * 16); loadB((it + 1) * 16); }
        #pragma unroll
        for (int ks = 0; ks < 16; ks += 8) {
            uint32_t a[2][4], bfr[4][2];
            #pragma unroll
            for (int i = 0; i < 2; i++) {
                a[i][0] = __float_as_uint(As[cur][ks + tk][mw + i * 16 + g]);
                a[i][1] = __float_as_uint(As[cur][ks + tk][mw + i * 16 + g + 8]);
                a[i][2] = __float_as_uint(As[cur][ks + tk + 4][mw + i * 16 + g]);
                a[i][3] = __float_as_uint(As[cur][ks + tk + 4][mw + i * 16 + g + 8]);
            }
            #pragma unroll
            for (int j = 0; j < 4; j++) {
                bfr[j][0] = __float_as_uint(Bs[cur][ks + tk][nw + j * 8 + g]);
                bfr[j][1] = __float_as_uint(Bs[cur][ks + tk + 4][nw + j * 8 + g]);
            }
            #pragma unroll
            for (int i = 0; i < 2; i++)
                #pragma unroll
                for (int j = 0; j < 4; j++)
                    mma_tf32(acc[i][j], a[i], bfr[j]);
        }
        if (more) {
            int nxt = cur ^ 1;
            As[nxt][lk + 0][lm] = tf32r(av0.x); As[nxt][lk + 1][lm] = tf32r(av0.y);
            As[nxt][lk + 2][lm] = tf32r(av0.z); As[nxt][lk + 3][lm] = tf32r(av0.w);
            As[nxt][lk + 4][lm] = tf32r(av1.x); As[nxt][lk + 5][lm] = tf32r(av1.y);
            As[nxt][lk + 6][lm] = tf32r(av1.z); As[nxt][lk + 7][lm] = tf32r(av1.w);
            *reinterpret_cast<float4*>(&Bs[nxt][bk][bn]) =
                make_float4(tf32r(bv.x), tf32r(bv.y), tf32r(bv.z), tf32r(bv.w));
        }
        __syncthreads();
    }

    #pragma unroll
    for (int i = 0; i < 2; i++) {
        #pragma unroll
        for (int j = 0; j < 4; j++) {
            int col = colBase + nw + j * 8 + tk * 2;
            if (col >= VV) continue;
            float bf0 = bfc[col], bf1 = bfc[col + 1];
            #pragma unroll
            for (int h = 0; h < 2; h++) {
                int rr = rowBase + mw + i * 16 + g + h * 8;
                if (rr < total) {
                    int mapped = d_rowmap[rr];
                    int t = mapped >> 6, b = mapped & 63;
                    float* orow = out + ((size_t)b * TT + t) * VV;
                    orow[col]     = acc[i][j][h * 2]     + bf0;
                    orow[col + 1] = acc[i][j][h * 2 + 1] + bf1;
                }
            }
        }
    }
}

// ---------------- embc = embs(active rows) @ Wih[0:512] : tf32 MMA ----------------
__global__ void __launch_bounds__(256, 2) k_embc_mma(const float* __restrict__ emb,
                                                     const int* __restrict__ caps,
                                                     const float* __restrict__ Wih) {
    int total = d_total;
    int rowBase = blockIdx.x * 128;
    if (rowBase >= total) return;
    int colBase = blockIdx.y * 64;
    const int Nw = 2048;

    __shared__ float As[2][16][136];
    __shared__ float Bs[2][16][72];
    int tid = threadIdx.x;
    int warp = tid >> 5, lane = tid & 31;
    int g = lane >> 2, tk = lane & 3;
    int mw = (warp & 3) * 32, nw = (warp >> 2) * 32;

    int lm = tid >> 1, lk = (tid & 1) << 3;
    int r = rowBase + lm;
    bool rvalid = (r < total);
    const float* Arow;
    {
        int mapped = rvalid ? d_rowmap[r] : 0;
        int t = mapped >> 6, b = mapped & 63;
        int cap = caps[d_sort_src[b] * LL + t];
        Arow = emb + (size_t)cap * EMB;
    }
    int bk = tid >> 4, bn = (tid & 15) << 2;
    int bcol = colBase + bn;

    float acc[2][4][4];
    #pragma unroll
    for (int i = 0; i < 2; i++)
        #pragma unroll
        for (int j = 0; j < 4; j++)
            #pragma unroll
            for (int q = 0; q < 4; q++) acc[i][j][q] = 0.f;

    float4 av0, av1, bv;
    auto loadA = [&](int k0) {
        if (rvalid) {
            av0 = *reinterpret_cast<const float4*>(Arow + k0 + lk);
            av1 = *reinterpret_cast<const float4*>(Arow + k0 + lk + 4);
        } else {
            av0 = make_float4(0.f, 0.f, 0.f, 0.f);
            av1 = av0;
        }
    };
    auto loadB = [&](int k0) {
        bv = *reinterpret_cast<const float4*>(Wih + (size_t)(k0 + bk) * Nw + bcol);
    };

    loadA(0); loadB(0);
    As[0][lk + 0][lm] = tf32r(av0.x); As[0][lk + 1][lm] = tf32r(av0.y);
    As[0][lk + 2][lm] = tf32r(av0.z); As[0][lk + 3][lm] = tf32r(av0.w);
    As[0][lk + 4][lm] = tf32r(av1.x); As[0][lk + 5][lm] = tf32r(av1.y);
    As[0][lk + 6][lm] = tf32r(av1.z); As[0][lk + 7][lm] = tf32r(av1.w);
    *reinterpret_cast<float4*>(&Bs[0][bk][bn]) =
        make_float4(tf32r(bv.x), tf32r(bv.y), tf32r(bv.z), tf32r(bv.w));
    __syncthreads();

    const int ntiles = EMB / 16;
    for (int it = 0; it < ntiles; it++) {
        int cur = it & 1;
        bool more = (it + 1 < ntiles);
        if (more) { loadA((it + 1) * 16); loadB((it + 1) * 16); }
        #pragma unroll
        for (int ks = 0; ks < 16; ks += 8) {
            uint32_t a[2][4], bfr[4][2];
            #pragma unroll
            for (int i = 0; i < 2; i++) {
                a[i][0] = __float_as_uint(As[cur][ks + tk][mw + i * 16 + g]);
                a[i][1] = __float_as_uint(As[cur][ks + tk][mw + i * 16 + g + 8]);
                a[i][2] = __float_as_uint(As[cur][ks + tk + 4][mw + i * 16 + g]);
                a[i][3] = __float_as_uint(As[cur][ks + tk + 4][mw + i * 16 + g + 8]);
            }
            #pragma unroll
            for (int j = 0; j < 4; j++) {
                bfr[j][0] = __float_as_uint(Bs[cur][ks + tk][nw + j * 8 + g]);
                bfr[j][1] = __float_as_uint(Bs[cur][ks + tk + 4][nw + j * 8 + g]);
            }
            #pragma unroll
            for (int i = 0; i < 2; i++)
                #pragma unroll
                for (int j = 0; j < 4; j++)
                    mma_tf32(acc[i][j], a[i], bfr[j]);
        }
        if (more) {
            int nxt = cur ^ 1;
            As[nxt][lk + 0][lm] = tf32r(av0.x); As[nxt][lk + 1][lm] = tf32r(av0.y);
            As[nxt][lk + 2][lm] = tf32r(av0.z); As[nxt][lk + 3][lm] = tf32r(av0.w);
            As[nxt][lk + 4][lm] = tf32r(av1.x); As[nxt][lk + 5][lm] = tf32r(av1.y);
            As[nxt][lk + 6][lm] = tf32r(av1.z); As[nxt][lk + 7][lm] = tf32r(av1.w);
            *reinterpret_cast<float4*>(&Bs[nxt][bk][bn]) =
                make_float4(tf32r(bv.x), tf32r(bv.y), tf32r(bv.z), tf32r(bv.w));
        }
        __syncthreads();
    }

    #pragma unroll
    for (int i = 0; i < 2; i++) {
        #pragma unroll
        for (int j = 0; j < 4; j++) {
            int col = colBase + nw + j * 8 + tk * 2;
            #pragma unroll
            for (int h = 0; h < 2; h++) {
                int rr = rowBase + mw + i * 16 + g + h * 8;
                if (rr < total) {
                    int mapped = d_rowmap[rr];
                    float* orow = d_embc + (size_t)mapped * 2048;
                    orow[col]     = acc[i][j][h * 2];
                    orow[col + 1] = acc[i][j][h * 2 + 1];
                }
            }
        }
    }
}

// ---------------- fused: e -> softmax -> awe, 1024 threads, 4-way p-split ----------------
__global__ void __launch_bounds__(1024, 1) k_attend(
        const float* __restrict__ enc,
        const float* __restrict__ Wf, const float* __restrict__ bf,
        const float* __restrict__ bd, const float* __restrict__ bb,
        float* __restrict__ out_alphas, int t) {
    int b = blockIdx.x;
    if (b >= d_nb[t]) return;
    __shared__ __align__(16) float a2[ATT];
    __shared__ __align__(16) float wf[ATT];
    __shared__ float es[PP + 4];
    __shared__ float red[32];
    __shared__ float redsum[32];
    __shared__ __align__(16) float awe_sh[3 * 2048];
    int tid = threadIdx.x;
    const float* p0 = d_agp + (size_t)b * AGC;
    const float* p1 = d_agp + (size_t)(BB + b) * AGC;
    if (tid < 512) {
        a2[tid] = p0[tid] + p1[tid] + bd[tid];
        wf[tid] = Wf[tid];
    }
    __syncthreads();
    int lane = tid & 31, warp = tid >> 5;

    const float4* a24 = reinterpret_cast<const float4*>(a2);
    const float4* wf4 = reinterpret_cast<const float4*>(wf);
    for (int p = warp; p < PP; p += 32) {
        const float4* row4 = reinterpret_cast<const float4*>(d_att1 + ((size_t)b * PP + p) * ATT);
        float s = 0.f;
        #pragma unroll
        for (int i = 0; i < 4; i++) {
            int idx = lane + i * 32;
            float4 v = row4[idx];
            float4 a = a24[idx];
            float4 w = wf4[idx];
            s += fmaxf(v.x + a.x, 0.f) * w.x;
            s += fmaxf(v.y + a.y, 0.f) * w.y;
            s += fmaxf(v.z + a.z, 0.f) * w.z;
            s += fmaxf(v.w + a.w, 0.f) * w.w;
        }
        #pragma unroll
        for (int off = 16; off > 0; off >>= 1) s += __shfl_xor_sync(0xffffffffu, s, off);
        if (lane == 0) es[p] = s + bf[0];
    }
    __syncthreads();

    float v = (tid < PP) ? es[tid] : -1e30f;
    float m = v;
    #pragma unroll
    for (int off = 16; off > 0; off >>= 1) m = fmaxf(m, __shfl_xor_sync(0xffffffffu, m, off));
    if (lane == 0) red[warp] = m;
    __syncthreads();
    if (tid == 0) {
        float mm = red[0];
        for (int i = 1; i < 32; i++) mm = fmaxf(mm, red[i]);
        red[0] = mm;
    }
    __syncthreads();
    float smax = red[0];
    float ev = (tid < PP) ? __expf(v - smax) : 0.f;
    float s = ev;
    #pragma unroll
    for (int off = 16; off > 0; off >>= 1) s += __shfl_xor_sync(0xffffffffu, s, off);
    if (lane == 0) redsum[warp] = s;
    __syncthreads();
    if (tid == 0) {
        float ss = redsum[0];
        for (int i = 1; i < 32; i++) ss += redsum[i];
        redsum[0] = ss;
    }
    __syncthreads();
    float inv = 1.0f / redsum[0];
    float al = ev * inv;
    if (tid < PP) {
        es[tid] = al;
        out_alphas[((size_t)b * TT + t) * PP + tid] = al;
    }
    __syncthreads();

    // awe: 4-way p-split (196 = 4*49). Quarter q covers p in [q*49, q*49+49),
    // each thread handles 2 float4 columns (c4a, c4a+256) for high MLP.
    int src = d_sort_src[b];
    int quarter = tid >> 8;      // 0..3
    int c4a = tid & 255;         // float4 col 0..255
    const float4* enc4 = reinterpret_cast<const float4*>(enc + (size_t)src * PP * EE);
    int pbeg = quarter * 49, pend = pbeg + 49;
    float4 accA = make_float4(0.f, 0.f, 0.f, 0.f);
    float4 accB = make_float4(0.f, 0.f, 0.f, 0.f);
    for (int p = pbeg; p < pend; p++) {
        float alp = es[p];
        float4 eA = enc4[p * 512 + c4a];
        float4 eB = enc4[p * 512 + c4a + 256];
        accA.x += alp * eA.x; accA.y += alp * eA.y;
        accA.z += alp * eA.z; accA.w += alp * eA.w;
        accB.x += alp * eB.x; accB.y += alp * eB.y;
        accB.z += alp * eB.z; accB.w += alp * eB.w;
    }
    float4* sh4 = reinterpret_cast<float4*>(awe_sh);
    if (quarter > 0) {
        sh4[(quarter - 1) * 512 + c4a] = accA;
        sh4[(quarter - 1) * 512 + c4a + 256] = accB;
    }
    __syncthreads();
    if (quarter == 0) {
        #pragma unroll
        for (int q = 0; q < 3; q++) {
            float4 oA = sh4[q * 512 + c4a];
            float4 oB = sh4[q * 512 + c4a + 256];
            accA.x += oA.x; accA.y += oA.y; accA.z += oA.z; accA.w += oA.w;
            accB.x += oB.x; accB.y += oB.y; accB.z += oB.z; accB.w += oB.w;
        }
        const float4* gp04 = reinterpret_cast<const float4*>(p0 + 512);
        const float4* gp14 = reinterpret_cast<const float4*>(p1 + 512);
        const float4* bb4 = reinterpret_cast<const float4*>(bb);
        float4* awe4 = reinterpret_cast<float4*>(d_awe + (size_t)b * EE);
        #pragma unroll
        for (int h = 0; h < 2; h++) {
            int c4 = c4a + h * 256;
            float4 acc = h ? accB : accA;
            float4 gp0 = gp04[c4], gp1 = gp14[c4], bbv = bb4[c4];
            float4 gt;
            gt.x = 1.0f / (1.0f + __expf(-(gp0.x + gp1.x + bbv.x)));
            gt.y = 1.0f / (1.0f + __expf(-(gp0.y + gp1.y + bbv.y)));
            gt.z = 1.0f / (1.0f + __expf(-(gp0.z + gp1.z + bbv.z)));
            gt.w = 1.0f / (1.0f + __expf(-(gp0.w + gp1.w + bbv.w)));
            awe4[c4] = make_float4(acc.x * gt.x, acc.y * gt.y, acc.z * gt.z, acc.w * gt.w);
        }
    }
}

// ---------------- host launch ----------------
extern "C" void kernel_launch(void* const* d_in, const int* in_sizes, int n_in,
                              void* d_out, int out_size) {
    const float* enc  = (const float*)d_in[0];
    const int*   caps = (const int*)d_in[1];
    const int*   clen = (const int*)d_in[2];
    const float* emb  = (const float*)d_in[3];
    const float* We   = (const float*)d_in[4];
    const float* be   = (const float*)d_in[5];
    const float* Wd   = (const float*)d_in[6];
    const float* bd   = (const float*)d_in[7];
    const float* Wf   = (const float*)d_in[8];
    const float* bf   = (const float*)d_in[9];
    const float* Wih  = (const float*)d_in[10];
    const float* bih  = (const float*)d_in[11];
    const float* Whh  = (const float*)d_in[12];
    const float* bhh  = (const float*)d_in[13];
    const float* Wb   = (const float*)d_in[14];
    const float* bb   = (const float*)d_in[15];
    const float* Whi  = (const float*)d_in[16];
    const float* bhi  = (const float*)d_in[17];
    const float* Wci  = (const float*)d_in[18];
    const float* bci  = (const float*)d_in[19];
    const float* Wfc  = (const float*)d_in[20];
    const float* bfc  = (const float*)d_in[21];
    float* out = (float*)d_out;
    float* out_alphas = out + (size_t)BB * TT * VV;

    k_setup<<<1, 64>>>(clen);
    k_zero<<<2048, 256>>>(out, (size_t)out_size);
    k_mean<<<dim3(8, BB), 256>>>(enc);

    // h0 + c0 in ONE split-K GEMM (concat [Whi|Wci], N=1024, K=2048, S=8)
    k_gemm32<<<dim3(32, 8), 256>>>(BUF_MEAN, Whi, Wci, 512, 512, 512, 1024, EE, 8, -1);
    k_reduce_hc<<<256, 256>>>(bhi, bci);

    // att1 via tf32 tensor cores
    k_att1_mma<<<dim3(98, 8), 256>>>(enc, We, be);

    // embc = embs(active rows) @ Wih[0:512]
    k_embc_mma<<<dim3(16, 32), 256>>>(emb, caps, Wih);

    for (int t = 0; t < TT; t++) {
        // phase A: att2/gate/hg partials, split-K 2, KTILE 32
        k_ag<<<dim3(144, 2), 256>>>(Wd, Wb, Whh, t);
        // attention: sums partials, softmax, gated awe (4-way p-split)
        k_attend<<<BB, 1024>>>(enc, Wf, bf, bd, bb, out_alphas, t);
        // awe part: d_awe @ Wih[512:2560] (K=2048, S=4, KTILE 32)
        k_gemm32<<<dim3(64, 4), 256>>>(BUF_AWE, Wih + (size_t)512 * 2048, nullptr,
                                       1 << 30, 2048, 0, 2048, 2048, 4, t);
        // g = embc + hg + awe-partials + biases, LSTM pointwise
        k_reduce_lstm<<<128, 256>>>(bih, bhh, t);
    }

    // batched vocab projection via tf32 tensor cores
    k_preds_mma<<<dim3(16, 157), 256>>>(Wfc, bfc, out);
}

// round 13
// speedup vs baseline: 1.3291x; 1.0804x over previous
#include <cuda_runtime.h>
#include <cuda_bf16.h>
#include <cstdint>

// Problem constants
#define BB 64
#define PP 196
#define EE 2048
#define LL 32
#define VV 10000
#define EMB 512
#define DEC 512
#define ATT 512
#define TT 31   // L-1 steps

// ---------------- device scratch ----------------
__device__ __align__(16) int   d_sort_src[BB];
__device__ __align__(16) int   d_nb[TT + 1];
__device__ int   d_total;
__device__ __align__(16) int   d_rowmap[BB * TT];
__device__ __align__(16) float d_mean[BB * EE];
__device__ __align__(16) float d_h[BB * DEC];
__device__ __align__(16) float d_c[BB * DEC];
__device__ __align__(16) float d_hhist[(size_t)TT * BB * DEC];
__device__ __align__(16) float d_att1[(size_t)BB * PP * ATT];
__device__ __align__(16) float d_awe[BB * EE];
__device__ __align__(16) float d_embc[(size_t)TT * BB * 2048];
__device__ __align__(16) float d_part[8 * BB * 2048];
// phase-A partials: [split(2)][b(64)][col(4608)] — 0..511 att2, 512..2559 gate, 2560..4607 hg
#define AGC 4608
__device__ __align__(16) float d_agp[2 * BB * AGC];

#define BUF_MEAN 0

__device__ __forceinline__ float* selbuf(int s) {
    switch (s) {
        case BUF_MEAN: return d_mean;
        default:       return nullptr;
    }
}

// ---------------- tf32 helpers ----------------
__device__ __forceinline__ float tf32r(float f) {
    uint32_t u;
    asm("cvt.rna.tf32.f32 %0, %1;" : "=r"(u) : "f"(f));
    return __uint_as_float(u);
}
__device__ __forceinline__ void mma_tf32(float* c, const uint32_t* a, const uint32_t* b) {
    asm volatile("mma.sync.aligned.m16n8k8.row.col.f32.tf32.tf32.f32 "
        "{%0,%1,%2,%3}, {%4,%5,%6,%7}, {%8,%9}, {%0,%1,%2,%3};"
        : "+f"(c[0]), "+f"(c[1]), "+f"(c[2]), "+f"(c[3])
        : "r"(a[0]), "r"(a[1]), "r"(a[2]), "r"(a[3]), "r"(b[0]), "r"(b[1]));
}

// ---------------- setup ----------------
__global__ void k_setup(const int* __restrict__ cap_len) {
    __shared__ int lens[BB];
    __shared__ int nbs[TT + 1];
    __shared__ int off[TT + 1];
    int b = threadIdx.x;
    if (b < BB) lens[b] = cap_len[b];
    __syncthreads();
    if (b < BB) {
        int rank = 0;
        int lb = lens[b];
        for (int j = 0; j < BB; j++) {
            int lj = lens[j];
            if (lj > lb || (lj == lb && j < b)) rank++;
        }
        d_sort_src[rank] = b;
    }
    if (b <= TT) {
        int cnt = 0;
        for (int j = 0; j < BB; j++) if (lens[j] - 1 > b) cnt++;
        d_nb[b] = cnt;
        nbs[b] = cnt;
    }
    __syncthreads();
    if (b == 0) {
        int a = 0;
        for (int t = 0; t < TT; t++) { off[t] = a; a += nbs[t]; }
        d_total = a;
    }
    __syncthreads();
    if (b < BB) {
        for (int t = 0; t < TT; t++)
            if (b < nbs[t]) d_rowmap[off[t] + b] = (t << 6) | b;
    }
}

__global__ void k_zero(float* __restrict__ out, size_t n) {
    size_t i = (size_t)blockIdx.x * blockDim.x + threadIdx.x;
    size_t stride = (size_t)gridDim.x * blockDim.x;
    for (; i < n; i += stride) out[i] = 0.0f;
}

__global__ void k_mean(const float* __restrict__ enc) {
    int b = blockIdx.y;
    int e = blockIdx.x * 256 + threadIdx.x;
    const float* base = enc + (size_t)d_sort_src[b] * PP * EE + e;
    float s = 0.0f;
    #pragma unroll 7
    for (int p = 0; p < PP; p++) s += base[(size_t)p * EE];
    d_mean[b * EE + e] = s * (1.0f / 196.0f);
}

// ---------------- split-K GEMM, KTILE=32, into d_part (h0/c0 only) ----------------
__global__ void __launch_bounds__(256, 2) k_gemm32(
        int xsel, const float* __restrict__ WA, const float* __restrict__ WB,
        int colSplit, int NA, int NB, int Nout, int K, int S, int t) {
    __shared__ __align__(16) float Xs[2][32][68];
    __shared__ __align__(16) float Ws[2][32][34];

    const float* X = selbuf(xsel);
    int tid = threadIdx.x;
    int nb = (t >= 0) ? d_nb[t] : BB;
    int n0 = blockIdx.x * 32;

    const float* W; int wc0, NW;
    if (n0 < colSplit) { W = WA; wc0 = n0; NW = NA; }
    else               { W = WB; wc0 = n0 - colSplit; NW = NB; }

    int s = blockIdx.y;
    int kbeg = s * (K / S);
    int ntiles = (K / S) / 32;

    int nl = tid & 15;
    int mg = tid >> 4;
    int m0 = mg << 2;
    bool rowact = (m0 < nb);

    int lm = tid >> 2, lk = (tid & 3) << 2;
    int wk = tid >> 4, wn = tid & 15;
    bool xact = (lm < nb);
    const float* Xrow = X + (size_t)lm * K;

    float acc[4][2];
    #pragma unroll
    for (int i = 0; i < 4; i++) { acc[i][0] = 0.f; acc[i][1] = 0.f; }

    float4 xr0 = make_float4(0.f, 0.f, 0.f, 0.f), xr1 = xr0;
    float wr00, wr01, wr10, wr11;
    auto loadG = [&](int k0) {
        if (xact) {
            xr0 = *reinterpret_cast<const float4*>(Xrow + k0 + lk);
            xr1 = *reinterpret_cast<const float4*>(Xrow + k0 + lk + 16);
        }
        int kg = k0 + wk;
        wr00 = W[(size_t)kg * NW + wc0 + wn];
        wr01 = W[(size_t)kg * NW + wc0 + wn + 16];
        wr10 = W[(size_t)(kg + 16) * NW + wc0 + wn];
        wr11 = W[(size_t)(kg + 16) * NW + wc0 + wn + 16];
    };
    auto stS = [&](int buf) {
        Xs[buf][lk + 0][lm] = xr0.x; Xs[buf][lk + 1][lm] = xr0.y;
        Xs[buf][lk + 2][lm] = xr0.z; Xs[buf][lk + 3][lm] = xr0.w;
        Xs[buf][lk + 16][lm] = xr1.x; Xs[buf][lk + 17][lm] = xr1.y;
        Xs[buf][lk + 18][lm] = xr1.z; Xs[buf][lk + 19][lm] = xr1.w;
        Ws[buf][wk][wn] = wr00; Ws[buf][wk][wn + 16] = wr01;
        Ws[buf][wk + 16][wn] = wr10; Ws[buf][wk + 16][wn + 16] = wr11;
    };

    loadG(kbeg);
    stS(0);
    __syncthreads();

    for (int it = 0; it < ntiles; it++) {
        int cur = it & 1;
        bool more = (it + 1 < ntiles);
        if (more) loadG(kbeg + (it + 1) * 32);
        if (rowact) {
            #pragma unroll
            for (int kk = 0; kk < 32; kk++) {
                float4 xv = *reinterpret_cast<const float4*>(&Xs[cur][kk][m0]);
                float2 wv = *reinterpret_cast<const float2*>(&Ws[cur][kk][nl * 2]);
                acc[0][0] += xv.x * wv.x; acc[0][1] += xv.x * wv.y;
                acc[1][0] += xv.y * wv.x; acc[1][1] += xv.y * wv.y;
                acc[2][0] += xv.z * wv.x; acc[2][1] += xv.z * wv.y;
                acc[3][0] += xv.w * wv.x; acc[3][1] += xv.w * wv.y;
            }
        }
        if (more) stS(cur ^ 1);
        __syncthreads();
    }

    if (!rowact) return;
    int na = n0 + nl * 2;
    #pragma unroll
    for (int j = 0; j < 4; j++) {
        int m = m0 + j;
        if (m < nb) {
            size_t base = ((size_t)(s * BB + m)) * Nout + na;
            d_part[base] = acc[j][0];
            d_part[base + 1] = acc[j][1];
        }
    }
}

// reduce combined h0/c0 (N=1024, S=8)
__global__ void k_reduce_hc(const float* __restrict__ bhi, const float* __restrict__ bci) {
    int idx = blockIdx.x * 256 + threadIdx.x;
    if (idx >= BB * 1024) return;
    int m = idx >> 10, n = idx & 1023;
    float v = 0.f;
    #pragma unroll
    for (int s = 0; s < 8; s++) v += d_part[((size_t)(s * BB + m)) * 1024 + n];
    if (n < 512) d_h[m * 512 + n] = v + bhi[n];
    else         d_c[m * 512 + (n - 512)] = v + bci[n - 512];
}

// ---------------- phase A: split-K2 KTILE=32 GEMM h @ [Wd|Wb|Whh] -> d_agp ----------------
__global__ void __launch_bounds__(256, 2) k_ag(
        const float* __restrict__ Wd, const float* __restrict__ Wb,
        const float* __restrict__ Whh, int t) {
    __shared__ __align__(16) float Xs[2][32][68];
    __shared__ __align__(16) float Ws[2][32][34];

    int n0 = blockIdx.x * 32;
    int s = blockIdx.y;
    int nb = d_nb[t];

    const float* W; int wc0, NW;
    if (n0 < 512)       { W = Wd;  wc0 = n0;        NW = ATT; }
    else if (n0 < 2560) { W = Wb;  wc0 = n0 - 512;  NW = 2048; }
    else                { W = Whh; wc0 = n0 - 2560; NW = 2048; }

    int kbeg = s * 256;
    const int ntiles = 8;

    int tid = threadIdx.x;
    int nl = tid & 15;
    int mg = tid >> 4;
    int m0 = mg << 2;
    bool rowact = (m0 < nb);

    int lm = tid >> 2, lk = (tid & 3) << 2;
    int wk = tid >> 4, wn = tid & 15;
    bool xact = (lm < nb);
    const float* Xrow = d_h + (size_t)lm * DEC;

    float acc[4][2];
    #pragma unroll
    for (int i = 0; i < 4; i++) { acc[i][0] = 0.f; acc[i][1] = 0.f; }

    float4 xr0 = make_float4(0.f, 0.f, 0.f, 0.f), xr1 = xr0;
    float wr00, wr01, wr10, wr11;
    auto loadG = [&](int k0) {
        if (xact) {
            xr0 = *reinterpret_cast<const float4*>(Xrow + k0 + lk);
            xr1 = *reinterpret_cast<const float4*>(Xrow + k0 + lk + 16);
        }
        int kg = k0 + wk;
        wr00 = W[(size_t)kg * NW + wc0 + wn];
        wr01 = W[(size_t)kg * NW + wc0 + wn + 16];
        wr10 = W[(size_t)(kg + 16) * NW + wc0 + wn];
        wr11 = W[(size_t)(kg + 16) * NW + wc0 + wn + 16];
    };
    auto stS = [&](int buf) {
        Xs[buf][lk + 0][lm] = xr0.x; Xs[buf][lk + 1][lm] = xr0.y;
        Xs[buf][lk + 2][lm] = xr0.z; Xs[buf][lk + 3][lm] = xr0.w;
        Xs[buf][lk + 16][lm] = xr1.x; Xs[buf][lk + 17][lm] = xr1.y;
        Xs[buf][lk + 18][lm] = xr1.z; Xs[buf][lk + 19][lm] = xr1.w;
        Ws[buf][wk][wn] = wr00; Ws[buf][wk][wn + 16] = wr01;
        Ws[buf][wk + 16][wn] = wr10; Ws[buf][wk + 16][wn + 16] = wr11;
    };

    loadG(kbeg);
    stS(0);
    __syncthreads();

    for (int it = 0; it < ntiles; it++) {
        int cur = it & 1;
        bool more = (it + 1 < ntiles);
        if (more) loadG(kbeg + (it + 1) * 32);
        if (rowact) {
            #pragma unroll
            for (int kk = 0; kk < 32; kk++) {
                float4 xv = *reinterpret_cast<const float4*>(&Xs[cur][kk][m0]);
                float2 wv = *reinterpret_cast<const float2*>(&Ws[cur][kk][nl * 2]);
                acc[0][0] += xv.x * wv.x; acc[0][1] += xv.x * wv.y;
                acc[1][0] += xv.y * wv.x; acc[1][1] += xv.y * wv.y;
                acc[2][0] += xv.z * wv.x; acc[2][1] += xv.z * wv.y;
                acc[3][0] += xv.w * wv.x; acc[3][1] += xv.w * wv.y;
            }
        }
        if (more) stS(cur ^ 1);
        __syncthreads();
    }

    if (!rowact) return;
    int na = n0 + nl * 2;
    #pragma unroll
    for (int j = 0; j < 4; j++) {
        int m = m0 + j;
        if (m < nb) {
            size_t base = ((size_t)(s * BB + m)) * AGC + na;
            d_agp[base] = acc[j][0];
            d_agp[base + 1] = acc[j][1];
        }
    }
}

// ---------------- awe GEMM via tf32 MMA: d_awe(64,2048) @ Wih2(2048,2048), S=8 ----------------
// Tile M=64, N=128; grid (16 n-tiles, 8 k-splits); 8 warps = 2(m) x 4(n), warp tile 32x32.
__global__ void __launch_bounds__(256, 2) k_awe_mma(const float* __restrict__ Wih2, int t) {
    __shared__ float As[2][16][72];    // [k][m]
    __shared__ float Bs[2][16][136];   // [k][n]
    int nb = d_nb[t];
    int tid = threadIdx.x;
    int warp = tid >> 5, lane = tid & 31;
    int g = lane >> 2, tk = lane & 3;
    int mw = (warp & 1) * 32, nw = (warp >> 1) * 32;
    int nBase = blockIdx.x * 128;
    int s = blockIdx.y;
    int kbeg = s * 256;
    const int ntiles = 16;

    int lm = tid >> 2, lk = (tid & 3) << 2;   // A: 64 rows x 4 threads/row (k-float4)
    bool xact = (lm < nb);
    const float* Arow = d_awe + (size_t)lm * 2048;
    int bk = tid >> 4, bn = (tid & 15) << 2;  // B: 16 k-rows x 16 threads (each 2 float4)
    bool wact = (mw < nb);

    float acc[2][4][4];
    #pragma unroll
    for (int i = 0; i < 2; i++)
        #pragma unroll
        for (int j = 0; j < 4; j++)
            #pragma unroll
            for (int q = 0; q < 4; q++) acc[i][j][q] = 0.f;

    float4 av = make_float4(0.f, 0.f, 0.f, 0.f), bv0, bv1;
    auto loadG = [&](int k0) {
        if (xact) av = *reinterpret_cast<const float4*>(Arow + k0 + lk);
        const float* wr = Wih2 + (size_t)(k0 + bk) * 2048 + nBase + bn;
        bv0 = *reinterpret_cast<const float4*>(wr);
        bv1 = *reinterpret_cast<const float4*>(wr + 64);
    };
    auto stS = [&](int buf) {
        As[buf][lk + 0][lm] = tf32r(av.x); As[buf][lk + 1][lm] = tf32r(av.y);
        As[buf][lk + 2][lm] = tf32r(av.z); As[buf][lk + 3][lm] = tf32r(av.w);
        *reinterpret_cast<float4*>(&Bs[buf][bk][bn]) =
            make_float4(tf32r(bv0.x), tf32r(bv0.y), tf32r(bv0.z), tf32r(bv0.w));
        *reinterpret_cast<float4*>(&Bs[buf][bk][bn + 64]) =
            make_float4(tf32r(bv1.x), tf32r(bv1.y), tf32r(bv1.z), tf32r(bv1.w));
    };

    loadG(kbeg);
    stS(0);
    __syncthreads();

    for (int it = 0; it < ntiles; it++) {
        int cur = it & 1;
        bool more = (it + 1 < ntiles);
        if (more) loadG(kbeg + (it + 1) * 16);
        if (wact) {
            #pragma unroll
            for (int ks = 0; ks < 16; ks += 8) {
                uint32_t a[2][4], bfr[4][2];
                #pragma unroll
                for (int i = 0; i < 2; i++) {
                    a[i][0] = __float_as_uint(As[cur][ks + tk][mw + i * 16 + g]);
                    a[i][1] = __float_as_uint(As[cur][ks + tk][mw + i * 16 + g + 8]);
                    a[i][2] = __float_as_uint(As[cur][ks + tk + 4][mw + i * 16 + g]);
                    a[i][3] = __float_as_uint(As[cur][ks + tk + 4][mw + i * 16 + g + 8]);
                }
                #pragma unroll
                for (int j = 0; j < 4; j++) {
                    bfr[j][0] = __float_as_uint(Bs[cur][ks + tk][nw + j * 8 + g]);
                    bfr[j][1] = __float_as_uint(Bs[cur][ks + tk + 4][nw + j * 8 + g]);
                }
                #pragma unroll
                for (int i = 0; i < 2; i++)
                    #pragma unroll
                    for (int j = 0; j < 4; j++)
                        mma_tf32(acc[i][j], a[i], bfr[j]);
            }
        }
        if (more) stS(cur ^ 1);
        __syncthreads();
    }

    if (!wact) return;
    #pragma unroll
    for (int i = 0; i < 2; i++) {
        #pragma unroll
        for (int j = 0; j < 4; j++) {
            int col = nBase + nw + j * 8 + tk * 2;
            #pragma unroll
            for (int h = 0; h < 2; h++) {
                int row = mw + i * 16 + g + h * 8;
                if (row < nb) {
                    float* p = d_part + ((size_t)(s * BB + row)) * 2048 + col;
                    p[0] = acc[i][j][h * 2];
                    p[1] = acc[i][j][h * 2 + 1];
                }
            }
        }
    }
}

// ---------------- reduce: g = embc + hg(2) + awe parts(8) + biases, LSTM ----------------
__global__ void k_reduce_lstm(const float* __restrict__ bih, const float* __restrict__ bhh, int t) {
    int idx = blockIdx.x * 256 + threadIdx.x;
    int b = idx >> 9, d = idx & 511;
    if (b >= d_nb[t]) return;
    const float* e   = d_embc + ((size_t)((t << 6) | b)) * 2048;
    const float* hg0 = d_agp + (size_t)b * AGC + 2560;
    const float* hg1 = d_agp + (size_t)(BB + b) * AGC + 2560;
    float gi = bih[d]        + bhh[d]        + e[d]        + hg0[d]        + hg1[d];
    float gf = bih[512 + d]  + bhh[512 + d]  + e[512 + d]  + hg0[512 + d]  + hg1[512 + d];
    float gg = bih[1024 + d] + bhh[1024 + d] + e[1024 + d] + hg0[1024 + d] + hg1[1024 + d];
    float go = bih[1536 + d] + bhh[1536 + d] + e[1536 + d] + hg0[1536 + d] + hg1[1536 + d];
    #pragma unroll
    for (int s = 0; s < 8; s++) {
        const float* p = d_part + ((size_t)(s * BB + b)) * 2048;
        gi += p[d]; gf += p[512 + d]; gg += p[1024 + d]; go += p[1536 + d];
    }
    float c = d_c[b * DEC + d];
    float si = 1.0f / (1.0f + __expf(-gi));
    float sf = 1.0f / (1.0f + __expf(-gf));
    float so = 1.0f / (1.0f + __expf(-go));
    float cn = sf * c + si * tanhf(gg);
    float hn = so * tanhf(cn);
    d_c[b * DEC + d] = cn;
    d_h[b * DEC + d] = hn;
    d_hhist[((size_t)t * BB + b) * DEC + d] = hn;
}

// ---------------- att1 = enc[sorted] @ We + be : tf32 MMA ----------------
__global__ void __launch_bounds__(256, 2) k_att1_mma(const float* __restrict__ enc,
                                                     const float* __restrict__ We,
                                                     const float* __restrict__ be) {
    __shared__ float As[2][16][136];
    __shared__ float Bs[2][16][72];
    int tid = threadIdx.x;
    int warp = tid >> 5, lane = tid & 31;
    int g = lane >> 2, tk = lane & 3;
    int mw = (warp & 3) * 32, nw = (warp >> 2) * 32;
    int rowBase = blockIdx.x * 128, colBase = blockIdx.y * 64;

    int lm = tid >> 1, lk = (tid & 1) << 3;
    int r = rowBase + lm;
    int bidx = r / PP, pidx = r % PP;
    const float* Arow = enc + ((size_t)d_sort_src[bidx] * PP + pidx) * EE;
    int bk = tid >> 4, bn = (tid & 15) << 2;

    float acc[2][4][4];
    #pragma unroll
    for (int i = 0; i < 2; i++)
        #pragma unroll
        for (int j = 0; j < 4; j++)
            #pragma unroll
            for (int q = 0; q < 4; q++) acc[i][j][q] = 0.f;

    float4 av0, av1, bv;
    av0 = *reinterpret_cast<const float4*>(Arow + lk);
    av1 = *reinterpret_cast<const float4*>(Arow + lk + 4);
    bv  = *reinterpret_cast<const float4*>(We + (size_t)bk * ATT + colBase + bn);
    As[0][lk + 0][lm] = tf32r(av0.x); As[0][lk + 1][lm] = tf32r(av0.y);
    As[0][lk + 2][lm] = tf32r(av0.z); As[0][lk + 3][lm] = tf32r(av0.w);
    As[0][lk + 4][lm] = tf32r(av1.x); As[0][lk + 5][lm] = tf32r(av1.y);
    As[0][lk + 6][lm] = tf32r(av1.z); As[0][lk + 7][lm] = tf32r(av1.w);
    *reinterpret_cast<float4*>(&Bs[0][bk][bn]) =
        make_float4(tf32r(bv.x), tf32r(bv.y), tf32r(bv.z), tf32r(bv.w));
    __syncthreads();

    const int ntiles = EE / 16;
    for (int it = 0; it < ntiles; it++) {
        int cur = it & 1;
        bool more = (it + 1 < ntiles);
        if (more) {
            int k0 = (it + 1) * 16;
            av0 = *reinterpret_cast<const float4*>(Arow + k0 + lk);
            av1 = *reinterpret_cast<const float4*>(Arow + k0 + lk + 4);
            bv  = *reinterpret_cast<const float4*>(We + (size_t)(k0 + bk) * ATT + colBase + bn);
        }
        #pragma unroll
        for (int ks = 0; ks < 16; ks += 8) {
            uint32_t a[2][4], bfr[4][2];
            #pragma unroll
            for (int i = 0; i < 2; i++) {
                a[i][0] = __float_as_uint(As[cur][ks + tk][mw + i * 16 + g]);
                a[i][1] = __float_as_uint(As[cur][ks + tk][mw + i * 16 + g + 8]);
                a[i][2] = __float_as_uint(As[cur][ks + tk + 4][mw + i * 16 + g]);
                a[i][3] = __float_as_uint(As[cur][ks + tk + 4][mw + i * 16 + g + 8]);
            }
            #pragma unroll
            for (int j = 0; j < 4; j++) {
                bfr[j][0] = __float_as_uint(Bs[cur][ks + tk][nw + j * 8 + g]);
                bfr[j][1] = __float_as_uint(Bs[cur][ks + tk + 4][nw + j * 8 + g]);
            }
            #pragma unroll
            for (int i = 0; i < 2; i++)
                #pragma unroll
                for (int j = 0; j < 4; j++)
                    mma_tf32(acc[i][j], a[i], bfr[j]);
        }
        if (more) {
            int nxt = cur ^ 1;
            As[nxt][lk + 0][lm] = tf32r(av0.x); As[nxt][lk + 1][lm] = tf32r(av0.y);
            As[nxt][lk + 2][lm] = tf32r(av0.z); As[nxt][lk + 3][lm] = tf32r(av0.w);
            As[nxt][lk + 4][lm] = tf32r(av1.x); As[nxt][lk + 5][lm] = tf32r(av1.y);
            As[nxt][lk + 6][lm] = tf32r(av1.z); As[nxt][lk + 7][lm] = tf32r(av1.w);
            *reinterpret_cast<float4*>(&Bs[nxt][bk][bn]) =
                make_float4(tf32r(bv.x), tf32r(bv.y), tf32r(bv.z), tf32r(bv.w));
        }
        __syncthreads();
    }

    #pragma unroll
    for (int i = 0; i < 2; i++) {
        int row0 = rowBase + mw + i * 16 + g;
        #pragma unroll
        for (int j = 0; j < 4; j++) {
            int col = colBase + nw + j * 8 + tk * 2;
            float be0 = be[col], be1 = be[col + 1];
            float2 o0 = make_float2(acc[i][j][0] + be0, acc[i][j][1] + be1);
            float2 o1 = make_float2(acc[i][j][2] + be0, acc[i][j][3] + be1);
            *reinterpret_cast<float2*>(d_att1 + (size_t)row0 * ATT + col) = o0;
            *reinterpret_cast<float2*>(d_att1 + (size_t)(row0 + 8) * ATT + col) = o1;
        }
    }
}

// ---------------- batched preds: tf32 MMA, compact rows @ Wfc ----------------
__global__ void __launch_bounds__(256, 2) k_preds_mma(const float* __restrict__ Wfc,
                                                      const float* __restrict__ bfc,
                                                      float* __restrict__ out) {
    int total = d_total;
    int rowBase = blockIdx.x * 128;
    if (rowBase >= total) return;
    int colBase = blockIdx.y * 64;

    __shared__ float As[2][16][136];
    __shared__ float Bs[2][16][72];
    int tid = threadIdx.x;
    int warp = tid >> 5, lane = tid & 31;
    int g = lane >> 2, tk = lane & 3;
    int mw = (warp & 3) * 32, nw = (warp >> 2) * 32;

    int lm = tid >> 1, lk = (tid & 1) << 3;
    int r = rowBase + lm;
    bool rvalid = (r < total);
    const float* Arow = d_hhist + (size_t)(rvalid ? d_rowmap[r] : 0) * DEC;
    int bk = tid >> 4, bn = (tid & 15) << 2;
    int bcol = colBase + bn;
    bool cvalid = (bcol < VV);

    float acc[2][4][4];
    #pragma unroll
    for (int i = 0; i < 2; i++)
        #pragma unroll
        for (int j = 0; j < 4; j++)
            #pragma unroll
            for (int q = 0; q < 4; q++) acc[i][j][q] = 0.f;

    float4 av0, av1, bv;
    auto loadA = [&](int k0) {
        if (rvalid) {
            av0 = *reinterpret_cast<const float4*>(Arow + k0 + lk);
            av1 = *reinterpret_cast<const float4*>(Arow + k0 + lk + 4);
        } else {
            av0 = make_float4(0.f, 0.f, 0.f, 0.f);
            av1 = av0;
        }
    };
    auto loadB = [&](int k0) {
        if (cvalid) bv = *reinterpret_cast<const float4*>(Wfc + (size_t)(k0 + bk) * VV + bcol);
        else        bv = make_float4(0.f, 0.f, 0.f, 0.f);
    };

    loadA(0); loadB(0);
    As[0][lk + 0][lm] = tf32r(av0.x); As[0][lk + 1][lm] = tf32r(av0.y);
    As[0][lk + 2][lm] = tf32r(av0.z); As[0][lk + 3][lm] = tf32r(av0.w);
    As[0][lk + 4][lm] = tf32r(av1.x); As[0][lk + 5][lm] = tf32r(av1.y);
    As[0][lk + 6][lm] = tf32r(av1.z); As[0][lk + 7][lm] = tf32r(av1.w);
    *reinterpret_cast<float4*>(&Bs[0][bk][bn]) =
        make_float4(tf32r(bv.x), tf32r(bv.y), tf32r(bv.z), tf32r(bv.w));
    __syncthreads();

    const int ntiles = DEC / 16;
    for (int it = 0; it < ntiles; it++) {
        int cur = it & 1;
        bool more = (it + 1 < ntiles);
        if (more) { loadA((it + 1) * 16); loadB((it + 1) * 16); }
        #pragma unroll
        for (int ks = 0; ks < 16; ks += 8) {
            uint32_t a[2][4], bfr[4][2];
            #pragma unroll
            for (int i = 0; i < 2; i++) {
                a[i][0] = __float_as_uint(As[cur][ks + tk][mw + i * 16 + g]);
                a[i][1] = __float_as_uint(As[cur][ks + tk][mw + i * 16 + g + 8]);
                a[i][2] = __float_as_uint(As[cur][ks + tk + 4][mw + i * 16 + g]);
                a[i][3] = __float_as_uint(As[cur][ks + tk + 4][mw + i * 16 + g + 8]);
            }
            #pragma unroll
            for (int j = 0; j < 4; j++) {
                bfr[j][0] = __float_as_uint(Bs[cur][ks + tk][nw + j * 8 + g]);
                bfr[j][1] = __float_as_uint(Bs[cur][ks + tk + 4][nw + j * 8 + g]);
            }
            #pragma unroll
            for (int i = 0; i < 2; i++)
                #pragma unroll
                for (int j = 0; j < 4; j++)
                    mma_tf32(acc[i][j], a[i], bfr[j]);
        }
        if (more) {
            int nxt = cur ^ 1;
            As[nxt][lk + 0][lm] = tf32r(av0.x); As[nxt][lk + 1][lm] = tf32r(av0.y);
            As[nxt][lk + 2][lm] = tf32r(av0.z); As[nxt][lk + 3][lm] = tf32r(av0.w);
            As[nxt][lk + 4][lm] = tf32r(av1.x); As[nxt][lk + 5][lm] = tf32r(av1.y);
            As[nxt][lk + 6][lm] = tf32r(av1.z); As[nxt][lk + 7][lm] = tf32r(av1.w);
            *reinterpret_cast<float4*>(&Bs[nxt][bk][bn]) =
                make_float4(tf32r(bv.x), tf32r(bv.y), tf32r(bv.z), tf32r(bv.w));
        }
        __syncthreads();
    }

    #pragma unroll
    for (int i = 0; i < 2; i++) {
        #pragma unroll
        for (int j = 0; j < 4; j++) {
            int col = colBase + nw + j * 8 + tk * 2;
            if (col >= VV) continue;
            float bf0 = bfc[col], bf1 = bfc[col + 1];
            #pragma unroll
            for (int h = 0; h < 2; h++) {
                int rr = rowBase + mw + i * 16 + g + h * 8;
                if (rr < total) {
                    int mapped = d_rowmap[rr];
                    int t = mapped >> 6, b = mapped & 63;
                    float* orow = out + ((size_t)b * TT + t) * VV;
                    orow[col]     = acc[i][j][h * 2]     + bf0;
                    orow[col + 1] = acc[i][j][h * 2 + 1] + bf1;
                }
            }
        }
    }
}

// ---------------- embc = embs(active rows) @ Wih[0:512] : tf32 MMA ----------------
__global__ void __launch_bounds__(256, 2) k_embc_mma(const float* __restrict__ emb,
                                                     const int* __restrict__ caps,
                                                     const float* __restrict__ Wih) {
    int total = d_total;
    int rowBase = blockIdx.x * 128;
    if (rowBase >= total) return;
    int colBase = blockIdx.y * 64;
    const int Nw = 2048;

    __shared__ float As[2][16][136];
    __shared__ float Bs[2][16][72];
    int tid = threadIdx.x;
    int warp = tid >> 5, lane = tid & 31;
    int g = lane >> 2, tk = lane & 3;
    int mw = (warp & 3) * 32, nw = (warp >> 2) * 32;

    int lm = tid >> 1, lk = (tid & 1) << 3;
    int r = rowBase + lm;
    bool rvalid = (r < total);
    const float* Arow;
    {
        int mapped = rvalid ? d_rowmap[r] : 0;
        int t = mapped >> 6, b = mapped & 63;
        int cap = caps[d_sort_src[b] * LL + t];
        Arow = emb + (size_t)cap * EMB;
    }
    int bk = tid >> 4, bn = (tid & 15) << 2;
    int bcol = colBase + bn;

    float acc[2][4][4];
    #pragma unroll
    for (int i = 0; i < 2; i++)
        #pragma unroll
        for (int j = 0; j < 4; j++)
            #pragma unroll
            for (int q = 0; q < 4; q++) acc[i][j][q] = 0.f;

    float4 av0, av1, bv;
    auto loadA = [&](int k0) {
        if (rvalid) {
            av0 = *reinterpret_cast<const float4*>(Arow + k0 + lk);
            av1 = *reinterpret_cast<const float4*>(Arow + k0 + lk + 4);
        } else {
            av0 = make_float4(0.f, 0.f, 0.f, 0.f);
            av1 = av0;
        }
    };
    auto loadB = [&](int k0) {
        bv = *reinterpret_cast<const float4*>(Wih + (size_t)(k0 + bk) * Nw + bcol);
    };

    loadA(0); loadB(0);
    As[0][lk + 0][lm] = tf32r(av0.x); As[0][lk + 1][lm] = tf32r(av0.y);
    As[0][lk + 2][lm] = tf32r(av0.z); As[0][lk + 3][lm] = tf32r(av0.w);
    As[0][lk + 4][lm] = tf32r(av1.x); As[0][lk + 5][lm] = tf32r(av1.y);
    As[0][lk + 6][lm] = tf32r(av1.z); As[0][lk + 7][lm] = tf32r(av1.w);
    *reinterpret_cast<float4*>(&Bs[0][bk][bn]) =
        make_float4(tf32r(bv.x), tf32r(bv.y), tf32r(bv.z), tf32r(bv.w));
    __syncthreads();

    const int ntiles = EMB / 16;
    for (int it = 0; it < ntiles; it++) {
        int cur = it & 1;
        bool more = (it + 1 < ntiles);
        if (more) { loadA((it + 1) * 16); loadB((it + 1) * 16); }
        #pragma unroll
        for (int ks = 0; ks < 16; ks += 8) {
            uint32_t a[2][4], bfr[4][2];
            #pragma unroll
            for (int i = 0; i < 2; i++) {
                a[i][0] = __float_as_uint(As[cur][ks + tk][mw + i * 16 + g]);
                a[i][1] = __float_as_uint(As[cur][ks + tk][mw + i * 16 + g + 8]);
                a[i][2] = __float_as_uint(As[cur][ks + tk + 4][mw + i * 16 + g]);
                a[i][3] = __float_as_uint(As[cur][ks + tk + 4][mw + i * 16 + g + 8]);
            }
            #pragma unroll
            for (int j = 0; j < 4; j++) {
                bfr[j][0] = __float_as_uint(Bs[cur][ks + tk][nw + j * 8 + g]);
                bfr[j][1] = __float_as_uint(Bs[cur][ks + tk + 4][nw + j * 8 + g]);
            }
            #pragma unroll
            for (int i = 0; i < 2; i++)
                #pragma unroll
                for (int j = 0; j < 4; j++)
                    mma_tf32(acc[i][j], a[i], bfr[j]);
        }
        if (more) {
            int nxt = cur ^ 1;
            As[nxt][lk + 0][lm] = tf32r(av0.x); As[nxt][lk + 1][lm] = tf32r(av0.y);
            As[nxt][lk + 2][lm] = tf32r(av0.z); As[nxt][lk + 3][lm] = tf32r(av0.w);
            As[nxt][lk + 4][lm] = tf32r(av1.x); As[nxt][lk + 5][lm] = tf32r(av1.y);
            As[nxt][lk + 6][lm] = tf32r(av1.z); As[nxt][lk + 7][lm] = tf32r(av1.w);
            *reinterpret_cast<float4*>(&Bs[nxt][bk][bn]) =
                make_float4(tf32r(bv.x), tf32r(bv.y), tf32r(bv.z), tf32r(bv.w));
        }
        __syncthreads();
    }

    #pragma unroll
    for (int i = 0; i < 2; i++) {
        #pragma unroll
        for (int j = 0; j < 4; j++) {
            int col = colBase + nw + j * 8 + tk * 2;
            #pragma unroll
            for (int h = 0; h < 2; h++) {
                int rr = rowBase + mw + i * 16 + g + h * 8;
                if (rr < total) {
                    int mapped = d_rowmap[rr];
                    float* orow = d_embc + (size_t)mapped * 2048;
                    orow[col]     = acc[i][j][h * 2];
                    orow[col + 1] = acc[i][j][h * 2 + 1];
                }
            }
        }
    }
}

// ---------------- fused: e -> softmax -> awe, 1024 threads, 4-way p-split ----------------
__global__ void __launch_bounds__(1024, 1) k_attend(
        const float* __restrict__ enc,
        const float* __restrict__ Wf, const float* __restrict__ bf,
        const float* __restrict__ bd, const float* __restrict__ bb,
        float* __restrict__ out_alphas, int t) {
    int b = blockIdx.x;
    if (b >= d_nb[t]) return;
    __shared__ __align__(16) float a2[ATT];
    __shared__ __align__(16) float wf[ATT];
    __shared__ float es[PP + 4];
    __shared__ float red[32];
    __shared__ float redsum[32];
    __shared__ __align__(16) float awe_sh[3 * 2048];
    int tid = threadIdx.x;
    const float* p0 = d_agp + (size_t)b * AGC;
    const float* p1 = d_agp + (size_t)(BB + b) * AGC;
    if (tid < 512) {
        a2[tid] = p0[tid] + p1[tid] + bd[tid];
        wf[tid] = Wf[tid];
    }
    __syncthreads();
    int lane = tid & 31, warp = tid >> 5;

    const float4* a24 = reinterpret_cast<const float4*>(a2);
    const float4* wf4 = reinterpret_cast<const float4*>(wf);
    for (int p = warp; p < PP; p += 32) {
        const float4* row4 = reinterpret_cast<const float4*>(d_att1 + ((size_t)b * PP + p) * ATT);
        float s = 0.f;
        #pragma unroll
        for (int i = 0; i < 4; i++) {
            int idx = lane + i * 32;
            float4 v = row4[idx];
            float4 a = a24[idx];
            float4 w = wf4[idx];
            s += fmaxf(v.x + a.x, 0.f) * w.x;
            s += fmaxf(v.y + a.y, 0.f) * w.y;
            s += fmaxf(v.z + a.z, 0.f) * w.z;
            s += fmaxf(v.w + a.w, 0.f) * w.w;
        }
        #pragma unroll
        for (int off = 16; off > 0; off >>= 1) s += __shfl_xor_sync(0xffffffffu, s, off);
        if (lane == 0) es[p] = s + bf[0];
    }
    __syncthreads();

    float v = (tid < PP) ? es[tid] : -1e30f;
    float m = v;
    #pragma unroll
    for (int off = 16; off > 0; off >>= 1) m = fmaxf(m, __shfl_xor_sync(0xffffffffu, m, off));
    if (lane == 0) red[warp] = m;
    __syncthreads();
    if (tid == 0) {
        float mm = red[0];
        for (int i = 1; i < 32; i++) mm = fmaxf(mm, red[i]);
        red[0] = mm;
    }
    __syncthreads();
    float smax = red[0];
    float ev = (tid < PP) ? __expf(v - smax) : 0.f;
    float s = ev;
    #pragma unroll
    for (int off = 16; off > 0; off >>= 1) s += __shfl_xor_sync(0xffffffffu, s, off);
    if (lane == 0) redsum[warp] = s;
    __syncthreads();
    if (tid == 0) {
        float ss = redsum[0];
        for (int i = 1; i < 32; i++) ss += redsum[i];
        redsum[0] = ss;
    }
    __syncthreads();
    float inv = 1.0f / redsum[0];
    float al = ev * inv;
    if (tid < PP) {
        es[tid] = al;
        out_alphas[((size_t)b * TT + t) * PP + tid] = al;
    }
    __syncthreads();

    int src = d_sort_src[b];
    int quarter = tid >> 8;
    int c4a = tid & 255;
    const float4* enc4 = reinterpret_cast<const float4*>(enc + (size_t)src * PP * EE);
    int pbeg = quarter * 49, pend = pbeg + 49;
    float4 accA = make_float4(0.f, 0.f, 0.f, 0.f);
    float4 accB = make_float4(0.f, 0.f, 0.f, 0.f);
    for (int p = pbeg; p < pend; p++) {
        float alp = es[p];
        float4 eA = enc4[p * 512 + c4a];
        float4 eB = enc4[p * 512 + c4a + 256];
        accA.x += alp * eA.x; accA.y += alp * eA.y;
        accA.z += alp * eA.z; accA.w += alp * eA.w;
        accB.x += alp * eB.x; accB.y += alp * eB.y;
        accB.z += alp * eB.z; accB.w += alp * eB.w;
    }
    float4* sh4 = reinterpret_cast<float4*>(awe_sh);
    if (quarter > 0) {
        sh4[(quarter - 1) * 512 + c4a] = accA;
        sh4[(quarter - 1) * 512 + c4a + 256] = accB;
    }
    __syncthreads();
    if (quarter == 0) {
        #pragma unroll
        for (int q = 0; q < 3; q++) {
            float4 oA = sh4[q * 512 + c4a];
            float4 oB = sh4[q * 512 + c4a + 256];
            accA.x += oA.x; accA.y += oA.y; accA.z += oA.z; accA.w += oA.w;
            accB.x += oB.x; accB.y += oB.y; accB.z += oB.z; accB.w += oB.w;
        }
        const float4* gp04 = reinterpret_cast<const float4*>(p0 + 512);
        const float4* gp14 = reinterpret_cast<const float4*>(p1 + 512);
        const float4* bb4 = reinterpret_cast<const float4*>(bb);
        float4* awe4 = reinterpret_cast<float4*>(d_awe + (size_t)b * EE);
        #pragma unroll
        for (int h = 0; h < 2; h++) {
            int c4 = c4a + h * 256;
            float4 acc = h ? accB : accA;
            float4 gp0 = gp04[c4], gp1 = gp14[c4], bbv = bb4[c4];
            float4 gt;
            gt.x = 1.0f / (1.0f + __expf(-(gp0.x + gp1.x + bbv.x)));
            gt.y = 1.0f / (1.0f + __expf(-(gp0.y + gp1.y + bbv.y)));
            gt.z = 1.0f / (1.0f + __expf(-(gp0.z + gp1.z + bbv.z)));
            gt.w = 1.0f / (1.0f + __expf(-(gp0.w + gp1.w + bbv.w)));
            awe4[c4] = make_float4(acc.x * gt.x, acc.y * gt.y, acc.z * gt.z, acc.w * gt.w);
        }
    }
}

// ---------------- host launch ----------------
extern "C" void kernel_launch(void* const* d_in, const int* in_sizes, int n_in,
                              void* d_out, int out_size) {
    const float* enc  = (const float*)d_in[0];
    const int*   caps = (const int*)d_in[1];
    const int*   clen = (const int*)d_in[2];
    const float* emb  = (const float*)d_in[3];
    const float* We   = (const float*)d_in[4];
    const float* be   = (const float*)d_in[5];
    const float* Wd   = (const float*)d_in[6];
    const float* bd   = (const float*)d_in[7];
    const float* Wf   = (const float*)d_in[8];
    const float* bf   = (const float*)d_in[9];
    const float* Wih  = (const float*)d_in[10];
    const float* bih  = (const float*)d_in[11];
    const float* Whh  = (const float*)d_in[12];
    const float* bhh  = (const float*)d_in[13];
    const float* Wb   = (const float*)d_in[14];
    const float* bb   = (const float*)d_in[15];
    const float* Whi  = (const float*)d_in[16];
    const float* bhi  = (const float*)d_in[17];
    const float* Wci  = (const float*)d_in[18];
    const float* bci  = (const float*)d_in[19];
    const float* Wfc  = (const float*)d_in[20];
    const float* bfc  = (const float*)d_in[21];
    float* out = (float*)d_out;
    float* out_alphas = out + (size_t)BB * TT * VV;

    k_setup<<<1, 64>>>(clen);
    k_zero<<<2048, 256>>>(out, (size_t)out_size);
    k_mean<<<dim3(8, BB), 256>>>(enc);

    // h0 + c0 in ONE split-K GEMM (concat [Whi|Wci], N=1024, K=2048, S=8)
    k_gemm32<<<dim3(32, 8), 256>>>(BUF_MEAN, Whi, Wci, 512, 512, 512, 1024, EE, 8, -1);
    k_reduce_hc<<<256, 256>>>(bhi, bci);

    // att1 via tf32 tensor cores
    k_att1_mma<<<dim3(98, 8), 256>>>(enc, We, be);

    // embc = embs(active rows) @ Wih[0:512]
    k_embc_mma<<<dim3(16, 32), 256>>>(emb, caps, Wih);

    for (int t = 0; t < TT; t++) {
        // phase A: att2/gate/hg partials, split-K 2, KTILE 32
        k_ag<<<dim3(144, 2), 256>>>(Wd, Wb, Whh, t);
        // attention: sums partials, softmax, gated awe (4-way p-split)
        k_attend<<<BB, 1024>>>(enc, Wf, bf, bd, bb, out_alphas, t);
        // awe part via tf32 MMA: d_awe @ Wih[512:2560] (S=8)
        k_awe_mma<<<dim3(16, 8), 256>>>(Wih + (size_t)512 * 2048, t);
        // g = embc + hg + awe-partials(8) + biases, LSTM pointwise
        k_reduce_lstm<<<128, 256>>>(bih, bhh, t);
    }

    // batched vocab projection via tf32 tensor cores
    k_preds_mma<<<dim3(16, 157), 256>>>(Wfc, bfc, out);
}

// round 14
// speedup vs baseline: 1.3784x; 1.0371x over previous
#include <cuda_runtime.h>
#include <cuda_bf16.h>
#include <cstdint>

// Problem constants
#define BB 64
#define PP 196
#define EE 2048
#define LL 32
#define VV 10000
#define EMB 512
#define DEC 512
#define ATT 512
#define TT 31   // L-1 steps

// ---------------- device scratch ----------------
__device__ __align__(16) int   d_sort_src[BB];
__device__ __align__(16) int   d_nb[TT + 1];
__device__ int   d_total;
__device__ __align__(16) int   d_rowmap[BB * TT];
__device__ __align__(16) float d_mean[BB * EE];
__device__ __align__(16) float d_h[BB * DEC];
__device__ __align__(16) float d_c[BB * DEC];
__device__ __align__(16) float d_hhist[(size_t)TT * BB * DEC];
__device__ __align__(16) float d_att1[(size_t)BB * PP * ATT];
__device__ __align__(16) float d_awe[BB * EE];
__device__ __align__(16) float d_embc[(size_t)TT * BB * 2048];
__device__ __align__(16) float d_part[8 * BB * 2048];
// phase-A partials: [split(2)][b(64)][col(4608)] — 0..511 att2, 512..2559 gate, 2560..4607 hg
#define AGC 4608
__device__ __align__(16) float d_agp[2 * BB * AGC];

#define BUF_MEAN 0

__device__ __forceinline__ float* selbuf(int s) {
    switch (s) {
        case BUF_MEAN: return d_mean;
        default:       return nullptr;
    }
}

// ---------------- PDL helper ----------------
__device__ __forceinline__ void grid_dep_sync() {
#if defined(__CUDA_ARCH__) && __CUDA_ARCH__ >= 900
    cudaGridDependencySynchronize();
#endif
}

// ---------------- tf32 helpers ----------------
__device__ __forceinline__ float tf32r(float f) {
    uint32_t u;
    asm("cvt.rna.tf32.f32 %0, %1;" : "=r"(u) : "f"(f));
    return __uint_as_float(u);
}
__device__ __forceinline__ void mma_tf32(float* c, const uint32_t* a, const uint32_t* b) {
    asm volatile("mma.sync.aligned.m16n8k8.row.col.f32.tf32.tf32.f32 "
        "{%0,%1,%2,%3}, {%4,%5,%6,%7}, {%8,%9}, {%0,%1,%2,%3};"
        : "+f"(c[0]), "+f"(c[1]), "+f"(c[2]), "+f"(c[3])
        : "r"(a[0]), "r"(a[1]), "r"(a[2]), "r"(a[3]), "r"(b[0]), "r"(b[1]));
}

// ---------------- setup ----------------
__global__ void k_setup(const int* __restrict__ cap_len) {
    __shared__ int lens[BB];
    __shared__ int nbs[TT + 1];
    __shared__ int off[TT + 1];
    int b = threadIdx.x;
    if (b < BB) lens[b] = cap_len[b];
    __syncthreads();
    if (b < BB) {
        int rank = 0;
        int lb = lens[b];
        for (int j = 0; j < BB; j++) {
            int lj = lens[j];
            if (lj > lb || (lj == lb && j < b)) rank++;
        }
        d_sort_src[rank] = b;
    }
    if (b <= TT) {
        int cnt = 0;
        for (int j = 0; j < BB; j++) if (lens[j] - 1 > b) cnt++;
        d_nb[b] = cnt;
        nbs[b] = cnt;
    }
    __syncthreads();
    if (b == 0) {
        int a = 0;
        for (int t = 0; t < TT; t++) { off[t] = a; a += nbs[t]; }
        d_total = a;
    }
    __syncthreads();
    if (b < BB) {
        for (int t = 0; t < TT; t++)
            if (b < nbs[t]) d_rowmap[off[t] + b] = (t << 6) | b;
    }
}

__global__ void k_zero(float* __restrict__ out, size_t n) {
    size_t i = (size_t)blockIdx.x * blockDim.x + threadIdx.x;
    size_t stride = (size_t)gridDim.x * blockDim.x;
    for (; i < n; i += stride) out[i] = 0.0f;
}

__global__ void k_mean(const float* __restrict__ enc) {
    int b = blockIdx.y;
    int e = blockIdx.x * 256 + threadIdx.x;
    const float* base = enc + (size_t)d_sort_src[b] * PP * EE + e;
    float s = 0.0f;
    #pragma unroll 7
    for (int p = 0; p < PP; p++) s += base[(size_t)p * EE];
    d_mean[b * EE + e] = s * (1.0f / 196.0f);
}

// ---------------- split-K GEMM, KTILE=32, into d_part (h0/c0 only) ----------------
__global__ void __launch_bounds__(256, 2) k_gemm32(
        int xsel, const float* __restrict__ WA, const float* __restrict__ WB,
        int colSplit, int NA, int NB, int Nout, int K, int S, int t) {
    __shared__ __align__(16) float Xs[2][32][68];
    __shared__ __align__(16) float Ws[2][32][34];

    const float* X = selbuf(xsel);
    int tid = threadIdx.x;
    int nb = (t >= 0) ? d_nb[t] : BB;
    int n0 = blockIdx.x * 32;

    const float* W; int wc0, NW;
    if (n0 < colSplit) { W = WA; wc0 = n0; NW = NA; }
    else               { W = WB; wc0 = n0 - colSplit; NW = NB; }

    int s = blockIdx.y;
    int kbeg = s * (K / S);
    int ntiles = (K / S) / 32;

    int nl = tid & 15;
    int mg = tid >> 4;
    int m0 = mg << 2;
    bool rowact = (m0 < nb);

    int lm = tid >> 2, lk = (tid & 3) << 2;
    int wk = tid >> 4, wn = tid & 15;
    bool xact = (lm < nb);
    const float* Xrow = X + (size_t)lm * K;

    float acc[4][2];
    #pragma unroll
    for (int i = 0; i < 4; i++) { acc[i][0] = 0.f; acc[i][1] = 0.f; }

    float4 xr0 = make_float4(0.f, 0.f, 0.f, 0.f), xr1 = xr0;
    float wr00, wr01, wr10, wr11;
    auto loadG = [&](int k0) {
        if (xact) {
            xr0 = *reinterpret_cast<const float4*>(Xrow + k0 + lk);
            xr1 = *reinterpret_cast<const float4*>(Xrow + k0 + lk + 16);
        }
        int kg = k0 + wk;
        wr00 = W[(size_t)kg * NW + wc0 + wn];
        wr01 = W[(size_t)kg * NW + wc0 + wn + 16];
        wr10 = W[(size_t)(kg + 16) * NW + wc0 + wn];
        wr11 = W[(size_t)(kg + 16) * NW + wc0 + wn + 16];
    };
    auto stS = [&](int buf) {
        Xs[buf][lk + 0][lm] = xr0.x; Xs[buf][lk + 1][lm] = xr0.y;
        Xs[buf][lk + 2][lm] = xr0.z; Xs[buf][lk + 3][lm] = xr0.w;
        Xs[buf][lk + 16][lm] = xr1.x; Xs[buf][lk + 17][lm] = xr1.y;
        Xs[buf][lk + 18][lm] = xr1.z; Xs[buf][lk + 19][lm] = xr1.w;
        Ws[buf][wk][wn] = wr00; Ws[buf][wk][wn + 16] = wr01;
        Ws[buf][wk + 16][wn] = wr10; Ws[buf][wk + 16][wn + 16] = wr11;
    };

    loadG(kbeg);
    stS(0);
    __syncthreads();

    for (int it = 0; it < ntiles; it++) {
        int cur = it & 1;
        bool more = (it + 1 < ntiles);
        if (more) loadG(kbeg + (it + 1) * 32);
        if (rowact) {
            #pragma unroll
            for (int kk = 0; kk < 32; kk++) {
                float4 xv = *reinterpret_cast<const float4*>(&Xs[cur][kk][m0]);
                float2 wv = *reinterpret_cast<const float2*>(&Ws[cur][kk][nl * 2]);
                acc[0][0] += xv.x * wv.x; acc[0][1] += xv.x * wv.y;
                acc[1][0] += xv.y * wv.x; acc[1][1] += xv.y * wv.y;
                acc[2][0] += xv.z * wv.x; acc[2][1] += xv.z * wv.y;
                acc[3][0] += xv.w * wv.x; acc[3][1] += xv.w * wv.y;
            }
        }
        if (more) stS(cur ^ 1);
        __syncthreads();
    }

    if (!rowact) return;
    int na = n0 + nl * 2;
    #pragma unroll
    for (int j = 0; j < 4; j++) {
        int m = m0 + j;
        if (m < nb) {
            size_t base = ((size_t)(s * BB + m)) * Nout + na;
            d_part[base] = acc[j][0];
            d_part[base + 1] = acc[j][1];
        }
    }
}

// reduce combined h0/c0 (N=1024, S=8)
__global__ void k_reduce_hc(const float* __restrict__ bhi, const float* __restrict__ bci) {
    int idx = blockIdx.x * 256 + threadIdx.x;
    if (idx >= BB * 1024) return;
    int m = idx >> 10, n = idx & 1023;
    float v = 0.f;
    #pragma unroll
    for (int s = 0; s < 8; s++) v += d_part[((size_t)(s * BB + m)) * 1024 + n];
    if (n < 512) d_h[m * 512 + n] = v + bhi[n];
    else         d_c[m * 512 + (n - 512)] = v + bci[n - 512];
}

// ---------------- phase A: split-K2 KTILE=32 GEMM h @ [Wd|Wb|Whh] -> d_agp (PDL) ----------------
__global__ void __launch_bounds__(256, 2) k_ag(
        const float* __restrict__ Wd, const float* __restrict__ Wb,
        const float* __restrict__ Whh, int t) {
    __shared__ __align__(16) float Xs[2][32][68];
    __shared__ __align__(16) float Ws[2][32][34];

    int n0 = blockIdx.x * 32;
    int s = blockIdx.y;
    int nb = d_nb[t];

    const float* W; int wc0, NW;
    if (n0 < 512)       { W = Wd;  wc0 = n0;        NW = ATT; }
    else if (n0 < 2560) { W = Wb;  wc0 = n0 - 512;  NW = 2048; }
    else                { W = Whh; wc0 = n0 - 2560; NW = 2048; }

    int kbeg = s * 256;
    const int ntiles = 8;

    int tid = threadIdx.x;
    int nl = tid & 15;
    int mg = tid >> 4;
    int m0 = mg << 2;
    bool rowact = (m0 < nb);

    int lm = tid >> 2, lk = (tid & 3) << 2;
    int wk = tid >> 4, wn = tid & 15;
    bool xact = (lm < nb);
    const float* Xrow = d_h + (size_t)lm * DEC;

    float acc[4][2];
    #pragma unroll
    for (int i = 0; i < 4; i++) { acc[i][0] = 0.f; acc[i][1] = 0.f; }

    float4 xr0 = make_float4(0.f, 0.f, 0.f, 0.f), xr1 = xr0;
    float wr00, wr01, wr10, wr11;
    auto loadW = [&](int k0) {
        int kg = k0 + wk;
        wr00 = W[(size_t)kg * NW + wc0 + wn];
        wr01 = W[(size_t)kg * NW + wc0 + wn + 16];
        wr10 = W[(size_t)(kg + 16) * NW + wc0 + wn];
        wr11 = W[(size_t)(kg + 16) * NW + wc0 + wn + 16];
    };
    auto loadX = [&](int k0) {
        if (xact) {
            xr0 = *reinterpret_cast<const float4*>(Xrow + k0 + lk);
            xr1 = *reinterpret_cast<const float4*>(Xrow + k0 + lk + 16);
        }
    };
    auto stS = [&](int buf) {
        Xs[buf][lk + 0][lm] = xr0.x; Xs[buf][lk + 1][lm] = xr0.y;
        Xs[buf][lk + 2][lm] = xr0.z; Xs[buf][lk + 3][lm] = xr0.w;
        Xs[buf][lk + 16][lm] = xr1.x; Xs[buf][lk + 17][lm] = xr1.y;
        Xs[buf][lk + 18][lm] = xr1.z; Xs[buf][lk + 19][lm] = xr1.w;
        Ws[buf][wk][wn] = wr00; Ws[buf][wk][wn + 16] = wr01;
        Ws[buf][wk + 16][wn] = wr10; Ws[buf][wk + 16][wn + 16] = wr11;
    };

    // PDL: preload independent W tile 0, then wait for predecessor (d_h producer)
    loadW(kbeg);
    grid_dep_sync();
    loadX(kbeg);
    stS(0);
    __syncthreads();

    for (int it = 0; it < ntiles; it++) {
        int cur = it & 1;
        bool more = (it + 1 < ntiles);
        if (more) { loadW(kbeg + (it + 1) * 32); loadX(kbeg + (it + 1) * 32); }
        if (rowact) {
            #pragma unroll
            for (int kk = 0; kk < 32; kk++) {
                float4 xv = *reinterpret_cast<const float4*>(&Xs[cur][kk][m0]);
                float2 wv = *reinterpret_cast<const float2*>(&Ws[cur][kk][nl * 2]);
                acc[0][0] += xv.x * wv.x; acc[0][1] += xv.x * wv.y;
                acc[1][0] += xv.y * wv.x; acc[1][1] += xv.y * wv.y;
                acc[2][0] += xv.z * wv.x; acc[2][1] += xv.z * wv.y;
                acc[3][0] += xv.w * wv.x; acc[3][1] += xv.w * wv.y;
            }
        }
        if (more) stS(cur ^ 1);
        __syncthreads();
    }

    if (!rowact) return;
    int na = n0 + nl * 2;
    #pragma unroll
    for (int j = 0; j < 4; j++) {
        int m = m0 + j;
        if (m < nb) {
            size_t base = ((size_t)(s * BB + m)) * AGC + na;
            d_agp[base] = acc[j][0];
            d_agp[base + 1] = acc[j][1];
        }
    }
}

// ---------------- awe GEMM via tf32 MMA (PDL): d_awe(64,2048) @ Wih2, S=8 ----------------
__global__ void __launch_bounds__(256, 2) k_awe_mma(const float* __restrict__ Wih2, int t) {
    __shared__ float As[2][16][72];
    __shared__ float Bs[2][16][136];
    int nb = d_nb[t];
    int tid = threadIdx.x;
    int warp = tid >> 5, lane = tid & 31;
    int g = lane >> 2, tk = lane & 3;
    int mw = (warp & 1) * 32, nw = (warp >> 1) * 32;
    int nBase = blockIdx.x * 128;
    int s = blockIdx.y;
    int kbeg = s * 256;
    const int ntiles = 16;

    int lm = tid >> 2, lk = (tid & 3) << 2;
    bool xact = (lm < nb);
    const float* Arow = d_awe + (size_t)lm * 2048;
    int bk = tid >> 4, bn = (tid & 15) << 2;
    bool wact = (mw < nb);

    float acc[2][4][4];
    #pragma unroll
    for (int i = 0; i < 2; i++)
        #pragma unroll
        for (int j = 0; j < 4; j++)
            #pragma unroll
            for (int q = 0; q < 4; q++) acc[i][j][q] = 0.f;

    float4 av = make_float4(0.f, 0.f, 0.f, 0.f), bv0, bv1;
    auto loadB = [&](int k0) {
        const float* wr = Wih2 + (size_t)(k0 + bk) * 2048 + nBase + bn;
        bv0 = *reinterpret_cast<const float4*>(wr);
        bv1 = *reinterpret_cast<const float4*>(wr + 64);
    };
    auto loadA = [&](int k0) {
        if (xact) av = *reinterpret_cast<const float4*>(Arow + k0 + lk);
    };
    auto stS = [&](int buf) {
        As[buf][lk + 0][lm] = tf32r(av.x); As[buf][lk + 1][lm] = tf32r(av.y);
        As[buf][lk + 2][lm] = tf32r(av.z); As[buf][lk + 3][lm] = tf32r(av.w);
        *reinterpret_cast<float4*>(&Bs[buf][bk][bn]) =
            make_float4(tf32r(bv0.x), tf32r(bv0.y), tf32r(bv0.z), tf32r(bv0.w));
        *reinterpret_cast<float4*>(&Bs[buf][bk][bn + 64]) =
            make_float4(tf32r(bv1.x), tf32r(bv1.y), tf32r(bv1.z), tf32r(bv1.w));
    };

    // PDL: preload independent W tile 0, then wait for attend (d_awe producer)
    loadB(kbeg);
    grid_dep_sync();
    loadA(kbeg);
    stS(0);
    __syncthreads();

    for (int it = 0; it < ntiles; it++) {
        int cur = it & 1;
        bool more = (it + 1 < ntiles);
        if (more) { loadB(kbeg + (it + 1) * 16); loadA(kbeg + (it + 1) * 16); }
        if (wact) {
            #pragma unroll
            for (int ks = 0; ks < 16; ks += 8) {
                uint32_t a[2][4], bfr[4][2];
                #pragma unroll
                for (int i = 0; i < 2; i++) {
                    a[i][0] = __float_as_uint(As[cur][ks + tk][mw + i * 16 + g]);
                    a[i][1] = __float_as_uint(As[cur][ks + tk][mw + i * 16 + g + 8]);
                    a[i][2] = __float_as_uint(As[cur][ks + tk + 4][mw + i * 16 + g]);
                    a[i][3] = __float_as_uint(As[cur][ks + tk + 4][mw + i * 16 + g + 8]);
                }
                #pragma unroll
                for (int j = 0; j < 4; j++) {
                    bfr[j][0] = __float_as_uint(Bs[cur][ks + tk][nw + j * 8 + g]);
                    bfr[j][1] = __float_as_uint(Bs[cur][ks + tk + 4][nw + j * 8 + g]);
                }
                #pragma unroll
                for (int i = 0; i < 2; i++)
                    #pragma unroll
                    for (int j = 0; j < 4; j++)
                        mma_tf32(acc[i][j], a[i], bfr[j]);
            }
        }
        if (more) stS(cur ^ 1);
        __syncthreads();
    }

    if (!wact) return;
    #pragma unroll
    for (int i = 0; i < 2; i++) {
        #pragma unroll
        for (int j = 0; j < 4; j++) {
            int col = nBase + nw + j * 8 + tk * 2;
            #pragma unroll
            for (int h = 0; h < 2; h++) {
                int row = mw + i * 16 + g + h * 8;
                if (row < nb) {
                    float* p = d_part + ((size_t)(s * BB + row)) * 2048 + col;
                    p[0] = acc[i][j][h * 2];
                    p[1] = acc[i][j][h * 2 + 1];
                }
            }
        }
    }
}

// ---------------- reduce (PDL): g = embc + hg(2) + awe parts(8) + biases, LSTM ----------------
__global__ void k_reduce_lstm(const float* __restrict__ bih, const float* __restrict__ bhh, int t) {
    int idx = blockIdx.x * 256 + threadIdx.x;
    int b = idx >> 9, d = idx & 511;
    bool act = (b < d_nb[t]);
    // independent reads first (biases + embc were written pre-loop)
    float gi = 0.f, gf = 0.f, gg = 0.f, go = 0.f;
    if (act) {
        const float* e = d_embc + ((size_t)((t << 6) | b)) * 2048;
        gi = bih[d]        + bhh[d]        + e[d];
        gf = bih[512 + d]  + bhh[512 + d]  + e[512 + d];
        gg = bih[1024 + d] + bhh[1024 + d] + e[1024 + d];
        go = bih[1536 + d] + bhh[1536 + d] + e[1536 + d];
    }
    grid_dep_sync();
    if (!act) return;
    const float* hg0 = d_agp + (size_t)b * AGC + 2560;
    const float* hg1 = d_agp + (size_t)(BB + b) * AGC + 2560;
    gi += hg0[d];        gi += hg1[d];
    gf += hg0[512 + d];  gf += hg1[512 + d];
    gg += hg0[1024 + d]; gg += hg1[1024 + d];
    go += hg0[1536 + d]; go += hg1[1536 + d];
    #pragma unroll
    for (int s = 0; s < 8; s++) {
        const float* p = d_part + ((size_t)(s * BB + b)) * 2048;
        gi += p[d]; gf += p[512 + d]; gg += p[1024 + d]; go += p[1536 + d];
    }
    float c = d_c[b * DEC + d];
    float si = 1.0f / (1.0f + __expf(-gi));
    float sf = 1.0f / (1.0f + __expf(-gf));
    float so = 1.0f / (1.0f + __expf(-go));
    float cn = sf * c + si * tanhf(gg);
    float hn = so * tanhf(cn);
    d_c[b * DEC + d] = cn;
    d_h[b * DEC + d] = hn;
    d_hhist[((size_t)t * BB + b) * DEC + d] = hn;
}

// ---------------- att1 = enc[sorted] @ We + be : tf32 MMA ----------------
__global__ void __launch_bounds__(256, 2) k_att1_mma(const float* __restrict__ enc,
                                                     const float* __restrict__ We,
                                                     const float* __restrict__ be) {
    __shared__ float As[2][16][136];
    __shared__ float Bs[2][16][72];
    int tid = threadIdx.x;
    int warp = tid >> 5, lane = tid & 31;
    int g = lane >> 2, tk = lane & 3;
    int mw = (warp & 3) * 32, nw = (warp >> 2) * 32;
    int rowBase = blockIdx.x * 128, colBase = blockIdx.y * 64;

    int lm = tid >> 1, lk = (tid & 1) << 3;
    int r = rowBase + lm;
    int bidx = r / PP, pidx = r % PP;
    const float* Arow = enc + ((size_t)d_sort_src[bidx] * PP + pidx) * EE;
    int bk = tid >> 4, bn = (tid & 15) << 2;

    float acc[2][4][4];
    #pragma unroll
    for (int i = 0; i < 2; i++)
        #pragma unroll
        for (int j = 0; j < 4; j++)
            #pragma unroll
            for (int q = 0; q < 4; q++) acc[i][j][q] = 0.f;

    float4 av0, av1, bv;
    av0 = *reinterpret_cast<const float4*>(Arow + lk);
    av1 = *reinterpret_cast<const float4*>(Arow + lk + 4);
    bv  = *reinterpret_cast<const float4*>(We + (size_t)bk * ATT + colBase + bn);
    As[0][lk + 0][lm] = tf32r(av0.x); As[0][lk + 1][lm] = tf32r(av0.y);
    As[0][lk + 2][lm] = tf32r(av0.z); As[0][lk + 3][lm] = tf32r(av0.w);
    As[0][lk + 4][lm] = tf32r(av1.x); As[0][lk + 5][lm] = tf32r(av1.y);
    As[0][lk + 6][lm] = tf32r(av1.z); As[0][lk + 7][lm] = tf32r(av1.w);
    *reinterpret_cast<float4*>(&Bs[0][bk][bn]) =
        make_float4(tf32r(bv.x), tf32r(bv.y), tf32r(bv.z), tf32r(bv.w));
    __syncthreads();

    const int ntiles = EE / 16;
    for (int it = 0; it < ntiles; it++) {
        int cur = it & 1;
        bool more = (it + 1 < ntiles);
        if (more) {
            int k0 = (it + 1) * 16;
            av0 = *reinterpret_cast<const float4*>(Arow + k0 + lk);
            av1 = *reinterpret_cast<const float4*>(Arow + k0 + lk + 4);
            bv  = *reinterpret_cast<const float4*>(We + (size_t)(k0 + bk) * ATT + colBase + bn);
        }
        #pragma unroll
        for (int ks = 0; ks < 16; ks += 8) {
            uint32_t a[2][4], bfr[4][2];
            #pragma unroll
            for (int i = 0; i < 2; i++) {
                a[i][0] = __float_as_uint(As[cur][ks + tk][mw + i * 16 + g]);
                a[i][1] = __float_as_uint(As[cur][ks + tk][mw + i * 16 + g + 8]);
                a[i][2] = __float_as_uint(As[cur][ks + tk + 4][mw + i * 16 + g]);
                a[i][3] = __float_as_uint(As[cur][ks + tk + 4][mw + i * 16 + g + 8]);
            }
            #pragma unroll
            for (int j = 0; j < 4; j++) {
                bfr[j][0] = __float_as_uint(Bs[cur][ks + tk][nw + j * 8 + g]);
                bfr[j][1] = __float_as_uint(Bs[cur][ks + tk + 4][nw + j * 8 + g]);
            }
            #pragma unroll
            for (int i = 0; i < 2; i++)
                #pragma unroll
                for (int j = 0; j < 4; j++)
                    mma_tf32(acc[i][j], a[i], bfr[j]);
        }
        if (more) {
            int nxt = cur ^ 1;
            As[nxt][lk + 0][lm] = tf32r(av0.x); As[nxt][lk + 1][lm] = tf32r(av0.y);
            As[nxt][lk + 2][lm] = tf32r(av0.z); As[nxt][lk + 3][lm] = tf32r(av0.w);
            As[nxt][lk + 4][lm] = tf32r(av1.x); As[nxt][lk + 5][lm] = tf32r(av1.y);
            As[nxt][lk + 6][lm] = tf32r(av1.z); As[nxt][lk + 7][lm] = tf32r(av1.w);
            *reinterpret_cast<float4*>(&Bs[nxt][bk][bn]) =
                make_float4(tf32r(bv.x), tf32r(bv.y), tf32r(bv.z), tf32r(bv.w));
        }
        __syncthreads();
    }

    #pragma unroll
    for (int i = 0; i < 2; i++) {
        int row0 = rowBase + mw + i * 16 + g;
        #pragma unroll
        for (int j = 0; j < 4; j++) {
            int col = colBase + nw + j * 8 + tk * 2;
            float be0 = be[col], be1 = be[col + 1];
            float2 o0 = make_float2(acc[i][j][0] + be0, acc[i][j][1] + be1);
            float2 o1 = make_float2(acc[i][j][2] + be0, acc[i][j][3] + be1);
            *reinterpret_cast<float2*>(d_att1 + (size_t)row0 * ATT + col) = o0;
            *reinterpret_cast<float2*>(d_att1 + (size_t)(row0 + 8) * ATT + col) = o1;
        }
    }
}

// ---------------- batched preds: tf32 MMA, compact rows @ Wfc ----------------
__global__ void __launch_bounds__(256, 2) k_preds_mma(const float* __restrict__ Wfc,
                                                      const float* __restrict__ bfc,
                                                      float* __restrict__ out) {
    int total = d_total;
    int rowBase = blockIdx.x * 128;
    if (rowBase >= total) return;
    int colBase = blockIdx.y * 64;

    __shared__ float As[2][16][136];
    __shared__ float Bs[2][16][72];
    int tid = threadIdx.x;
    int warp = tid >> 5, lane = tid & 31;
    int g = lane >> 2, tk = lane & 3;
    int mw = (warp & 3) * 32, nw = (warp >> 2) * 32;

    int lm = tid >> 1, lk = (tid & 1) << 3;
    int r = rowBase + lm;
    bool rvalid = (r < total);
    const float* Arow = d_hhist + (size_t)(rvalid ? d_rowmap[r] : 0) * DEC;
    int bk = tid >> 4, bn = (tid & 15) << 2;
    int bcol = colBase + bn;
    bool cvalid = (bcol < VV);

    float acc[2][4][4];
    #pragma unroll
    for (int i = 0; i < 2; i++)
        #pragma unroll
        for (int j = 0; j < 4; j++)
            #pragma unroll
            for (int q = 0; q < 4; q++) acc[i][j][q] = 0.f;

    float4 av0, av1, bv;
    auto loadA = [&](int k0) {
        if (rvalid) {
            av0 = *reinterpret_cast<const float4*>(Arow + k0 + lk);
            av1 = *reinterpret_cast<const float4*>(Arow + k0 + lk + 4);
        } else {
            av0 = make_float4(0.f, 0.f, 0.f, 0.f);
            av1 = av0;
        }
    };
    auto loadB = [&](int k0) {
        if (cvalid) bv = *reinterpret_cast<const float4*>(Wfc + (size_t)(k0 + bk) * VV + bcol);
        else        bv = make_float4(0.f, 0.f, 0.f, 0.f);
    };

    loadA(0); loadB(0);
    As[0][lk + 0][lm] = tf32r(av0.x); As[0][lk + 1][lm] = tf32r(av0.y);
    As[0][lk + 2][lm] = tf32r(av0.z); As[0][lk + 3][lm] = tf32r(av0.w);
    As[0][lk + 4][lm] = tf32r(av1.x); As[0][lk + 5][lm] = tf32r(av1.y);
    As[0][lk + 6][lm] = tf32r(av1.z); As[0][lk + 7][lm] = tf32r(av1.w);
    *reinterpret_cast<float4*>(&Bs[0][bk][bn]) =
        make_float4(tf32r(bv.x), tf32r(bv.y), tf32r(bv.z), tf32r(bv.w));
    __syncthreads();

    const int ntiles = DEC / 16;
    for (int it = 0; it < ntiles; it++) {
        int cur = it & 1;
        bool more = (it + 1 < ntiles);
        if (more) { loadA((it + 1) * 16); loadB((it + 1) * 16); }
        #pragma unroll
        for (int ks = 0; ks < 16; ks += 8) {
            uint32_t a[2][4], bfr[4][2];
            #pragma unroll
            for (int i = 0; i < 2; i++) {
                a[i][0] = __float_as_uint(As[cur][ks + tk][mw + i * 16 + g]);
                a[i][1] = __float_as_uint(As[cur][ks + tk][mw + i * 16 + g + 8]);
                a[i][2] = __float_as_uint(As[cur][ks + tk + 4][mw + i * 16 + g]);
                a[i][3] = __float_as_uint(As[cur][ks + tk + 4][mw + i * 16 + g + 8]);
            }
            #pragma unroll
            for (int j = 0; j < 4; j++) {
                bfr[j][0] = __float_as_uint(Bs[cur][ks + tk][nw + j * 8 + g]);
                bfr[j][1] = __float_as_uint(Bs[cur][ks + tk + 4][nw + j * 8 + g]);
            }
            #pragma unroll
            for (int i = 0; i < 2; i++)
                #pragma unroll
                for (int j = 0; j < 4; j++)
                    mma_tf32(acc[i][j], a[i], bfr[j]);
        }
        if (more) {
            int nxt = cur ^ 1;
            As[nxt][lk + 0][lm] = tf32r(av0.x); As[nxt][lk + 1][lm] = tf32r(av0.y);
            As[nxt][lk + 2][lm] = tf32r(av0.z); As[nxt][lk + 3][lm] = tf32r(av0.w);
            As[nxt][lk + 4][lm] = tf32r(av1.x); As[nxt][lk + 5][lm] = tf32r(av1.y);
            As[nxt][lk + 6][lm] = tf32r(av1.z); As[nxt][lk + 7][lm] = tf32r(av1.w);
            *reinterpret_cast<float4*>(&Bs[nxt][bk][bn]) =
                make_float4(tf32r(bv.x), tf32r(bv.y), tf32r(bv.z), tf32r(bv.w));
        }
        __syncthreads();
    }

    #pragma unroll
    for (int i = 0; i < 2; i++) {
        #pragma unroll
        for (int j = 0; j < 4; j++) {
            int col = colBase + nw + j * 8 + tk * 2;
            if (col >= VV) continue;
            float bf0 = bfc[col], bf1 = bfc[col + 1];
            #pragma unroll
            for (int h = 0; h < 2; h++) {
                int rr = rowBase + mw + i * 16 + g + h * 8;
                if (rr < total) {
                    int mapped = d_rowmap[rr];
                    int t = mapped >> 6, b = mapped & 63;
                    float* orow = out + ((size_t)b * TT + t) * VV;
                    orow[col]     = acc[i][j][h * 2]     + bf0;
                    orow[col + 1] = acc[i][j][h * 2 + 1] + bf1;
                }
            }
        }
    }
}

// ---------------- embc = embs(active rows) @ Wih[0:512] : tf32 MMA ----------------
__global__ void __launch_bounds__(256, 2) k_embc_mma(const float* __restrict__ emb,
                                                     const int* __restrict__ caps,
                                                     const float* __restrict__ Wih) {
    int total = d_total;
    int rowBase = blockIdx.x * 128;
    if (rowBase >= total) return;
    int colBase = blockIdx.y * 64;
    const int Nw = 2048;

    __shared__ float As[2][16][136];
    __shared__ float Bs[2][16][72];
    int tid = threadIdx.x;
    int warp = tid >> 5, lane = tid & 31;
    int g = lane >> 2, tk = lane & 3;
    int mw = (warp & 3) * 32, nw = (warp >> 2) * 32;

    int lm = tid >> 1, lk = (tid & 1) << 3;
    int r = rowBase + lm;
    bool rvalid = (r < total);
    const float* Arow;
    {
        int mapped = rvalid ? d_rowmap[r] : 0;
        int t = mapped >> 6, b = mapped & 63;
        int cap = caps[d_sort_src[b] * LL + t];
        Arow = emb + (size_t)cap * EMB;
    }
    int bk = tid >> 4, bn = (tid & 15) << 2;
    int bcol = colBase + bn;

    float acc[2][4][4];
    #pragma unroll
    for (int i = 0; i < 2; i++)
        #pragma unroll
        for (int j = 0; j < 4; j++)
            #pragma unroll
            for (int q = 0; q < 4; q++) acc[i][j][q] = 0.f;

    float4 av0, av1, bv;
    auto loadA = [&](int k0) {
        if (rvalid) {
            av0 = *reinterpret_cast<const float4*>(Arow + k0 + lk);
            av1 = *reinterpret_cast<const float4*>(Arow + k0 + lk + 4);
        } else {
            av0 = make_float4(0.f, 0.f, 0.f, 0.f);
            av1 = av0;
        }
    };
    auto loadB = [&](int k0) {
        bv = *reinterpret_cast<const float4*>(Wih + (size_t)(k0 + bk) * Nw + bcol);
    };

    loadA(0); loadB(0);
    As[0][lk + 0][lm] = tf32r(av0.x); As[0][lk + 1][lm] = tf32r(av0.y);
    As[0][lk + 2][lm] = tf32r(av0.z); As[0][lk + 3][lm] = tf32r(av0.w);
    As[0][lk + 4][lm] = tf32r(av1.x); As[0][lk + 5][lm] = tf32r(av1.y);
    As[0][lk + 6][lm] = tf32r(av1.z); As[0][lk + 7][lm] = tf32r(av1.w);
    *reinterpret_cast<float4*>(&Bs[0][bk][bn]) =
        make_float4(tf32r(bv.x), tf32r(bv.y), tf32r(bv.z), tf32r(bv.w));
    __syncthreads();

    const int ntiles = EMB / 16;
    for (int it = 0; it < ntiles; it++) {
        int cur = it & 1;
        bool more = (it + 1 < ntiles);
        if (more) { loadA((it + 1) * 16); loadB((it + 1) * 16); }
        #pragma unroll
        for (int ks = 0; ks < 16; ks += 8) {
            uint32_t a[2][4], bfr[4][2];
            #pragma unroll
            for (int i = 0; i < 2; i++) {
                a[i][0] = __float_as_uint(As[cur][ks + tk][mw + i * 16 + g]);
                a[i][1] = __float_as_uint(As[cur][ks + tk][mw + i * 16 + g + 8]);
                a[i][2] = __float_as_uint(As[cur][ks + tk + 4][mw + i * 16 + g]);
                a[i][3] = __float_as_uint(As[cur][ks + tk + 4][mw + i * 16 + g + 8]);
            }
            #pragma unroll
            for (int j = 0; j < 4; j++) {
                bfr[j][0] = __float_as_uint(Bs[cur][ks + tk][nw + j * 8 + g]);
                bfr[j][1] = __float_as_uint(Bs[cur][ks + tk + 4][nw + j * 8 + g]);
            }
            #pragma unroll
            for (int i = 0; i < 2; i++)
                #pragma unroll
                for (int j = 0; j < 4; j++)
                    mma_tf32(acc[i][j], a[i], bfr[j]);
        }
        if (more) {
            int nxt = cur ^ 1;
            As[nxt][lk + 0][lm] = tf32r(av0.x); As[nxt][lk + 1][lm] = tf32r(av0.y);
            As[nxt][lk + 2][lm] = tf32r(av0.z); As[nxt][lk + 3][lm] = tf32r(av0.w);
            As[nxt][lk + 4][lm] = tf32r(av1.x); As[nxt][lk + 5][lm] = tf32r(av1.y);
            As[nxt][lk + 6][lm] = tf32r(av1.z); As[nxt][lk + 7][lm] = tf32r(av1.w);
            *reinterpret_cast<float4*>(&Bs[nxt][bk][bn]) =
                make_float4(tf32r(bv.x), tf32r(bv.y), tf32r(bv.z), tf32r(bv.w));
        }
        __syncthreads();
    }

    #pragma unroll
    for (int i = 0; i < 2; i++) {
        #pragma unroll
        for (int j = 0; j < 4; j++) {
            int col = colBase + nw + j * 8 + tk * 2;
            #pragma unroll
            for (int h = 0; h < 2; h++) {
                int rr = rowBase + mw + i * 16 + g + h * 8;
                if (rr < total) {
                    int mapped = d_rowmap[rr];
                    float* orow = d_embc + (size_t)mapped * 2048;
                    orow[col]     = acc[i][j][h * 2];
                    orow[col + 1] = acc[i][j][h * 2 + 1];
                }
            }
        }
    }
}

// ---------------- fused attend (PDL): e -> softmax -> awe, 1024 thr, 4-way p-split ----------------
__global__ void __launch_bounds__(1024, 1) k_attend(
        const float* __restrict__ enc,
        const float* __restrict__ Wf, const float* __restrict__ bf,
        const float* __restrict__ bd, const float* __restrict__ bb,
        float* __restrict__ out_alphas, int t) {
    int b = blockIdx.x;
    if (b >= d_nb[t]) return;
    __shared__ __align__(16) float a2[ATT];
    __shared__ __align__(16) float wf[ATT];
    __shared__ float es[PP + 4];
    __shared__ float red[32];
    __shared__ float redsum[32];
    __shared__ __align__(16) float awe_sh[3 * 2048];
    int tid = threadIdx.x;
    const float* p0 = d_agp + (size_t)b * AGC;
    const float* p1 = d_agp + (size_t)(BB + b) * AGC;
    // independent prologue: Wf into smem
    if (tid < 512) wf[tid] = Wf[tid];
    grid_dep_sync();
    if (tid < 512) a2[tid] = p0[tid] + p1[tid] + bd[tid];
    __syncthreads();
    int lane = tid & 31, warp = tid >> 5;

    const float4* a24 = reinterpret_cast<const float4*>(a2);
    const float4* wf4 = reinterpret_cast<const float4*>(wf);
    for (int p = warp; p < PP; p += 32) {
        const float4* row4 = reinterpret_cast<const float4*>(d_att1 + ((size_t)b * PP + p) * ATT);
        float s = 0.f;
        #pragma unroll
        for (int i = 0; i < 4; i++) {
            int idx = lane + i * 32;
            float4 v = row4[idx];
            float4 a = a24[idx];
            float4 w = wf4[idx];
            s += fmaxf(v.x + a.x, 0.f) * w.x;
            s += fmaxf(v.y + a.y, 0.f) * w.y;
            s += fmaxf(v.z + a.z, 0.f) * w.z;
            s += fmaxf(v.w + a.w, 0.f) * w.w;
        }
        #pragma unroll
        for (int off = 16; off > 0; off >>= 1) s += __shfl_xor_sync(0xffffffffu, s, off);
        if (lane == 0) es[p] = s + bf[0];
    }
    __syncthreads();

    float v = (tid < PP) ? es[tid] : -1e30f;
    float m = v;
    #pragma unroll
    for (int off = 16; off > 0; off >>= 1) m = fmaxf(m, __shfl_xor_sync(0xffffffffu, m, off));
    if (lane == 0) red[warp] = m;
    __syncthreads();
    if (tid == 0) {
        float mm = red[0];
        for (int i = 1; i < 32; i++) mm = fmaxf(mm, red[i]);
        red[0] = mm;
    }
    __syncthreads();
    float smax = red[0];
    float ev = (tid < PP) ? __expf(v - smax) : 0.f;
    float s = ev;
    #pragma unroll
    for (int off = 16; off > 0; off >>= 1) s += __shfl_xor_sync(0xffffffffu, s, off);
    if (lane == 0) redsum[warp] = s;
    __syncthreads();
    if (tid == 0) {
        float ss = redsum[0];
        for (int i = 1; i < 32; i++) ss += redsum[i];
        redsum[0] = ss;
    }
    __syncthreads();
    float inv = 1.0f / redsum[0];
    float al = ev * inv;
    if (tid < PP) {
        es[tid] = al;
        out_alphas[((size_t)b * TT + t) * PP + tid] = al;
    }
    __syncthreads();

    int src = d_sort_src[b];
    int quarter = tid >> 8;
    int c4a = tid & 255;
    const float4* enc4 = reinterpret_cast<const float4*>(enc + (size_t)src * PP * EE);
    int pbeg = quarter * 49, pend = pbeg + 49;
    float4 accA = make_float4(0.f, 0.f, 0.f, 0.f);
    float4 accB = make_float4(0.f, 0.f, 0.f, 0.f);
    for (int p = pbeg; p < pend; p++) {
        float alp = es[p];
        float4 eA = enc4[p * 512 + c4a];
        float4 eB = enc4[p * 512 + c4a + 256];
        accA.x += alp * eA.x; accA.y += alp * eA.y;
        accA.z += alp * eA.z; accA.w += alp * eA.w;
        accB.x += alp * eB.x; accB.y += alp * eB.y;
        accB.z += alp * eB.z; accB.w += alp * eB.w;
    }
    float4* sh4 = reinterpret_cast<float4*>(awe_sh);
    if (quarter > 0) {
        sh4[(quarter - 1) * 512 + c4a] = accA;
        sh4[(quarter - 1) * 512 + c4a + 256] = accB;
    }
    __syncthreads();
    if (quarter == 0) {
        #pragma unroll
        for (int q = 0; q < 3; q++) {
            float4 oA = sh4[q * 512 + c4a];
            float4 oB = sh4[q * 512 + c4a + 256];
            accA.x += oA.x; accA.y += oA.y; accA.z += oA.z; accA.w += oA.w;
            accB.x += oB.x; accB.y += oB.y; accB.z += oB.z; accB.w += oB.w;
        }
        const float4* gp04 = reinterpret_cast<const float4*>(p0 + 512);
        const float4* gp14 = reinterpret_cast<const float4*>(p1 + 512);
        const float4* bb4 = reinterpret_cast<const float4*>(bb);
        float4* awe4 = reinterpret_cast<float4*>(d_awe + (size_t)b * EE);
        #pragma unroll
        for (int h = 0; h < 2; h++) {
            int c4 = c4a + h * 256;
            float4 acc = h ? accB : accA;
            float4 gp0 = gp04[c4], gp1 = gp14[c4], bbv = bb4[c4];
            float4 gt;
            gt.x = 1.0f / (1.0f + __expf(-(gp0.x + gp1.x + bbv.x)));
            gt.y = 1.0f / (1.0f + __expf(-(gp0.y + gp1.y + bbv.y)));
            gt.z = 1.0f / (1.0f + __expf(-(gp0.z + gp1.z + bbv.z)));
            gt.w = 1.0f / (1.0f + __expf(-(gp0.w + gp1.w + bbv.w)));
            awe4[c4] = make_float4(acc.x * gt.x, acc.y * gt.y, acc.z * gt.z, acc.w * gt.w);
        }
    }
}

// ---------------- host launch ----------------
extern "C" void kernel_launch(void* const* d_in, const int* in_sizes, int n_in,
                              void* d_out, int out_size) {
    const float* enc  = (const float*)d_in[0];
    const int*   caps = (const int*)d_in[1];
    const int*   clen = (const int*)d_in[2];
    const float* emb  = (const float*)d_in[3];
    const float* We   = (const float*)d_in[4];
    const float* be   = (const float*)d_in[5];
    const float* Wd   = (const float*)d_in[6];
    const float* bd   = (const float*)d_in[7];
    const float* Wf   = (const float*)d_in[8];
    const float* bf   = (const float*)d_in[9];
    const float* Wih  = (const float*)d_in[10];
    const float* bih  = (const float*)d_in[11];
    const float* Whh  = (const float*)d_in[12];
    const float* bhh  = (const float*)d_in[13];
    const float* Wb   = (const float*)d_in[14];
    const float* bb   = (const float*)d_in[15];
    const float* Whi  = (const float*)d_in[16];
    const float* bhi  = (const float*)d_in[17];
    const float* Wci  = (const float*)d_in[18];
    const float* bci  = (const float*)d_in[19];
    const float* Wfc  = (const float*)d_in[20];
    const float* bfc  = (const float*)d_in[21];
    float* out = (float*)d_out;
    float* out_alphas = out + (size_t)BB * TT * VV;

    k_setup<<<1, 64>>>(clen);
    k_zero<<<2048, 256>>>(out, (size_t)out_size);
    k_mean<<<dim3(8, BB), 256>>>(enc);

    // h0 + c0 in ONE split-K GEMM (concat [Whi|Wci], N=1024, K=2048, S=8)
    k_gemm32<<<dim3(32, 8), 256>>>(BUF_MEAN, Whi, Wci, 512, 512, 512, 1024, EE, 8, -1);
    k_reduce_hc<<<256, 256>>>(bhi, bci);

    // att1 via tf32 tensor cores
    k_att1_mma<<<dim3(98, 8), 256>>>(enc, We, be);

    // embc = embs(active rows) @ Wih[0:512]
    k_embc_mma<<<dim3(16, 32), 256>>>(emb, caps, Wih);

    // PDL attribute shared by the loop launches
    cudaLaunchAttribute pattr;
    pattr.id = cudaLaunchAttributeProgrammaticStreamSerialization;
    pattr.val.programmaticStreamSerializationAllowed = 1;
    auto mkcfg = [&](unsigned gx, unsigned gy, unsigned bx) {
        cudaLaunchConfig_t c;
        c.gridDim = dim3(gx, gy, 1);
        c.blockDim = dim3(bx, 1, 1);
        c.dynamicSmemBytes = 0;
        c.stream = 0;
        c.attrs = &pattr;
        c.numAttrs = 1;
        return c;
    };

    const float* Wih2 = Wih + (size_t)512 * 2048;
    for (int t = 0; t < TT; t++) {
        cudaLaunchConfig_t c1 = mkcfg(144, 2, 256);
        cudaLaunchKernelEx(&c1, k_ag, Wd, Wb, Whh, t);
        cudaLaunchConfig_t c2 = mkcfg(BB, 1, 1024);
        cudaLaunchKernelEx(&c2, k_attend, enc, Wf, bf, bd, bb, out_alphas, t);
        cudaLaunchConfig_t c3 = mkcfg(16, 8, 256);
        cudaLaunchKernelEx(&c3, k_awe_mma, Wih2, t);
        cudaLaunchConfig_t c4 = mkcfg(128, 1, 256);
        cudaLaunchKernelEx(&c4, k_reduce_lstm, bih, bhh, t);
    }

    // batched vocab projection via tf32 tensor cores
    k_preds_mma<<<dim3(16, 157), 256>>>(Wfc, bfc, out);
}

// round 15
// speedup vs baseline: 1.4233x; 1.0326x over previous
#include <cuda_runtime.h>
#include <cuda_bf16.h>
#include <cstdint>

// Problem constants
#define BB 64
#define PP 196
#define EE 2048
#define LL 32
#define VV 10000
#define EMB 512
#define DEC 512
#define ATT 512
#define TT 31   // L-1 steps

// ---------------- device scratch ----------------
__device__ __align__(16) int   d_sort_src[BB];
__device__ __align__(16) int   d_nb[TT + 1];
__device__ int   d_total;
__device__ __align__(16) int   d_rowmap[BB * TT];
__device__ __align__(16) float d_mean[BB * EE];
__device__ __align__(16) float d_h[BB * DEC];
__device__ __align__(16) float d_c[BB * DEC];
__device__ __align__(16) float d_hhist[(size_t)TT * BB * DEC];
__device__ __align__(16) float d_att1[(size_t)BB * PP * ATT];
__device__ __align__(16) float d_awe[BB * EE];
__device__ __align__(16) float d_embc[(size_t)TT * BB * 2048];
__device__ __align__(16) float d_part[8 * BB * 2048];
// phase-A partials: [split(4)][b(64)][col(4608)] — 0..511 att2, 512..2559 gate, 2560..4607 hg
#define AGC 4608
__device__ __align__(16) float d_agp[4 * BB * AGC];

#define BUF_MEAN 0

__device__ __forceinline__ float* selbuf(int s) {
    switch (s) {
        case BUF_MEAN: return d_mean;
        default:       return nullptr;
    }
}

// ---------------- PDL helper ----------------
__device__ __forceinline__ void grid_dep_sync() {
#if defined(__CUDA_ARCH__) && __CUDA_ARCH__ >= 900
    cudaGridDependencySynchronize();
#endif
}

// ---------------- tf32 helpers ----------------
__device__ __forceinline__ float tf32r(float f) {
    uint32_t u;
    asm("cvt.rna.tf32.f32 %0, %1;" : "=r"(u) : "f"(f));
    return __uint_as_float(u);
}
__device__ __forceinline__ void mma_tf32(float* c, const uint32_t* a, const uint32_t* b) {
    asm volatile("mma.sync.aligned.m16n8k8.row.col.f32.tf32.tf32.f32 "
        "{%0,%1,%2,%3}, {%4,%5,%6,%7}, {%8,%9}, {%0,%1,%2,%3};"
        : "+f"(c[0]), "+f"(c[1]), "+f"(c[2]), "+f"(c[3])
        : "r"(a[0]), "r"(a[1]), "r"(a[2]), "r"(a[3]), "r"(b[0]), "r"(b[1]));
}

// ---------------- setup ----------------
__global__ void k_setup(const int* __restrict__ cap_len) {
    __shared__ int lens[BB];
    __shared__ int nbs[TT + 1];
    __shared__ int off[TT + 1];
    int b = threadIdx.x;
    if (b < BB) lens[b] = cap_len[b];
    __syncthreads();
    if (b < BB) {
        int rank = 0;
        int lb = lens[b];
        for (int j = 0; j < BB; j++) {
            int lj = lens[j];
            if (lj > lb || (lj == lb && j < b)) rank++;
        }
        d_sort_src[rank] = b;
    }
    if (b <= TT) {
        int cnt = 0;
        for (int j = 0; j < BB; j++) if (lens[j] - 1 > b) cnt++;
        d_nb[b] = cnt;
        nbs[b] = cnt;
    }
    __syncthreads();
    if (b == 0) {
        int a = 0;
        for (int t = 0; t < TT; t++) { off[t] = a; a += nbs[t]; }
        d_total = a;
    }
    __syncthreads();
    if (b < BB) {
        for (int t = 0; t < TT; t++)
            if (b < nbs[t]) d_rowmap[off[t] + b] = (t << 6) | b;
    }
}

__global__ void k_zero(float* __restrict__ out, size_t n) {
    size_t i = (size_t)blockIdx.x * blockDim.x + threadIdx.x;
    size_t stride = (size_t)gridDim.x * blockDim.x;
    for (; i < n; i += stride) out[i] = 0.0f;
}

__global__ void k_mean(const float* __restrict__ enc) {
    int b = blockIdx.y;
    int e = blockIdx.x * 256 + threadIdx.x;
    const float* base = enc + (size_t)d_sort_src[b] * PP * EE + e;
    float s = 0.0f;
    #pragma unroll 7
    for (int p = 0; p < PP; p++) s += base[(size_t)p * EE];
    d_mean[b * EE + e] = s * (1.0f / 196.0f);
}

// ---------------- split-K GEMM, KTILE=32, into d_part (h0/c0 only) ----------------
__global__ void __launch_bounds__(256, 2) k_gemm32(
        int xsel, const float* __restrict__ WA, const float* __restrict__ WB,
        int colSplit, int NA, int NB, int Nout, int K, int S, int t) {
    __shared__ __align__(16) float Xs[2][32][68];
    __shared__ __align__(16) float Ws[2][32][34];

    const float* X = selbuf(xsel);
    int tid = threadIdx.x;
    int nb = (t >= 0) ? d_nb[t] : BB;
    int n0 = blockIdx.x * 32;

    const float* W; int wc0, NW;
    if (n0 < colSplit) { W = WA; wc0 = n0; NW = NA; }
    else               { W = WB; wc0 = n0 - colSplit; NW = NB; }

    int s = blockIdx.y;
    int kbeg = s * (K / S);
    int ntiles = (K / S) / 32;

    int nl = tid & 15;
    int mg = tid >> 4;
    int m0 = mg << 2;
    bool rowact = (m0 < nb);

    int lm = tid >> 2, lk = (tid & 3) << 2;
    int wk = tid >> 4, wn = tid & 15;
    bool xact = (lm < nb);
    const float* Xrow = X + (size_t)lm * K;

    float acc[4][2];
    #pragma unroll
    for (int i = 0; i < 4; i++) { acc[i][0] = 0.f; acc[i][1] = 0.f; }

    float4 xr0 = make_float4(0.f, 0.f, 0.f, 0.f), xr1 = xr0;
    float wr00, wr01, wr10, wr11;
    auto loadG = [&](int k0) {
        if (xact) {
            xr0 = *reinterpret_cast<const float4*>(Xrow + k0 + lk);
            xr1 = *reinterpret_cast<const float4*>(Xrow + k0 + lk + 16);
        }
        int kg = k0 + wk;
        wr00 = W[(size_t)kg * NW + wc0 + wn];
        wr01 = W[(size_t)kg * NW + wc0 + wn + 16];
        wr10 = W[(size_t)(kg + 16) * NW + wc0 + wn];
        wr11 = W[(size_t)(kg + 16) * NW + wc0 + wn + 16];
    };
    auto stS = [&](int buf) {
        Xs[buf][lk + 0][lm] = xr0.x; Xs[buf][lk + 1][lm] = xr0.y;
        Xs[buf][lk + 2][lm] = xr0.z; Xs[buf][lk + 3][lm] = xr0.w;
        Xs[buf][lk + 16][lm] = xr1.x; Xs[buf][lk + 17][lm] = xr1.y;
        Xs[buf][lk + 18][lm] = xr1.z; Xs[buf][lk + 19][lm] = xr1.w;
        Ws[buf][wk][wn] = wr00; Ws[buf][wk][wn + 16] = wr01;
        Ws[buf][wk + 16][wn] = wr10; Ws[buf][wk + 16][wn + 16] = wr11;
    };

    loadG(kbeg);
    stS(0);
    __syncthreads();

    for (int it = 0; it < ntiles; it++) {
        int cur = it & 1;
        bool more = (it + 1 < ntiles);
        if (more) loadG(kbeg + (it + 1) * 32);
        if (rowact) {
            #pragma unroll
            for (int kk = 0; kk < 32; kk++) {
                float4 xv = *reinterpret_cast<const float4*>(&Xs[cur][kk][m0]);
                float2 wv = *reinterpret_cast<const float2*>(&Ws[cur][kk][nl * 2]);
                acc[0][0] += xv.x * wv.x; acc[0][1] += xv.x * wv.y;
                acc[1][0] += xv.y * wv.x; acc[1][1] += xv.y * wv.y;
                acc[2][0] += xv.z * wv.x; acc[2][1] += xv.z * wv.y;
                acc[3][0] += xv.w * wv.x; acc[3][1] += xv.w * wv.y;
            }
        }
        if (more) stS(cur ^ 1);
        __syncthreads();
    }

    if (!rowact) return;
    int na = n0 + nl * 2;
    #pragma unroll
    for (int j = 0; j < 4; j++) {
        int m = m0 + j;
        if (m < nb) {
            size_t base = ((size_t)(s * BB + m)) * Nout + na;
            d_part[base] = acc[j][0];
            d_part[base + 1] = acc[j][1];
        }
    }
}

// reduce combined h0/c0 (N=1024, S=8)
__global__ void k_reduce_hc(const float* __restrict__ bhi, const float* __restrict__ bci) {
    int idx = blockIdx.x * 256 + threadIdx.x;
    if (idx >= BB * 1024) return;
    int m = idx >> 10, n = idx & 1023;
    float v = 0.f;
    #pragma unroll
    for (int s = 0; s < 8; s++) v += d_part[((size_t)(s * BB + m)) * 1024 + n];
    if (n < 512) d_h[m * 512 + n] = v + bhi[n];
    else         d_c[m * 512 + (n - 512)] = v + bci[n - 512];
}

// ---------------- phase A via tf32 MMA (PDL): h(64,512) @ [Wd|Wb|Whh] -> d_agp, S=4 ----------------
// grid (36, 4): 36 n-tiles of 128 over concat N=4608; tiles never straddle weight boundaries.
__global__ void __launch_bounds__(256, 2) k_ag_mma(
        const float* __restrict__ Wd, const float* __restrict__ Wb,
        const float* __restrict__ Whh, int t) {
    __shared__ float As[2][16][72];
    __shared__ float Bs[2][16][136];
    int nb = d_nb[t];
    int tid = threadIdx.x;
    int warp = tid >> 5, lane = tid & 31;
    int g = lane >> 2, tk = lane & 3;
    int mw = (warp & 1) * 32, nw = (warp >> 1) * 32;
    int nBase = blockIdx.x * 128;
    int s = blockIdx.y;
    int kbeg = s * 128;
    const int ntiles = 8;

    const float* W; int wc0, NW;
    if (nBase < 512)       { W = Wd;  wc0 = nBase;        NW = ATT; }
    else if (nBase < 2560) { W = Wb;  wc0 = nBase - 512;  NW = 2048; }
    else                   { W = Whh; wc0 = nBase - 2560; NW = 2048; }

    int lm = tid >> 2, lk = (tid & 3) << 2;
    bool xact = (lm < nb);
    const float* Arow = d_h + (size_t)lm * DEC;
    int bk = tid >> 4, bn = (tid & 15) << 2;
    bool wact = (mw < nb);

    float acc[2][4][4];
    #pragma unroll
    for (int i = 0; i < 2; i++)
        #pragma unroll
        for (int j = 0; j < 4; j++)
            #pragma unroll
            for (int q = 0; q < 4; q++) acc[i][j][q] = 0.f;

    float4 av = make_float4(0.f, 0.f, 0.f, 0.f), bv0, bv1;
    auto loadB = [&](int k0) {
        const float* wr = W + (size_t)(k0 + bk) * NW + wc0 + bn;
        bv0 = *reinterpret_cast<const float4*>(wr);
        bv1 = *reinterpret_cast<const float4*>(wr + 64);
    };
    auto loadA = [&](int k0) {
        if (xact) av = *reinterpret_cast<const float4*>(Arow + k0 + lk);
    };
    auto stS = [&](int buf) {
        As[buf][lk + 0][lm] = tf32r(av.x); As[buf][lk + 1][lm] = tf32r(av.y);
        As[buf][lk + 2][lm] = tf32r(av.z); As[buf][lk + 3][lm] = tf32r(av.w);
        *reinterpret_cast<float4*>(&Bs[buf][bk][bn]) =
            make_float4(tf32r(bv0.x), tf32r(bv0.y), tf32r(bv0.z), tf32r(bv0.w));
        *reinterpret_cast<float4*>(&Bs[buf][bk][bn + 64]) =
            make_float4(tf32r(bv1.x), tf32r(bv1.y), tf32r(bv1.z), tf32r(bv1.w));
    };

    // PDL: preload independent W tile 0, then wait for predecessor (d_h producer)
    loadB(kbeg);
    grid_dep_sync();
    loadA(kbeg);
    stS(0);
    __syncthreads();

    for (int it = 0; it < ntiles; it++) {
        int cur = it & 1;
        bool more = (it + 1 < ntiles);
        if (more) { loadB(kbeg + (it + 1) * 16); loadA(kbeg + (it + 1) * 16); }
        if (wact) {
            #pragma unroll
            for (int ks = 0; ks < 16; ks += 8) {
                uint32_t a[2][4], bfr[4][2];
                #pragma unroll
                for (int i = 0; i < 2; i++) {
                    a[i][0] = __float_as_uint(As[cur][ks + tk][mw + i * 16 + g]);
                    a[i][1] = __float_as_uint(As[cur][ks + tk][mw + i * 16 + g + 8]);
                    a[i][2] = __float_as_uint(As[cur][ks + tk + 4][mw + i * 16 + g]);
                    a[i][3] = __float_as_uint(As[cur][ks + tk + 4][mw + i * 16 + g + 8]);
                }
                #pragma unroll
                for (int j = 0; j < 4; j++) {
                    bfr[j][0] = __float_as_uint(Bs[cur][ks + tk][nw + j * 8 + g]);
                    bfr[j][1] = __float_as_uint(Bs[cur][ks + tk + 4][nw + j * 8 + g]);
                }
                #pragma unroll
                for (int i = 0; i < 2; i++)
                    #pragma unroll
                    for (int j = 0; j < 4; j++)
                        mma_tf32(acc[i][j], a[i], bfr[j]);
            }
        }
        if (more) stS(cur ^ 1);
        __syncthreads();
    }

    if (!wact) return;
    #pragma unroll
    for (int i = 0; i < 2; i++) {
        #pragma unroll
        for (int j = 0; j < 4; j++) {
            int col = nBase + nw + j * 8 + tk * 2;
            #pragma unroll
            for (int h = 0; h < 2; h++) {
                int row = mw + i * 16 + g + h * 8;
                if (row < nb) {
                    float* p = d_agp + ((size_t)(s * BB + row)) * AGC + col;
                    p[0] = acc[i][j][h * 2];
                    p[1] = acc[i][j][h * 2 + 1];
                }
            }
        }
    }
}

// ---------------- awe GEMM via tf32 MMA (PDL): d_awe(64,2048) @ Wih2, S=8 ----------------
__global__ void __launch_bounds__(256, 2) k_awe_mma(const float* __restrict__ Wih2, int t) {
    __shared__ float As[2][16][72];
    __shared__ float Bs[2][16][136];
    int nb = d_nb[t];
    int tid = threadIdx.x;
    int warp = tid >> 5, lane = tid & 31;
    int g = lane >> 2, tk = lane & 3;
    int mw = (warp & 1) * 32, nw = (warp >> 1) * 32;
    int nBase = blockIdx.x * 128;
    int s = blockIdx.y;
    int kbeg = s * 256;
    const int ntiles = 16;

    int lm = tid >> 2, lk = (tid & 3) << 2;
    bool xact = (lm < nb);
    const float* Arow = d_awe + (size_t)lm * 2048;
    int bk = tid >> 4, bn = (tid & 15) << 2;
    bool wact = (mw < nb);

    float acc[2][4][4];
    #pragma unroll
    for (int i = 0; i < 2; i++)
        #pragma unroll
        for (int j = 0; j < 4; j++)
            #pragma unroll
            for (int q = 0; q < 4; q++) acc[i][j][q] = 0.f;

    float4 av = make_float4(0.f, 0.f, 0.f, 0.f), bv0, bv1;
    auto loadB = [&](int k0) {
        const float* wr = Wih2 + (size_t)(k0 + bk) * 2048 + nBase + bn;
        bv0 = *reinterpret_cast<const float4*>(wr);
        bv1 = *reinterpret_cast<const float4*>(wr + 64);
    };
    auto loadA = [&](int k0) {
        if (xact) av = *reinterpret_cast<const float4*>(Arow + k0 + lk);
    };
    auto stS = [&](int buf) {
        As[buf][lk + 0][lm] = tf32r(av.x); As[buf][lk + 1][lm] = tf32r(av.y);
        As[buf][lk + 2][lm] = tf32r(av.z); As[buf][lk + 3][lm] = tf32r(av.w);
        *reinterpret_cast<float4*>(&Bs[buf][bk][bn]) =
            make_float4(tf32r(bv0.x), tf32r(bv0.y), tf32r(bv0.z), tf32r(bv0.w));
        *reinterpret_cast<float4*>(&Bs[buf][bk][bn + 64]) =
            make_float4(tf32r(bv1.x), tf32r(bv1.y), tf32r(bv1.z), tf32r(bv1.w));
    };

    loadB(kbeg);
    grid_dep_sync();
    loadA(kbeg);
    stS(0);
    __syncthreads();

    for (int it = 0; it < ntiles; it++) {
        int cur = it & 1;
        bool more = (it + 1 < ntiles);
        if (more) { loadB(kbeg + (it + 1) * 16); loadA(kbeg + (it + 1) * 16); }
        if (wact) {
            #pragma unroll
            for (int ks = 0; ks < 16; ks += 8) {
                uint32_t a[2][4], bfr[4][2];
                #pragma unroll
                for (int i = 0; i < 2; i++) {
                    a[i][0] = __float_as_uint(As[cur][ks + tk][mw + i * 16 + g]);
                    a[i][1] = __float_as_uint(As[cur][ks + tk][mw + i * 16 + g + 8]);
                    a[i][2] = __float_as_uint(As[cur][ks + tk + 4][mw + i * 16 + g]);
                    a[i][3] = __float_as_uint(As[cur][ks + tk + 4][mw + i * 16 + g + 8]);
                }
                #pragma unroll
                for (int j = 0; j < 4; j++) {
                    bfr[j][0] = __float_as_uint(Bs[cur][ks + tk][nw + j * 8 + g]);
                    bfr[j][1] = __float_as_uint(Bs[cur][ks + tk + 4][nw + j * 8 + g]);
                }
                #pragma unroll
                for (int i = 0; i < 2; i++)
                    #pragma unroll
                    for (int j = 0; j < 4; j++)
                        mma_tf32(acc[i][j], a[i], bfr[j]);
            }
        }
        if (more) stS(cur ^ 1);
        __syncthreads();
    }

    if (!wact) return;
    #pragma unroll
    for (int i = 0; i < 2; i++) {
        #pragma unroll
        for (int j = 0; j < 4; j++) {
            int col = nBase + nw + j * 8 + tk * 2;
            #pragma unroll
            for (int h = 0; h < 2; h++) {
                int row = mw + i * 16 + g + h * 8;
                if (row < nb) {
                    float* p = d_part + ((size_t)(s * BB + row)) * 2048 + col;
                    p[0] = acc[i][j][h * 2];
                    p[1] = acc[i][j][h * 2 + 1];
                }
            }
        }
    }
}

// ---------------- reduce (PDL): g = embc + hg(4) + awe parts(8) + biases, LSTM ----------------
__global__ void k_reduce_lstm(const float* __restrict__ bih, const float* __restrict__ bhh, int t) {
    int idx = blockIdx.x * 256 + threadIdx.x;
    int b = idx >> 9, d = idx & 511;
    bool act = (b < d_nb[t]);
    float gi = 0.f, gf = 0.f, gg = 0.f, go = 0.f;
    if (act) {
        const float* e = d_embc + ((size_t)((t << 6) | b)) * 2048;
        gi = bih[d]        + bhh[d]        + e[d];
        gf = bih[512 + d]  + bhh[512 + d]  + e[512 + d];
        gg = bih[1024 + d] + bhh[1024 + d] + e[1024 + d];
        go = bih[1536 + d] + bhh[1536 + d] + e[1536 + d];
    }
    grid_dep_sync();
    if (!act) return;
    #pragma unroll
    for (int s = 0; s < 4; s++) {
        const float* hg = d_agp + (size_t)(s * BB + b) * AGC + 2560;
        gi += hg[d]; gf += hg[512 + d]; gg += hg[1024 + d]; go += hg[1536 + d];
    }
    #pragma unroll
    for (int s = 0; s < 8; s++) {
        const float* p = d_part + ((size_t)(s * BB + b)) * 2048;
        gi += p[d]; gf += p[512 + d]; gg += p[1024 + d]; go += p[1536 + d];
    }
    float c = d_c[b * DEC + d];
    float si = 1.0f / (1.0f + __expf(-gi));
    float sf = 1.0f / (1.0f + __expf(-gf));
    float so = 1.0f / (1.0f + __expf(-go));
    float cn = sf * c + si * tanhf(gg);
    float hn = so * tanhf(cn);
    d_c[b * DEC + d] = cn;
    d_h[b * DEC + d] = hn;
    d_hhist[((size_t)t * BB + b) * DEC + d] = hn;
}

// ---------------- att1 = enc[sorted] @ We + be : tf32 MMA ----------------
__global__ void __launch_bounds__(256, 2) k_att1_mma(const float* __restrict__ enc,
                                                     const float* __restrict__ We,
                                                     const float* __restrict__ be) {
    __shared__ float As[2][16][136];
    __shared__ float Bs[2][16][72];
    int tid = threadIdx.x;
    int warp = tid >> 5, lane = tid & 31;
    int g = lane >> 2, tk = lane & 3;
    int mw = (warp & 3) * 32, nw = (warp >> 2) * 32;
    int rowBase = blockIdx.x * 128, colBase = blockIdx.y * 64;

    int lm = tid >> 1, lk = (tid & 1) << 3;
    int r = rowBase + lm;
    int bidx = r / PP, pidx = r % PP;
    const float* Arow = enc + ((size_t)d_sort_src[bidx] * PP + pidx) * EE;
    int bk = tid >> 4, bn = (tid & 15) << 2;

    float acc[2][4][4];
    #pragma unroll
    for (int i = 0; i < 2; i++)
        #pragma unroll
        for (int j = 0; j < 4; j++)
            #pragma unroll
            for (int q = 0; q < 4; q++) acc[i][j][q] = 0.f;

    float4 av0, av1, bv;
    av0 = *reinterpret_cast<const float4*>(Arow + lk);
    av1 = *reinterpret_cast<const float4*>(Arow + lk + 4);
    bv  = *reinterpret_cast<const float4*>(We + (size_t)bk * ATT + colBase + bn);
    As[0][lk + 0][lm] = tf32r(av0.x); As[0][lk + 1][lm] = tf32r(av0.y);
    As[0][lk + 2][lm] = tf32r(av0.z); As[0][lk + 3][lm] = tf32r(av0.w);
    As[0][lk + 4][lm] = tf32r(av1.x); As[0][lk + 5][lm] = tf32r(av1.y);
    As[0][lk + 6][lm] = tf32r(av1.z); As[0][lk + 7][lm] = tf32r(av1.w);
    *reinterpret_cast<float4*>(&Bs[0][bk][bn]) =
        make_float4(tf32r(bv.x), tf32r(bv.y), tf32r(bv.z), tf32r(bv.w));
    __syncthreads();

    const int ntiles = EE / 16;
    for (int it = 0; it < ntiles; it++) {
        int cur = it & 1;
        bool more = (it + 1 < ntiles);
        if (more) {
            int k0 = (it + 1) * 16;
            av0 = *reinterpret_cast<const float4*>(Arow + k0 + lk);
            av1 = *reinterpret_cast<const float4*>(Arow + k0 + lk + 4);
            bv  = *reinterpret_cast<const float4*>(We + (size_t)(k0 + bk) * ATT + colBase + bn);
        }
        #pragma unroll
        for (int ks = 0; ks < 16; ks += 8) {
            uint32_t a[2][4], bfr[4][2];
            #pragma unroll
            for (int i = 0; i < 2; i++) {
                a[i][0] = __float_as_uint(As[cur][ks + tk][mw + i * 16 + g]);
                a[i][1] = __float_as_uint(As[cur][ks + tk][mw + i * 16 + g + 8]);
                a[i][2] = __float_as_uint(As[cur][ks + tk + 4][mw + i * 16 + g]);
                a[i][3] = __float_as_uint(As[cur][ks + tk + 4][mw + i * 16 + g + 8]);
            }
            #pragma unroll
            for (int j = 0; j < 4; j++) {
                bfr[j][0] = __float_as_uint(Bs[cur][ks + tk][nw + j * 8 + g]);
                bfr[j][1] = __float_as_uint(Bs[cur][ks + tk + 4][nw + j * 8 + g]);
            }
            #pragma unroll
            for (int i = 0; i < 2; i++)
                #pragma unroll
                for (int j = 0; j < 4; j++)
                    mma_tf32(acc[i][j], a[i], bfr[j]);
        }
        if (more) {
            int nxt = cur ^ 1;
            As[nxt][lk + 0][lm] = tf32r(av0.x); As[nxt][lk + 1][lm] = tf32r(av0.y);
            As[nxt][lk + 2][lm] = tf32r(av0.z); As[nxt][lk + 3][lm] = tf32r(av0.w);
            As[nxt][lk + 4][lm] = tf32r(av1.x); As[nxt][lk + 5][lm] = tf32r(av1.y);
            As[nxt][lk + 6][lm] = tf32r(av1.z); As[nxt][lk + 7][lm] = tf32r(av1.w);
            *reinterpret_cast<float4*>(&Bs[nxt][bk][bn]) =
                make_float4(tf32r(bv.x), tf32r(bv.y), tf32r(bv.z), tf32r(bv.w));
        }
        __syncthreads();
    }

    #pragma unroll
    for (int i = 0; i < 2; i++) {
        int row0 = rowBase + mw + i * 16 + g;
        #pragma unroll
        for (int j = 0; j < 4; j++) {
            int col = colBase + nw + j * 8 + tk * 2;
            float be0 = be[col], be1 = be[col + 1];
            float2 o0 = make_float2(acc[i][j][0] + be0, acc[i][j][1] + be1);
            float2 o1 = make_float2(acc[i][j][2] + be0, acc[i][j][3] + be1);
            *reinterpret_cast<float2*>(d_att1 + (size_t)row0 * ATT + col) = o0;
            *reinterpret_cast<float2*>(d_att1 + (size_t)(row0 + 8) * ATT + col) = o1;
        }
    }
}

// ---------------- batched preds: tf32 MMA, compact rows @ Wfc ----------------
__global__ void __launch_bounds__(256, 2) k_preds_mma(const float* __restrict__ Wfc,
                                                      const float* __restrict__ bfc,
                                                      float* __restrict__ out) {
    int total = d_total;
    int rowBase = blockIdx.x * 128;
    if (rowBase >= total) return;
    int colBase = blockIdx.y * 64;

    __shared__ float As[2][16][136];
    __shared__ float Bs[2][16][72];
    int tid = threadIdx.x;
    int warp = tid >> 5, lane = tid & 31;
    int g = lane >> 2, tk = lane & 3;
    int mw = (warp & 3) * 32, nw = (warp >> 2) * 32;

    int lm = tid >> 1, lk = (tid & 1) << 3;
    int r = rowBase + lm;
    bool rvalid = (r < total);
    const float* Arow = d_hhist + (size_t)(rvalid ? d_rowmap[r] : 0) * DEC;
    int bk = tid >> 4, bn = (tid & 15) << 2;
    int bcol = colBase + bn;
    bool cvalid = (bcol < VV);

    float acc[2][4][4];
    #pragma unroll
    for (int i = 0; i < 2; i++)
        #pragma unroll
        for (int j = 0; j < 4; j++)
            #pragma unroll
            for (int q = 0; q < 4; q++) acc[i][j][q] = 0.f;

    float4 av0, av1, bv;
    auto loadA = [&](int k0) {
        if (rvalid) {
            av0 = *reinterpret_cast<const float4*>(Arow + k0 + lk);
            av1 = *reinterpret_cast<const float4*>(Arow + k0 + lk + 4);
        } else {
            av0 = make_float4(0.f, 0.f, 0.f, 0.f);
            av1 = av0;
        }
    };
    auto loadB = [&](int k0) {
        if (cvalid) bv = *reinterpret_cast<const float4*>(Wfc + (size_t)(k0 + bk) * VV + bcol);
        else        bv = make_float4(0.f, 0.f, 0.f, 0.f);
    };

    loadA(0); loadB(0);
    As[0][lk + 0][lm] = tf32r(av0.x); As[0][lk + 1][lm] = tf32r(av0.y);
    As[0][lk + 2][lm] = tf32r(av0.z); As[0][lk + 3][lm] = tf32r(av0.w);
    As[0][lk + 4][lm] = tf32r(av1.x); As[0][lk + 5][lm] = tf32r(av1.y);
    As[0][lk + 6][lm] = tf32r(av1.z); As[0][lk + 7][lm] = tf32r(av1.w);
    *reinterpret_cast<float4*>(&Bs[0][bk][bn]) =
        make_float4(tf32r(bv.x), tf32r(bv.y), tf32r(bv.z), tf32r(bv.w));
    __syncthreads();

    const int ntiles = DEC / 16;
    for (int it = 0; it < ntiles; it++) {
        int cur = it & 1;
        bool more = (it + 1 < ntiles);
        if (more) { loadA((it + 1) * 16); loadB((it + 1) * 16); }
        #pragma unroll
        for (int ks = 0; ks < 16; ks += 8) {
            uint32_t a[2][4], bfr[4][2];
            #pragma unroll
            for (int i = 0; i < 2; i++) {
                a[i][0] = __float_as_uint(As[cur][ks + tk][mw + i * 16 + g]);
                a[i][1] = __float_as_uint(As[cur][ks + tk][mw + i * 16 + g + 8]);
                a[i][2] = __float_as_uint(As[cur][ks + tk + 4][mw + i * 16 + g]);
                a[i][3] = __float_as_uint(As[cur][ks + tk + 4][mw + i * 16 + g + 8]);
            }
            #pragma unroll
            for (int j = 0; j < 4; j++) {
                bfr[j][0] = __float_as_uint(Bs[cur][ks + tk][nw + j * 8 + g]);
                bfr[j][1] = __float_as_uint(Bs[cur][ks + tk + 4][nw + j * 8 + g]);
            }
            #pragma unroll
            for (int i = 0; i < 2; i++)
                #pragma unroll
                for (int j = 0; j < 4; j++)
                    mma_tf32(acc[i][j], a[i], bfr[j]);
        }
        if (more) {
            int nxt = cur ^ 1;
            As[nxt][lk + 0][lm] = tf32r(av0.x); As[nxt][lk + 1][lm] = tf32r(av0.y);
            As[nxt][lk + 2][lm] = tf32r(av0.z); As[nxt][lk + 3][lm] = tf32r(av0.w);
            As[nxt][lk + 4][lm] = tf32r(av1.x); As[nxt][lk + 5][lm] = tf32r(av1.y);
            As[nxt][lk + 6][lm] = tf32r(av1.z); As[nxt][lk + 7][lm] = tf32r(av1.w);
            *reinterpret_cast<float4*>(&Bs[nxt][bk][bn]) =
                make_float4(tf32r(bv.x), tf32r(bv.y), tf32r(bv.z), tf32r(bv.w));
        }
        __syncthreads();
    }

    #pragma unroll
    for (int i = 0; i < 2; i++) {
        #pragma unroll
        for (int j = 0; j < 4; j++) {
            int col = colBase + nw + j * 8 + tk * 2;
            if (col >= VV) continue;
            float bf0 = bfc[col], bf1 = bfc[col + 1];
            #pragma unroll
            for (int h = 0; h < 2; h++) {
                int rr = rowBase + mw + i * 16 + g + h * 8;
                if (rr < total) {
                    int mapped = d_rowmap[rr];
                    int t = mapped >> 6, b = mapped & 63;
                    float* orow = out + ((size_t)b * TT + t) * VV;
                    orow[col]     = acc[i][j][h * 2]     + bf0;
                    orow[col + 1] = acc[i][j][h * 2 + 1] + bf1;
                }
            }
        }
    }
}

// ---------------- embc = embs(active rows) @ Wih[0:512] : tf32 MMA ----------------
__global__ void __launch_bounds__(256, 2) k_embc_mma(const float* __restrict__ emb,
                                                     const int* __restrict__ caps,
                                                     const float* __restrict__ Wih) {
    int total = d_total;
    int rowBase = blockIdx.x * 128;
    if (rowBase >= total) return;
    int colBase = blockIdx.y * 64;
    const int Nw = 2048;

    __shared__ float As[2][16][136];
    __shared__ float Bs[2][16][72];
    int tid = threadIdx.x;
    int warp = tid >> 5, lane = tid & 31;
    int g = lane >> 2, tk = lane & 3;
    int mw = (warp & 3) * 32, nw = (warp >> 2) * 32;

    int lm = tid >> 1, lk = (tid & 1) << 3;
    int r = rowBase + lm;
    bool rvalid = (r < total);
    const float* Arow;
    {
        int mapped = rvalid ? d_rowmap[r] : 0;
        int t = mapped >> 6, b = mapped & 63;
        int cap = caps[d_sort_src[b] * LL + t];
        Arow = emb + (size_t)cap * EMB;
    }
    int bk = tid >> 4, bn = (tid & 15) << 2;
    int bcol = colBase + bn;

    float acc[2][4][4];
    #pragma unroll
    for (int i = 0; i < 2; i++)
        #pragma unroll
        for (int j = 0; j < 4; j++)
            #pragma unroll
            for (int q = 0; q < 4; q++) acc[i][j][q] = 0.f;

    float4 av0, av1, bv;
    auto loadA = [&](int k0) {
        if (rvalid) {
            av0 = *reinterpret_cast<const float4*>(Arow + k0 + lk);
            av1 = *reinterpret_cast<const float4*>(Arow + k0 + lk + 4);
        } else {
            av0 = make_float4(0.f, 0.f, 0.f, 0.f);
            av1 = av0;
        }
    };
    auto loadB = [&](int k0) {
        bv = *reinterpret_cast<const float4*>(Wih + (size_t)(k0 + bk) * Nw + bcol);
    };

    loadA(0); loadB(0);
    As[0][lk + 0][lm] = tf32r(av0.x); As[0][lk + 1][lm] = tf32r(av0.y);
    As[0][lk + 2][lm] = tf32r(av0.z); As[0][lk + 3][lm] = tf32r(av0.w);
    As[0][lk + 4][lm] = tf32r(av1.x); As[0][lk + 5][lm] = tf32r(av1.y);
    As[0][lk + 6][lm] = tf32r(av1.z); As[0][lk + 7][lm] = tf32r(av1.w);
    *reinterpret_cast<float4*>(&Bs[0][bk][bn]) =
        make_float4(tf32r(bv.x), tf32r(bv.y), tf32r(bv.z), tf32r(bv.w));
    __syncthreads();

    const int ntiles = EMB / 16;
    for (int it = 0; it < ntiles; it++) {
        int cur = it & 1;
        bool more = (it + 1 < ntiles);
        if (more) { loadA((it + 1) * 16); loadB((it + 1) * 16); }
        #pragma unroll
        for (int ks = 0; ks < 16; ks += 8) {
            uint32_t a[2][4], bfr[4][2];
            #pragma unroll
            for (int i = 0; i < 2; i++) {
                a[i][0] = __float_as_uint(As[cur][ks + tk][mw + i * 16 + g]);
                a[i][1] = __float_as_uint(As[cur][ks + tk][mw + i * 16 + g + 8]);
                a[i][2] = __float_as_uint(As[cur][ks + tk + 4][mw + i * 16 + g]);
                a[i][3] = __float_as_uint(As[cur][ks + tk + 4][mw + i * 16 + g + 8]);
            }
            #pragma unroll
            for (int j = 0; j < 4; j++) {
                bfr[j][0] = __float_as_uint(Bs[cur][ks + tk][nw + j * 8 + g]);
                bfr[j][1] = __float_as_uint(Bs[cur][ks + tk + 4][nw + j * 8 + g]);
            }
            #pragma unroll
            for (int i = 0; i < 2; i++)
                #pragma unroll
                for (int j = 0; j < 4; j++)
                    mma_tf32(acc[i][j], a[i], bfr[j]);
        }
        if (more) {
            int nxt = cur ^ 1;
            As[nxt][lk + 0][lm] = tf32r(av0.x); As[nxt][lk + 1][lm] = tf32r(av0.y);
            As[nxt][lk + 2][lm] = tf32r(av0.z); As[nxt][lk + 3][lm] = tf32r(av0.w);
            As[nxt][lk + 4][lm] = tf32r(av1.x); As[nxt][lk + 5][lm] = tf32r(av1.y);
            As[nxt][lk + 6][lm] = tf32r(av1.z); As[nxt][lk + 7][lm] = tf32r(av1.w);
            *reinterpret_cast<float4*>(&Bs[nxt][bk][bn]) =
                make_float4(tf32r(bv.x), tf32r(bv.y), tf32r(bv.z), tf32r(bv.w));
        }
        __syncthreads();
    }

    #pragma unroll
    for (int i = 0; i < 2; i++) {
        #pragma unroll
        for (int j = 0; j < 4; j++) {
            int col = colBase + nw + j * 8 + tk * 2;
            #pragma unroll
            for (int h = 0; h < 2; h++) {
                int rr = rowBase + mw + i * 16 + g + h * 8;
                if (rr < total) {
                    int mapped = d_rowmap[rr];
                    float* orow = d_embc + (size_t)mapped * 2048;
                    orow[col]     = acc[i][j][h * 2];
                    orow[col + 1] = acc[i][j][h * 2 + 1];
                }
            }
        }
    }
}

// ---------------- fused attend (PDL): e -> softmax -> awe, 1024 thr, 4-way p-split ----------------
__global__ void __launch_bounds__(1024, 1) k_attend(
        const float* __restrict__ enc,
        const float* __restrict__ Wf, const float* __restrict__ bf,
        const float* __restrict__ bd, const float* __restrict__ bb,
        float* __restrict__ out_alphas, int t) {
    int b = blockIdx.x;
    if (b >= d_nb[t]) return;
    __shared__ __align__(16) float a2[ATT];
    __shared__ __align__(16) float wf[ATT];
    __shared__ float es[PP + 4];
    __shared__ float red[32];
    __shared__ float redsum[32];
    __shared__ __align__(16) float awe_sh[3 * 2048];
    int tid = threadIdx.x;
    const float* p0 = d_agp + (size_t)b * AGC;
    const float* p1 = d_agp + (size_t)(BB + b) * AGC;
    const float* p2 = d_agp + (size_t)(2 * BB + b) * AGC;
    const float* p3 = d_agp + (size_t)(3 * BB + b) * AGC;
    // independent prologue: Wf into smem
    if (tid < 512) wf[tid] = Wf[tid];
    grid_dep_sync();
    if (tid < 512) a2[tid] = p0[tid] + p1[tid] + p2[tid] + p3[tid] + bd[tid];
    __syncthreads();
    int lane = tid & 31, warp = tid >> 5;

    const float4* a24 = reinterpret_cast<const float4*>(a2);
    const float4* wf4 = reinterpret_cast<const float4*>(wf);
    for (int p = warp; p < PP; p += 32) {
        const float4* row4 = reinterpret_cast<const float4*>(d_att1 + ((size_t)b * PP + p) * ATT);
        float s = 0.f;
        #pragma unroll
        for (int i = 0; i < 4; i++) {
            int idx = lane + i * 32;
            float4 v = row4[idx];
            float4 a = a24[idx];
            float4 w = wf4[idx];
            s += fmaxf(v.x + a.x, 0.f) * w.x;
            s += fmaxf(v.y + a.y, 0.f) * w.y;
            s += fmaxf(v.z + a.z, 0.f) * w.z;
            s += fmaxf(v.w + a.w, 0.f) * w.w;
        }
        #pragma unroll
        for (int off = 16; off > 0; off >>= 1) s += __shfl_xor_sync(0xffffffffu, s, off);
        if (lane == 0) es[p] = s + bf[0];
    }
    __syncthreads();

    float v = (tid < PP) ? es[tid] : -1e30f;
    float m = v;
    #pragma unroll
    for (int off = 16; off > 0; off >>= 1) m = fmaxf(m, __shfl_xor_sync(0xffffffffu, m, off));
    if (lane == 0) red[warp] = m;
    __syncthreads();
    if (tid == 0) {
        float mm = red[0];
        for (int i = 1; i < 32; i++) mm = fmaxf(mm, red[i]);
        red[0] = mm;
    }
    __syncthreads();
    float smax = red[0];
    float ev = (tid < PP) ? __expf(v - smax) : 0.f;
    float s = ev;
    #pragma unroll
    for (int off = 16; off > 0; off >>= 1) s += __shfl_xor_sync(0xffffffffu, s, off);
    if (lane == 0) redsum[warp] = s;
    __syncthreads();
    if (tid == 0) {
        float ss = redsum[0];
        for (int i = 1; i < 32; i++) ss += redsum[i];
        redsum[0] = ss;
    }
    __syncthreads();
    float inv = 1.0f / redsum[0];
    float al = ev * inv;
    if (tid < PP) {
        es[tid] = al;
        out_alphas[((size_t)b * TT + t) * PP + tid] = al;
    }
    __syncthreads();

    int src = d_sort_src[b];
    int quarter = tid >> 8;
    int c4a = tid & 255;
    const float4* enc4 = reinterpret_cast<const float4*>(enc + (size_t)src * PP * EE);
    int pbeg = quarter * 49, pend = pbeg + 49;
    float4 accA = make_float4(0.f, 0.f, 0.f, 0.f);
    float4 accB = make_float4(0.f, 0.f, 0.f, 0.f);
    for (int p = pbeg; p < pend; p++) {
        float alp = es[p];
        float4 eA = enc4[p * 512 + c4a];
        float4 eB = enc4[p * 512 + c4a + 256];
        accA.x += alp * eA.x; accA.y += alp * eA.y;
        accA.z += alp * eA.z; accA.w += alp * eA.w;
        accB.x += alp * eB.x; accB.y += alp * eB.y;
        accB.z += alp * eB.z; accB.w += alp * eB.w;
    }
    float4* sh4 = reinterpret_cast<float4*>(awe_sh);
    if (quarter > 0) {
        sh4[(quarter - 1) * 512 + c4a] = accA;
        sh4[(quarter - 1) * 512 + c4a + 256] = accB;
    }
    __syncthreads();
    if (quarter == 0) {
        #pragma unroll
        for (int q = 0; q < 3; q++) {
            float4 oA = sh4[q * 512 + c4a];
            float4 oB = sh4[q * 512 + c4a + 256];
            accA.x += oA.x; accA.y += oA.y; accA.z += oA.z; accA.w += oA.w;
            accB.x += oB.x; accB.y += oB.y; accB.z += oB.z; accB.w += oB.w;
        }
        const float4* gp04 = reinterpret_cast<const float4*>(p0 + 512);
        const float4* gp14 = reinterpret_cast<const float4*>(p1 + 512);
        const float4* gp24 = reinterpret_cast<const float4*>(p2 + 512);
        const float4* gp34 = reinterpret_cast<const float4*>(p3 + 512);
        const float4* bb4 = reinterpret_cast<const float4*>(bb);
        float4* awe4 = reinterpret_cast<float4*>(d_awe + (size_t)b * EE);
        #pragma unroll
        for (int h = 0; h < 2; h++) {
            int c4 = c4a + h * 256;
            float4 acc = h ? accB : accA;
            float4 g0 = gp04[c4], g1 = gp14[c4], g2 = gp24[c4], g3 = gp34[c4], bbv = bb4[c4];
            float4 gt;
            gt.x = 1.0f / (1.0f + __expf(-(g0.x + g1.x + g2.x + g3.x + bbv.x)));
            gt.y = 1.0f / (1.0f + __expf(-(g0.y + g1.y + g2.y + g3.y + bbv.y)));
            gt.z = 1.0f / (1.0f + __expf(-(g0.z + g1.z + g2.z + g3.z + bbv.z)));
            gt.w = 1.0f / (1.0f + __expf(-(g0.w + g1.w + g2.w + g3.w + bbv.w)));
            awe4[c4] = make_float4(acc.x * gt.x, acc.y * gt.y, acc.z * gt.z, acc.w * gt.w);
        }
    }
}

// ---------------- host launch ----------------
extern "C" void kernel_launch(void* const* d_in, const int* in_sizes, int n_in,
                              void* d_out, int out_size) {
    const float* enc  = (const float*)d_in[0];
    const int*   caps = (const int*)d_in[1];
    const int*   clen = (const int*)d_in[2];
    const float* emb  = (const float*)d_in[3];
    const float* We   = (const float*)d_in[4];
    const float* be   = (const float*)d_in[5];
    const float* Wd   = (const float*)d_in[6];
    const float* bd   = (const float*)d_in[7];
    const float* Wf   = (const float*)d_in[8];
    const float* bf   = (const float*)d_in[9];
    const float* Wih  = (const float*)d_in[10];
    const float* bih  = (const float*)d_in[11];
    const float* Whh  = (const float*)d_in[12];
    const float* bhh  = (const float*)d_in[13];
    const float* Wb   = (const float*)d_in[14];
    const float* bb   = (const float*)d_in[15];
    const float* Whi  = (const float*)d_in[16];
    const float* bhi  = (const float*)d_in[17];
    const float* Wci  = (const float*)d_in[18];
    const float* bci  = (const float*)d_in[19];
    const float* Wfc  = (const float*)d_in[20];
    const float* bfc  = (const float*)d_in[21];
    float* out = (float*)d_out;
    float* out_alphas = out + (size_t)BB * TT * VV;

    k_setup<<<1, 64>>>(clen);
    k_zero<<<2048, 256>>>(out, (size_t)out_size);
    k_mean<<<dim3(8, BB), 256>>>(enc);

    // h0 + c0 in ONE split-K GEMM (concat [Whi|Wci], N=1024, K=2048, S=8)
    k_gemm32<<<dim3(32, 8), 256>>>(BUF_MEAN, Whi, Wci, 512, 512, 512, 1024, EE, 8, -1);
    k_reduce_hc<<<256, 256>>>(bhi, bci);

    // att1 via tf32 tensor cores
    k_att1_mma<<<dim3(98, 8), 256>>>(enc, We, be);

    // embc = embs(active rows) @ Wih[0:512]
    k_embc_mma<<<dim3(16, 32), 256>>>(emb, caps, Wih);

    // PDL attribute shared by the loop launches
    cudaLaunchAttribute pattr;
    pattr.id = cudaLaunchAttributeProgrammaticStreamSerialization;
    pattr.val.programmaticStreamSerializationAllowed = 1;
    auto mkcfg = [&](unsigned gx, unsigned gy, unsigned bx) {
        cudaLaunchConfig_t c;
        c.gridDim = dim3(gx, gy, 1);
        c.blockDim = dim3(bx, 1, 1);
        c.dynamicSmemBytes = 0;
        c.stream = 0;
        c.attrs = &pattr;
        c.numAttrs = 1;
        return c;
    };

    const float* Wih2 = Wih + (size_t)512 * 2048;
    for (int t = 0; t < TT; t++) {
        cudaLaunchConfig_t c1 = mkcfg(36, 4, 256);
        cudaLaunchKernelEx(&c1, k_ag_mma, Wd, Wb, Whh, t);
        cudaLaunchConfig_t c2 = mkcfg(BB, 1, 1024);
        cudaLaunchKernelEx(&c2, k_attend, enc, Wf, bf, bd, bb, out_alphas, t);
        cudaLaunchConfig_t c3 = mkcfg(16, 8, 256);
        cudaLaunchKernelEx(&c3, k_awe_mma, Wih2, t);
        cudaLaunchConfig_t c4 = mkcfg(128, 1, 256);
        cudaLaunchKernelEx(&c4, k_reduce_lstm, bih, bhh, t);
    }

    // batched vocab projection via tf32 tensor cores
    k_preds_mma<<<dim3(16, 157), 256>>>(Wfc, bfc, out);
}